// round 1
// baseline (speedup 1.0000x reference)
#include <cuda_runtime.h>
#include <math.h>

#define BB 8
#define WW 256
#define FF 16
#define DD 128
#define HH 8
#define NL 4
#define INNER 1024
#define NT (BB*WW*FF)          /* 32768 tokens */
#define QKVLD 3072
#define SCALE 0.08838834764831845f   /* 128^-0.5 */

/* ---------------- scratch (static __device__, no allocation) ---------------- */
__device__ float g_h [NT*DD];                      /* 16 MB  running hidden state */
__device__ float g_hn[NT*DD];                      /* 16 MB  layernorm output     */
__device__ float g_qkv[(size_t)NT*QKVLD];          /* 402 MB qkv activations      */
__device__ float g_o [(size_t)NT*INNER];           /* 134 MB attention output     */
__device__ float g_S [(size_t)BB*FF*HH*WW*WW];     /* 268 MB temporal scores      */

/* ---------------- embed: convs + value proj + positional encoding ---------------- */
__global__ void embed_kernel(const float* __restrict__ x,
    const float* __restrict__ w1, const float* __restrict__ b1,
    const float* __restrict__ w2, const float* __restrict__ b2,
    const float* __restrict__ w3, const float* __restrict__ b3,
    const float* __restrict__ wv, const float* __restrict__ bv)
{
    int tok = blockIdx.x;
    int d   = threadIdx.x;
    int f   = tok % FF;
    int bw  = tok / FF;           /* b*W + w */
    int w   = bw % WW;
    const float* xp = x + (size_t)(bw - w)*FF + f;   /* &x[b][w'=0][f]; step FF per w' */

    float s0 = xp[(size_t)w*FF];
    float c1 = b1[f];
    #pragma unroll
    for (int j = 0; j < 4; j++) { int wi = w - (3-j);    if (wi >= 0) c1 += xp[(size_t)wi*FF]*w1[f*4+j]; }
    float c2 = b2[f];
    #pragma unroll
    for (int j = 0; j < 8; j++) { int wi = w - (7-j)*2;  if (wi >= 0) c2 += xp[(size_t)wi*FF]*w2[f*8+j]; }
    float c3 = b3[f];
    #pragma unroll
    for (int j = 0; j < 16; j++){ int wi = w - (15-j)*3; if (wi >= 0) c3 += xp[(size_t)wi*FF]*w3[f*16+j]; }

    float e = s0*wv[d] + c1*wv[DD+d] + c2*wv[2*DD+d] + c3*wv[3*DD+d] + bv[d];

    int   i2  = (d >> 1) * 2;
    float div = expf(-logf(10000.0f)/(float)DD * (float)i2);
    float ang = (float)w * div;
    float pe  = (d & 1) ? cosf(ang) : sinf(ang);

    g_h[(size_t)tok*DD + d] = e + pe;
}

/* ---------------- layernorm over D=128 ---------------- */
__global__ void ln_kernel(const float* __restrict__ gam, const float* __restrict__ bet)
{
    int tok = blockIdx.x;
    int d   = threadIdx.x;
    float v = g_h[(size_t)tok*DD + d];
    float s = v, ss = v*v;
    #pragma unroll
    for (int o = 16; o > 0; o >>= 1) {
        s  += __shfl_xor_sync(~0u, s,  o);
        ss += __shfl_xor_sync(~0u, ss, o);
    }
    __shared__ float sm[4], ssm[4];
    int wid = threadIdx.x >> 5;
    if ((threadIdx.x & 31) == 0) { sm[wid] = s; ssm[wid] = ss; }
    __syncthreads();
    s  = sm[0]+sm[1]+sm[2]+sm[3];
    ss = ssm[0]+ssm[1]+ssm[2]+ssm[3];
    float mean = s * (1.0f/DD);
    float var  = ss * (1.0f/DD) - mean*mean;
    float r    = rsqrtf(var + 1e-5f);
    g_hn[(size_t)tok*DD + d] = (v - mean)*r*gam[d] + bet[d];
}

/* ---------------- generic fp32 tiled GEMM: C = A[M,K] @ B[K,N] (+bias +resid) ----------------
   BM=BN=64, BK=32, 256 threads, 4x4 microtile. Dims must divide tiles (they do here). */
__global__ void sgemm_nn(const float* __restrict__ A, const float* __restrict__ Bm,
                         float* __restrict__ C,
                         int M, int N, int K, int lda, int ldb, int ldc,
                         const float* __restrict__ bias, const float* __restrict__ resid)
{
    const int BM=64, BN=64, BK=32;
    __shared__ float As[BK][BM+1];
    __shared__ float Bs[BK][BN+1];
    int m0 = blockIdx.y*BM, n0 = blockIdx.x*BN;
    int tid = threadIdx.x;
    int tx = tid & 15, ty = tid >> 4;
    float acc[4][4] = {};
    for (int k0 = 0; k0 < K; k0 += BK) {
        #pragma unroll
        for (int i = 0; i < 8; i++) {
            int idx = tid + i*256;
            int m = idx >> 5, kk = idx & 31;
            As[kk][m] = A[(size_t)(m0+m)*lda + k0 + kk];
        }
        #pragma unroll
        for (int i = 0; i < 8; i++) {
            int idx = tid + i*256;
            int kk = idx >> 6, n = idx & 63;
            Bs[kk][n] = Bm[(size_t)(k0+kk)*ldb + n0 + n];
        }
        __syncthreads();
        #pragma unroll
        for (int kk = 0; kk < BK; kk++) {
            float a[4], b[4];
            #pragma unroll
            for (int i=0;i<4;i++) a[i] = As[kk][ty*4+i];
            #pragma unroll
            for (int j=0;j<4;j++) b[j] = Bs[kk][tx*4+j];
            #pragma unroll
            for (int i=0;i<4;i++)
                #pragma unroll
                for (int j=0;j<4;j++) acc[i][j] += a[i]*b[j];
        }
        __syncthreads();
    }
    #pragma unroll
    for (int i=0;i<4;i++) {
        int m = m0 + ty*4 + i;
        #pragma unroll
        for (int j=0;j<4;j++) {
            int n = n0 + tx*4 + j;
            float v = acc[i][j];
            if (bias)  v += bias[n];
            if (resid) v += resid[(size_t)m*ldc + n];
            C[(size_t)m*ldc + n] = v;
        }
    }
}

/* ---------------- variable attention (feature axis, F=16), fully fused ----------------
   one block per (b*W+w, head): 16x16 scores, softmax, 16x128 output */
__global__ void vattn_kernel()
{
    __shared__ float Qs[FF][DD+1], Ks[FF][DD+1], Vs[FF][DD+1];
    __shared__ float Ssm[FF][FF+1], Psm[FF][FF+1];
    int bw = blockIdx.x / HH, hd = blockIdx.x % HH;
    size_t base = (size_t)bw*FF*QKVLD + hd*DD;
    int tid = threadIdx.x;
    #pragma unroll
    for (int i=0;i<8;i++){
        int idx = tid + i*256;
        int fr = idx >> 7, e = idx & 127;
        size_t r = base + (size_t)fr*QKVLD + e;
        Qs[fr][e] = g_qkv[r];
        Ks[fr][e] = g_qkv[r + INNER];
        Vs[fr][e] = g_qkv[r + 2*INNER];
    }
    __syncthreads();
    int i = tid >> 4, j = tid & 15;
    float s = 0.f;
    #pragma unroll
    for (int e=0;e<DD;e++) s += Qs[i][e]*Ks[j][e];
    Ssm[i][j] = s*SCALE;
    __syncthreads();
    if (tid < FF) {
        float mx = -1e30f;
        #pragma unroll
        for (int jj=0;jj<FF;jj++) mx = fmaxf(mx, Ssm[tid][jj]);
        float tmp[FF]; float sum = 0.f;
        #pragma unroll
        for (int jj=0;jj<FF;jj++){ tmp[jj] = expf(Ssm[tid][jj]-mx); sum += tmp[jj]; }
        float inv = 1.0f/sum;
        #pragma unroll
        for (int jj=0;jj<FF;jj++) Psm[tid][jj] = tmp[jj]*inv;
    }
    __syncthreads();
    int cg = tid & 15;
    float acc[8] = {};
    #pragma unroll
    for (int jj=0;jj<FF;jj++){
        float pp = Psm[i][jj];
        #pragma unroll
        for (int u=0;u<8;u++) acc[u] += pp*Vs[jj][cg*8+u];
    }
    size_t ob = (size_t)(bw*FF + i)*INNER + hd*DD + cg*8;
    #pragma unroll
    for (int u=0;u<8;u++) g_o[ob+u] = acc[u];
}

/* ---------------- temporal scores: S[bfh, i, j] = SCALE * q_i . k_j (strided rows) ---------------- */
__global__ void tscore_kernel()
{
    const int BM=64, BN=64, BK=32;
    __shared__ float As[BK][BM+1];
    __shared__ float Bs[BK][BN+1];
    int batch = blockIdx.z;
    int hd = batch % HH; int f = (batch / HH) % FF; int b = batch / (FF*HH);
    size_t baseQ = ((size_t)(b*WW)*FF + f)*QKVLD + hd*DD;
    size_t baseK = baseQ + INNER;
    const int RS = FF*QKVLD;   /* 49152: stride between consecutive w */
    int i0 = blockIdx.y*BM, j0 = blockIdx.x*BN;
    int tid = threadIdx.x, tx = tid & 15, ty = tid >> 4;
    float acc[4][4] = {};
    for (int k0 = 0; k0 < DD; k0 += BK) {
        #pragma unroll
        for (int i=0;i<8;i++){
            int idx = tid + i*256;
            int m = idx >> 5, kk = idx & 31;
            As[kk][m] = g_qkv[baseQ + (size_t)(i0+m)*RS + k0+kk];
        }
        #pragma unroll
        for (int i=0;i<8;i++){
            int idx = tid + i*256;
            int n = idx >> 5, kk = idx & 31;
            Bs[kk][n] = g_qkv[baseK + (size_t)(j0+n)*RS + k0+kk];
        }
        __syncthreads();
        #pragma unroll
        for (int kk=0;kk<BK;kk++){
            float a[4], bb[4];
            #pragma unroll
            for (int i=0;i<4;i++) a[i]  = As[kk][ty*4+i];
            #pragma unroll
            for (int j=0;j<4;j++) bb[j] = Bs[kk][tx*4+j];
            #pragma unroll
            for (int i=0;i<4;i++)
                #pragma unroll
                for (int j=0;j<4;j++) acc[i][j] += a[i]*bb[j];
        }
        __syncthreads();
    }
    size_t baseS = (size_t)batch*WW*WW;
    #pragma unroll
    for (int i=0;i<4;i++)
        #pragma unroll
        for (int j=0;j<4;j++)
            g_S[baseS + (size_t)(i0+ty*4+i)*WW + j0+tx*4+j] = acc[i][j]*SCALE;
}

/* ---------------- row softmax over W=256 (warp per row) ---------------- */
__global__ void softmax_kernel()
{
    int row  = blockIdx.x*8 + (threadIdx.x >> 5);
    int lane = threadIdx.x & 31;
    float* p = g_S + (size_t)row*WW;
    float v[8]; float mx = -1e30f;
    #pragma unroll
    for (int u=0;u<8;u++){ v[u] = p[lane + u*32]; mx = fmaxf(mx, v[u]); }
    #pragma unroll
    for (int o=16;o>0;o>>=1) mx = fmaxf(mx, __shfl_xor_sync(~0u, mx, o));
    float s = 0.f;
    #pragma unroll
    for (int u=0;u<8;u++){ v[u] = expf(v[u]-mx); s += v[u]; }
    #pragma unroll
    for (int o=16;o>0;o>>=1) s += __shfl_xor_sync(~0u, s, o);
    float inv = 1.0f/s;
    #pragma unroll
    for (int u=0;u<8;u++) p[lane + u*32] = v[u]*inv;
}

/* ---------------- temporal AV: g_o += P @ V (strided rows), accumulate ---------------- */
__global__ void tav_kernel()
{
    const int BM=64, BN=64, BK=32;
    __shared__ float As[BK][BM+1];
    __shared__ float Bs[BK][BN+1];
    int batch = blockIdx.z;
    int hd = batch % HH; int f = (batch / HH) % FF; int b = batch / (FF*HH);
    size_t baseS = (size_t)batch*WW*WW;
    size_t baseV = ((size_t)(b*WW)*FF + f)*QKVLD + 2*INNER + hd*DD;
    size_t baseO = ((size_t)(b*WW)*FF + f)*INNER + hd*DD;
    const int RS = FF*QKVLD, RO = FF*INNER;  /* 49152, 16384 */
    int i0 = blockIdx.y*BM, n0 = blockIdx.x*BN;
    int tid = threadIdx.x, tx = tid & 15, ty = tid >> 4;
    float acc[4][4] = {};
    for (int k0 = 0; k0 < WW; k0 += BK) {
        #pragma unroll
        for (int i=0;i<8;i++){
            int idx = tid + i*256;
            int m = idx >> 5, kk = idx & 31;
            As[kk][m] = g_S[baseS + (size_t)(i0+m)*WW + k0+kk];
        }
        #pragma unroll
        for (int i=0;i<8;i++){
            int idx = tid + i*256;
            int kk = idx >> 6, n = idx & 63;
            Bs[kk][n] = g_qkv[baseV + (size_t)(k0+kk)*RS + n0 + n];
        }
        __syncthreads();
        #pragma unroll
        for (int kk=0;kk<BK;kk++){
            float a[4], bb[4];
            #pragma unroll
            for (int i=0;i<4;i++) a[i]  = As[kk][ty*4+i];
            #pragma unroll
            for (int j=0;j<4;j++) bb[j] = Bs[kk][tx*4+j];
            #pragma unroll
            for (int i=0;i<4;i++)
                #pragma unroll
                for (int j=0;j<4;j++) acc[i][j] += a[i]*bb[j];
        }
        __syncthreads();
    }
    #pragma unroll
    for (int i=0;i<4;i++){
        size_t r = baseO + (size_t)(i0+ty*4+i)*RO;
        #pragma unroll
        for (int j=0;j<4;j++)
            g_o[r + n0 + tx*4 + j] += acc[i][j];
    }
}

/* ---------------- head: out[bw, n] = h_row[2048] . w_head[:, n] + b_head ---------------- */
__global__ void head_kernel(const float* __restrict__ wh, const float* __restrict__ bh,
                            float* __restrict__ out)
{
    int bw = blockIdx.x;
    int n = threadIdx.x >> 5, lane = threadIdx.x & 31;
    const float* hrow = g_h + (size_t)bw*(FF*DD);
    float acc = 0.f;
    #pragma unroll 4
    for (int k = lane; k < FF*DD; k += 32)
        acc += hrow[k]*wh[k*FF + n];
    #pragma unroll
    for (int o=16;o>0;o>>=1) acc += __shfl_xor_sync(~0u, acc, o);
    if (lane == 0) out[bw*FF + n] = acc + bh[n];
}

/* ---------------- launcher ---------------- */
extern "C" void kernel_launch(void* const* d_in, const int* in_sizes, int n_in,
                              void* d_out, int out_size)
{
    (void)in_sizes; (void)n_in; (void)out_size;
    const float* x   = (const float*)d_in[0];
    const float* w1  = (const float*)d_in[1];
    const float* b1  = (const float*)d_in[2];
    const float* w2  = (const float*)d_in[3];
    const float* b2  = (const float*)d_in[4];
    const float* w3  = (const float*)d_in[5];
    const float* b3  = (const float*)d_in[6];
    const float* wv  = (const float*)d_in[7];
    const float* bv  = (const float*)d_in[8];
    const float* lng = (const float*)d_in[9];
    const float* lnb = (const float*)d_in[10];
    const float* wq  = (const float*)d_in[11];
    const float* wo  = (const float*)d_in[12];
    const float* bo  = (const float*)d_in[13];
    const float* wh  = (const float*)d_in[14];
    const float* bh  = (const float*)d_in[15];
    float* out = (float*)d_out;

    float *p_h, *p_hn, *p_qkv, *p_o;
    cudaGetSymbolAddress((void**)&p_h,   g_h);
    cudaGetSymbolAddress((void**)&p_hn,  g_hn);
    cudaGetSymbolAddress((void**)&p_qkv, g_qkv);
    cudaGetSymbolAddress((void**)&p_o,   g_o);

    embed_kernel<<<NT, DD>>>(x, w1, b1, w2, b2, w3, b3, wv, bv);

    for (int l = 0; l < NL; l++) {
        ln_kernel<<<NT, DD>>>(lng + l*DD, lnb + l*DD);

        /* qkv = hn @ Wqkv[l] : [32768,128]@[128,3072] */
        sgemm_nn<<<dim3(QKVLD/64, NT/64), 256>>>(
            p_hn, wq + (size_t)l*DD*QKVLD, p_qkv,
            NT, QKVLD, DD, DD, QKVLD, QKVLD, nullptr, nullptr);

        /* variable attention writes g_o (plain store) */
        vattn_kernel<<<BB*WW*HH, 256>>>();

        /* temporal attention: scores -> softmax -> AV (accumulates into g_o) */
        tscore_kernel<<<dim3(WW/64, WW/64, BB*FF*HH), 256>>>();
        softmax_kernel<<<(BB*FF*HH*WW)/8, 256>>>();
        tav_kernel<<<dim3(DD/64, WW/64, BB*FF*HH), 256>>>();

        /* h = o @ Wout[l] + b_out[l] + h : [32768,1024]@[1024,128] */
        sgemm_nn<<<dim3(DD/64, NT/64), 256>>>(
            p_o, wo + (size_t)l*INNER*DD, p_h,
            NT, DD, INNER, INNER, DD, DD, bo + l*DD, p_h);
    }

    head_kernel<<<BB*WW, 512>>>(wh, bh, out);
}

// round 2
// speedup vs baseline: 1.4479x; 1.4479x over previous
#include <cuda_runtime.h>
#include <mma.h>
#include <math.h>
using namespace nvcuda;

#define BB 8
#define WW 256
#define FF 16
#define DD 128
#define HH 8
#define NL 4
#define INNER 1024
#define NT (BB*WW*FF)          /* 32768 tokens */
#define QKVLD 3072
#define SCALE 0.08838834764831845f   /* 128^-0.5 */
#define RS (FF*QKVLD)          /* 49152: row stride (per w) in qkv */
#define RO (FF*INNER)          /* 16384: row stride (per w) in o   */

/* ---------------- scratch (static __device__, no allocation) ---------------- */
__device__ float g_h [NT*DD];                      /* 16 MB  running hidden state */
__device__ float g_hn[NT*DD];                      /* 16 MB  layernorm output     */
__device__ float g_qkv[(size_t)NT*QKVLD];          /* 402 MB qkv activations      */
__device__ float g_o [(size_t)NT*INNER];           /* 134 MB attention output     */

/* ---------------- fast exp on the FMA pipe (MUFU is slow on B300) ----------------
   exp(x) = 2^(x*log2e); k = round(z) via magic number, 2^f deg-5 Taylor, |relerr|~3e-6 */
__device__ __forceinline__ float fexp(float x)
{
    x = fmaxf(x, -80.0f);
    float z  = x * 1.4426950408889634f;
    float zj = z + 12582912.0f;                 /* 1.5*2^23: round-to-nearest-int  */
    int   k  = __float_as_int(zj) - 0x4B400000;
    float f  = z - (zj - 12582912.0f);          /* f in [-0.5, 0.5] */
    float p  = 1.3333558146e-3f;
    p = p*f + 9.6181291076e-3f;
    p = p*f + 5.5504108665e-2f;
    p = p*f + 2.4022650696e-1f;
    p = p*f + 6.9314718056e-1f;
    p = p*f + 1.0f;
    return __int_as_float(__float_as_int(p) + (k << 23));
}

/* ---------------- embed: convs + value proj + positional encoding ---------------- */
__global__ void embed_kernel(const float* __restrict__ x,
    const float* __restrict__ w1, const float* __restrict__ b1,
    const float* __restrict__ w2, const float* __restrict__ b2,
    const float* __restrict__ w3, const float* __restrict__ b3,
    const float* __restrict__ wv, const float* __restrict__ bv)
{
    int tok = blockIdx.x;
    int d   = threadIdx.x;
    int f   = tok % FF;
    int bw  = tok / FF;
    int w   = bw % WW;
    const float* xp = x + (size_t)(bw - w)*FF + f;

    float s0 = xp[(size_t)w*FF];
    float c1 = b1[f];
    #pragma unroll
    for (int j = 0; j < 4; j++) { int wi = w - (3-j);    if (wi >= 0) c1 += xp[(size_t)wi*FF]*w1[f*4+j]; }
    float c2 = b2[f];
    #pragma unroll
    for (int j = 0; j < 8; j++) { int wi = w - (7-j)*2;  if (wi >= 0) c2 += xp[(size_t)wi*FF]*w2[f*8+j]; }
    float c3 = b3[f];
    #pragma unroll
    for (int j = 0; j < 16; j++){ int wi = w - (15-j)*3; if (wi >= 0) c3 += xp[(size_t)wi*FF]*w3[f*16+j]; }

    float e = s0*wv[d] + c1*wv[DD+d] + c2*wv[2*DD+d] + c3*wv[3*DD+d] + bv[d];

    int   i2  = (d >> 1) * 2;
    float div = expf(-logf(10000.0f)/(float)DD * (float)i2);
    float ang = (float)w * div;
    float pe  = (d & 1) ? cosf(ang) : sinf(ang);

    g_h[(size_t)tok*DD + d] = e + pe;
}

/* ---------------- layernorm over D=128 ---------------- */
__global__ void ln_kernel(const float* __restrict__ gam, const float* __restrict__ bet)
{
    int tok = blockIdx.x;
    int d   = threadIdx.x;
    float v = g_h[(size_t)tok*DD + d];
    float s = v, ss = v*v;
    #pragma unroll
    for (int o = 16; o > 0; o >>= 1) {
        s  += __shfl_xor_sync(~0u, s,  o);
        ss += __shfl_xor_sync(~0u, ss, o);
    }
    __shared__ float sm[4], ssm[4];
    int wid = threadIdx.x >> 5;
    if ((threadIdx.x & 31) == 0) { sm[wid] = s; ssm[wid] = ss; }
    __syncthreads();
    s  = sm[0]+sm[1]+sm[2]+sm[3];
    ss = ssm[0]+ssm[1]+ssm[2]+ssm[3];
    float mean = s * (1.0f/DD);
    float var  = ss * (1.0f/DD) - mean*mean;
    float r    = rsqrtf(var + 1e-5f);
    g_hn[(size_t)tok*DD + d] = (v - mean)*r*gam[d] + bet[d];
}

/* ---------------- tf32 WMMA GEMM: C = A[M,K]@B[K,N] (+bias+resid if EPI) ----------------
   BM=128, BN=64, BK=16. 256 threads = 8 warps (4 along M x 2 along N), 32x32 per warp. */
template<bool EPI>
__global__ void wgemm(const float* __restrict__ A, const float* __restrict__ B,
                      float* __restrict__ C, int K, int lda, int ldb, int ldc,
                      const float* __restrict__ bias, const float* __restrict__ resid)
{
    const int ASLD = 20, BSLD = 72;
    __shared__ float buf[128*72];            /* 36KB union: (As+Bs) | Cs */
    float* As = buf;                         /* 128 x ASLD = 2560 floats  */
    float* Bs = buf + 2560;                  /*  16 x BSLD = 1152 floats  */
    int m0 = blockIdx.y*128, n0 = blockIdx.x*64;
    int tid = threadIdx.x, w = tid >> 5;
    int wm = w & 3, wn = w >> 2;

    wmma::fragment<wmma::accumulator,16,16,8,float> acc[2][2];
    #pragma unroll
    for (int i=0;i<2;i++)
        #pragma unroll
        for (int j=0;j<2;j++) wmma::fill_fragment(acc[i][j], 0.0f);

    for (int k0 = 0; k0 < K; k0 += 16) {
        #pragma unroll
        for (int i=0;i<2;i++){
            int idx = tid + i*256;
            int r = idx >> 2, c4 = (idx & 3)*4;
            *(float4*)&As[r*ASLD + c4] = *(const float4*)&A[(size_t)(m0+r)*lda + k0 + c4];
        }
        {
            int r = tid >> 4, c4 = (tid & 15)*4;
            *(float4*)&Bs[r*BSLD + c4] = *(const float4*)&B[(size_t)(k0+r)*ldb + n0 + c4];
        }
        __syncthreads();
        #pragma unroll
        for (int ks = 0; ks < 16; ks += 8) {
            wmma::fragment<wmma::matrix_a,16,16,8,wmma::precision::tf32,wmma::row_major> af[2];
            wmma::fragment<wmma::matrix_b,16,16,8,wmma::precision::tf32,wmma::row_major> bf[2];
            #pragma unroll
            for (int i=0;i<2;i++){
                wmma::load_matrix_sync(af[i], &As[(wm*32 + i*16)*ASLD + ks], ASLD);
                #pragma unroll
                for (int e=0;e<af[i].num_elements;e++) af[i].x[e] = wmma::__float_to_tf32(af[i].x[e]);
            }
            #pragma unroll
            for (int j=0;j<2;j++){
                wmma::load_matrix_sync(bf[j], &Bs[ks*BSLD + wn*32 + j*16], BSLD);
                #pragma unroll
                for (int e=0;e<bf[j].num_elements;e++) bf[j].x[e] = wmma::__float_to_tf32(bf[j].x[e]);
            }
            #pragma unroll
            for (int i=0;i<2;i++)
                #pragma unroll
                for (int j=0;j<2;j++)
                    wmma::mma_sync(acc[i][j], af[i], bf[j], acc[i][j]);
        }
        __syncthreads();
    }

    if (!EPI) {
        #pragma unroll
        for (int i=0;i<2;i++)
            #pragma unroll
            for (int j=0;j<2;j++)
                wmma::store_matrix_sync(&C[(size_t)(m0 + wm*32 + i*16)*ldc + n0 + wn*32 + j*16],
                                        acc[i][j], ldc, wmma::mem_row_major);
    } else {
        float* Cs = buf;                    /* 128 x BSLD, reuses As/Bs space */
        #pragma unroll
        for (int i=0;i<2;i++)
            #pragma unroll
            for (int j=0;j<2;j++)
                wmma::store_matrix_sync(&Cs[(wm*32 + i*16)*BSLD + wn*32 + j*16],
                                        acc[i][j], BSLD, wmma::mem_row_major);
        __syncthreads();
        #pragma unroll
        for (int i=0;i<8;i++){
            int idx = tid + i*256;
            int r = idx >> 4, c4 = (idx & 15)*4;
            float4 v  = *(float4*)&Cs[r*BSLD + c4];
            float4 bb = *(const float4*)&bias[n0 + c4];
            float4 rr = *(const float4*)&resid[(size_t)(m0+r)*ldc + n0 + c4];
            v.x += bb.x + rr.x; v.y += bb.y + rr.y;
            v.z += bb.z + rr.z; v.w += bb.w + rr.w;
            *(float4*)&C[(size_t)(m0+r)*ldc + n0 + c4] = v;
        }
    }
}

/* ---------------- variable attention (feature axis, F=16), fused ---------------- */
__global__ void vattn_kernel()
{
    __shared__ float Qs[FF][DD+1], Ks[FF][DD+1], Vs[FF][DD+1];
    __shared__ float Ssm[FF][FF+1], Psm[FF][FF+1];
    int bw = blockIdx.x / HH, hd = blockIdx.x % HH;
    size_t base = (size_t)bw*FF*QKVLD + hd*DD;
    int tid = threadIdx.x;
    #pragma unroll
    for (int i=0;i<8;i++){
        int idx = tid + i*256;
        int fr = idx >> 7, e = idx & 127;
        size_t r = base + (size_t)fr*QKVLD + e;
        Qs[fr][e] = g_qkv[r];
        Ks[fr][e] = g_qkv[r + INNER];
        Vs[fr][e] = g_qkv[r + 2*INNER];
    }
    __syncthreads();
    int i = tid >> 4, j = tid & 15;
    float s = 0.f;
    #pragma unroll
    for (int e=0;e<DD;e++) s += Qs[i][e]*Ks[j][e];
    Ssm[i][j] = s*SCALE;
    __syncthreads();
    if (tid < FF) {
        float mx = -1e30f;
        #pragma unroll
        for (int jj=0;jj<FF;jj++) mx = fmaxf(mx, Ssm[tid][jj]);
        float tmp[FF]; float sum = 0.f;
        #pragma unroll
        for (int jj=0;jj<FF;jj++){ tmp[jj] = fexp(Ssm[tid][jj]-mx); sum += tmp[jj]; }
        float inv = 1.0f/sum;
        #pragma unroll
        for (int jj=0;jj<FF;jj++) Psm[tid][jj] = tmp[jj]*inv;
    }
    __syncthreads();
    int cg = tid & 15;
    float acc[8] = {};
    #pragma unroll
    for (int jj=0;jj<FF;jj++){
        float pp = Psm[i][jj];
        #pragma unroll
        for (int u=0;u<8;u++) acc[u] += pp*Vs[jj][cg*8+u];
    }
    size_t ob = (size_t)(bw*FF + i)*INNER + hd*DD + cg*8;
    #pragma unroll
    for (int u=0;u<8;u++) g_o[ob+u] = acc[u];
}

/* ---------------- fused temporal attention (WMMA tf32, exact softmax) ----------------
   one block per (batch=(b,f,h), i-tile of 128 rows). 256 threads.
   smem: Ss[128][256] | Qs/Vs[128][132] | Ks[64][128] | Linv[128]  = 231936 B dynamic */
#define QLD 132
#define KLD 128
#define SLD 256
#define VLD 132
#define OLD 132
#define TATTN_SMEM ((128*SLD + 128*QLD + 64*KLD + 128) * 4)

__global__ void tattn_kernel(const float* __restrict__ qkv, float* __restrict__ o)
{
    extern __shared__ float sm[];
    float* Ss = sm;                         /* 32768 floats */
    float* Qs = sm + 128*SLD;               /* 16896 floats */
    float* Ks = Qs + 128*QLD;               /*  8192 floats */
    float* Ll = Ks + 64*KLD;                /*   128 floats */
    float* Vs = Qs;                         /* reuse after phase1 */
    float* Os = Ss;                         /* reuse after phase2 */

    int batch = blockIdx.y;
    int hd = batch & 7, f = (batch >> 3) & 15, b = batch >> 7;
    int i0 = blockIdx.x * 128;
    size_t baseQ = ((size_t)(b*WW)*FF + f)*QKVLD + hd*DD;
    size_t baseK = baseQ + INNER;
    size_t baseV = baseQ + 2*INNER;
    size_t baseO = ((size_t)(b*WW)*FF + f)*INNER + hd*DD;
    int tid = threadIdx.x, w = tid >> 5;
    int wm = w & 3, wn = w >> 2;

    /* load Q tile (pre-scaled) */
    #pragma unroll
    for (int i=0;i<16;i++){
        int idx = tid + i*256;
        int r = idx >> 5, c4 = (idx & 31)*4;
        float4 v = *(const float4*)&qkv[baseQ + (size_t)(i0+r)*RS + c4];
        v.x *= SCALE; v.y *= SCALE; v.z *= SCALE; v.w *= SCALE;
        *(float4*)&Qs[r*QLD + c4] = v;
    }

    /* phase 1: S = Q @ K^T in 64-col chunks */
    for (int jc=0; jc<4; jc++){
        __syncthreads();
        #pragma unroll
        for (int i=0;i<8;i++){
            int idx = tid + i*256;
            int r = idx >> 5, c4 = (idx & 31)*4;
            *(float4*)&Ks[r*KLD + c4] =
                *(const float4*)&qkv[baseK + (size_t)(jc*64 + r)*RS + c4];
        }
        __syncthreads();
        wmma::fragment<wmma::accumulator,16,16,8,float> sf[2][2];
        #pragma unroll
        for (int i=0;i<2;i++)
            #pragma unroll
            for (int j=0;j<2;j++) wmma::fill_fragment(sf[i][j], 0.0f);
        #pragma unroll
        for (int ks=0; ks<DD; ks+=8){
            wmma::fragment<wmma::matrix_a,16,16,8,wmma::precision::tf32,wmma::row_major> af[2];
            wmma::fragment<wmma::matrix_b,16,16,8,wmma::precision::tf32,wmma::col_major> bf[2];
            #pragma unroll
            for (int i=0;i<2;i++){
                wmma::load_matrix_sync(af[i], &Qs[(wm*32 + i*16)*QLD + ks], QLD);
                #pragma unroll
                for (int e=0;e<af[i].num_elements;e++) af[i].x[e] = wmma::__float_to_tf32(af[i].x[e]);
            }
            #pragma unroll
            for (int j=0;j<2;j++){
                wmma::load_matrix_sync(bf[j], &Ks[(wn*32 + j*16)*KLD + ks], KLD);
                #pragma unroll
                for (int e=0;e<bf[j].num_elements;e++) bf[j].x[e] = wmma::__float_to_tf32(bf[j].x[e]);
            }
            #pragma unroll
            for (int i=0;i<2;i++)
                #pragma unroll
                for (int j=0;j<2;j++)
                    wmma::mma_sync(sf[i][j], af[i], bf[j], sf[i][j]);
        }
        #pragma unroll
        for (int i=0;i<2;i++)
            #pragma unroll
            for (int j=0;j<2;j++)
                wmma::store_matrix_sync(&Ss[(wm*32 + i*16)*SLD + jc*64 + wn*32 + j*16],
                                        sf[i][j], SLD, wmma::mem_row_major);
    }
    __syncthreads();

    /* softmax rows (full row present -> exact); store unnormalized exp + 1/sum */
    {
        int r = tid >> 1, half = tid & 1;
        float* row = Ss + r*SLD + half*128;
        float mx = -1e30f;
        #pragma unroll 4
        for (int c=0;c<128;c++) mx = fmaxf(mx, row[c]);
        mx = fmaxf(mx, __shfl_xor_sync(0xFFFFFFFFu, mx, 1));
        float s = 0.f;
        #pragma unroll 4
        for (int c=0;c<128;c++){ float p = fexp(row[c]-mx); row[c] = p; s += p; }
        s += __shfl_xor_sync(0xFFFFFFFFu, s, 1);
        if (half == 0) Ll[r] = 1.0f/s;
    }

    /* phase 2: O = P @ V (V streamed in 64-row chunks into Qs space) */
    wmma::fragment<wmma::accumulator,16,16,8,float> of[2][4];
    #pragma unroll
    for (int i=0;i<2;i++)
        #pragma unroll
        for (int j=0;j<4;j++) wmma::fill_fragment(of[i][j], 0.0f);
    for (int jc=0; jc<4; jc++){
        __syncthreads();
        #pragma unroll
        for (int i=0;i<8;i++){
            int idx = tid + i*256;
            int r = idx >> 5, c4 = (idx & 31)*4;
            *(float4*)&Vs[r*VLD + c4] =
                *(const float4*)&qkv[baseV + (size_t)(jc*64 + r)*RS + c4];
        }
        __syncthreads();
        #pragma unroll
        for (int ks=0; ks<64; ks+=8){
            wmma::fragment<wmma::matrix_a,16,16,8,wmma::precision::tf32,wmma::row_major> pf[2];
            wmma::fragment<wmma::matrix_b,16,16,8,wmma::precision::tf32,wmma::row_major> vf[4];
            #pragma unroll
            for (int i=0;i<2;i++){
                wmma::load_matrix_sync(pf[i], &Ss[(wm*32 + i*16)*SLD + jc*64 + ks], SLD);
                #pragma unroll
                for (int e=0;e<pf[i].num_elements;e++) pf[i].x[e] = wmma::__float_to_tf32(pf[i].x[e]);
            }
            #pragma unroll
            for (int j=0;j<4;j++){
                wmma::load_matrix_sync(vf[j], &Vs[ks*VLD + wn*64 + j*16], VLD);
                #pragma unroll
                for (int e=0;e<vf[j].num_elements;e++) vf[j].x[e] = wmma::__float_to_tf32(vf[j].x[e]);
            }
            #pragma unroll
            for (int i=0;i<2;i++)
                #pragma unroll
                for (int j=0;j<4;j++)
                    wmma::mma_sync(of[i][j], pf[i], vf[j], of[i][j]);
        }
    }
    __syncthreads();
    #pragma unroll
    for (int i=0;i<2;i++)
        #pragma unroll
        for (int j=0;j<4;j++)
            wmma::store_matrix_sync(&Os[(wm*32 + i*16)*OLD + wn*64 + j*16],
                                    of[i][j], OLD, wmma::mem_row_major);
    __syncthreads();

    /* epilogue: o += Os * (1/l) per row */
    #pragma unroll
    for (int i=0;i<16;i++){
        int idx = tid + i*256;
        int r = idx >> 5, c4 = (idx & 31)*4;
        float inv = Ll[r];
        float4 v = *(float4*)&Os[r*OLD + c4];
        size_t p = baseO + (size_t)(i0 + r)*RO + c4;
        o[p]   += v.x*inv;
        o[p+1] += v.y*inv;
        o[p+2] += v.z*inv;
        o[p+3] += v.w*inv;
    }
}

/* ---------------- head: out[bw, n] = h_row[2048] . w_head[:, n] + b_head ---------------- */
__global__ void head_kernel(const float* __restrict__ wh, const float* __restrict__ bh,
                            float* __restrict__ out)
{
    int bw = blockIdx.x;
    int n = threadIdx.x >> 5, lane = threadIdx.x & 31;
    const float* hrow = g_h + (size_t)bw*(FF*DD);
    float acc = 0.f;
    #pragma unroll 4
    for (int k = lane; k < FF*DD; k += 32)
        acc += hrow[k]*wh[k*FF + n];
    #pragma unroll
    for (int o=16;o>0;o>>=1) acc += __shfl_xor_sync(~0u, acc, o);
    if (lane == 0) out[bw*FF + n] = acc + bh[n];
}

/* ---------------- launcher ---------------- */
extern "C" void kernel_launch(void* const* d_in, const int* in_sizes, int n_in,
                              void* d_out, int out_size)
{
    (void)in_sizes; (void)n_in; (void)out_size;
    const float* x   = (const float*)d_in[0];
    const float* w1  = (const float*)d_in[1];
    const float* b1  = (const float*)d_in[2];
    const float* w2  = (const float*)d_in[3];
    const float* b2  = (const float*)d_in[4];
    const float* w3  = (const float*)d_in[5];
    const float* b3  = (const float*)d_in[6];
    const float* wv  = (const float*)d_in[7];
    const float* bv  = (const float*)d_in[8];
    const float* lng = (const float*)d_in[9];
    const float* lnb = (const float*)d_in[10];
    const float* wq  = (const float*)d_in[11];
    const float* wo  = (const float*)d_in[12];
    const float* bo  = (const float*)d_in[13];
    const float* wh  = (const float*)d_in[14];
    const float* bh  = (const float*)d_in[15];
    float* out = (float*)d_out;

    float *p_h, *p_hn, *p_qkv, *p_o;
    cudaGetSymbolAddress((void**)&p_h,   g_h);
    cudaGetSymbolAddress((void**)&p_hn,  g_hn);
    cudaGetSymbolAddress((void**)&p_qkv, g_qkv);
    cudaGetSymbolAddress((void**)&p_o,   g_o);

    cudaFuncSetAttribute(tattn_kernel,
        cudaFuncAttributeMaxDynamicSharedMemorySize, TATTN_SMEM);

    embed_kernel<<<NT, DD>>>(x, w1, b1, w2, b2, w3, b3, wv, bv);

    for (int l = 0; l < NL; l++) {
        ln_kernel<<<NT, DD>>>(lng + l*DD, lnb + l*DD);

        /* qkv = hn @ Wqkv[l] : [32768,128]@[128,3072], tf32 wmma */
        wgemm<false><<<dim3(QKVLD/64, NT/128), 256>>>(
            p_hn, wq + (size_t)l*DD*QKVLD, p_qkv,
            DD, DD, QKVLD, QKVLD, nullptr, nullptr);

        /* variable attention writes g_o */
        vattn_kernel<<<BB*WW*HH, 256>>>();

        /* fused temporal attention accumulates into g_o */
        tattn_kernel<<<dim3(2, BB*FF*HH), 256, TATTN_SMEM>>>(p_qkv, p_o);

        /* h = o @ Wout[l] + b_out[l] + h : [32768,1024]@[1024,128], tf32 wmma */
        wgemm<true><<<dim3(DD/64, NT/128), 256>>>(
            p_o, wo + (size_t)l*INNER*DD, p_h,
            INNER, INNER, DD, DD, bo + l*DD, p_h);
    }

    head_kernel<<<BB*WW, 512>>>(wh, bh, out);
}

// round 4
// speedup vs baseline: 1.6724x; 1.1550x over previous
#include <cuda_runtime.h>
#include <mma.h>
#include <math.h>
using namespace nvcuda;

#define BB 8
#define WW 256
#define FF 16
#define DD 128
#define HH 8
#define NL 4
#define INNER 1024
#define NT (BB*WW*FF)          /* 32768 tokens */
#define QKVLD 3072
#define SCALE 0.08838834764831845f   /* 128^-0.5 */
#define RS (FF*QKVLD)          /* 49152: row stride (per w) in qkv */
#define RO (FF*INNER)          /* 16384: row stride (per w) in o   */

/* ---------------- scratch (static __device__, no allocation) ---------------- */
__device__ float g_h [NT*DD];
__device__ float g_hn[NT*DD];
__device__ float g_qkv[(size_t)NT*QKVLD];
__device__ float g_o [(size_t)NT*INNER];

/* ---------------- fast exp on the FMA pipe ---------------- */
__device__ __forceinline__ float fexp(float x)
{
    x = fmaxf(x, -80.0f);
    float z  = x * 1.4426950408889634f;
    float zj = z + 12582912.0f;
    int   k  = __float_as_int(zj) - 0x4B400000;
    float f  = z - (zj - 12582912.0f);
    float p  = 1.3333558146e-3f;
    p = p*f + 9.6181291076e-3f;
    p = p*f + 5.5504108665e-2f;
    p = p*f + 2.4022650696e-1f;
    p = p*f + 6.9314718056e-1f;
    p = p*f + 1.0f;
    return __int_as_float(__float_as_int(p) + (k << 23));
}

template<class Frag>
__device__ __forceinline__ void cvt_tf32(Frag& f)
{
    #pragma unroll
    for (int e = 0; e < f.num_elements; e++) f.x[e] = wmma::__float_to_tf32(f.x[e]);
}

/* ---------------- embed: convs + value proj + positional encoding ---------------- */
__global__ void embed_kernel(const float* __restrict__ x,
    const float* __restrict__ w1, const float* __restrict__ b1,
    const float* __restrict__ w2, const float* __restrict__ b2,
    const float* __restrict__ w3, const float* __restrict__ b3,
    const float* __restrict__ wv, const float* __restrict__ bv)
{
    int tok = blockIdx.x;
    int d   = threadIdx.x;
    int f   = tok % FF;
    int bw  = tok / FF;
    int w   = bw % WW;
    const float* xp = x + (size_t)(bw - w)*FF + f;

    float s0 = xp[(size_t)w*FF];
    float c1 = b1[f];
    #pragma unroll
    for (int j = 0; j < 4; j++) { int wi = w - (3-j);    if (wi >= 0) c1 += xp[(size_t)wi*FF]*w1[f*4+j]; }
    float c2 = b2[f];
    #pragma unroll
    for (int j = 0; j < 8; j++) { int wi = w - (7-j)*2;  if (wi >= 0) c2 += xp[(size_t)wi*FF]*w2[f*8+j]; }
    float c3 = b3[f];
    #pragma unroll
    for (int j = 0; j < 16; j++){ int wi = w - (15-j)*3; if (wi >= 0) c3 += xp[(size_t)wi*FF]*w3[f*16+j]; }

    float e = s0*wv[d] + c1*wv[DD+d] + c2*wv[2*DD+d] + c3*wv[3*DD+d] + bv[d];

    int   i2  = (d >> 1) * 2;
    float div = expf(-logf(10000.0f)/(float)DD * (float)i2);
    float ang = (float)w * div;
    float pe  = (d & 1) ? cosf(ang) : sinf(ang);

    g_h[(size_t)tok*DD + d] = e + pe;
}

/* ---------------- layernorm over D=128 ---------------- */
__global__ void ln_kernel(const float* __restrict__ gam, const float* __restrict__ bet)
{
    int tok = blockIdx.x;
    int d   = threadIdx.x;
    float v = g_h[(size_t)tok*DD + d];
    float s = v, ss = v*v;
    #pragma unroll
    for (int o = 16; o > 0; o >>= 1) {
        s  += __shfl_xor_sync(~0u, s,  o);
        ss += __shfl_xor_sync(~0u, ss, o);
    }
    __shared__ float sm[4], ssm[4];
    int wid = threadIdx.x >> 5;
    if ((threadIdx.x & 31) == 0) { sm[wid] = s; ssm[wid] = ss; }
    __syncthreads();
    s  = sm[0]+sm[1]+sm[2]+sm[3];
    ss = ssm[0]+ssm[1]+ssm[2]+ssm[3];
    float mean = s * (1.0f/DD);
    float var  = ss * (1.0f/DD) - mean*mean;
    float r    = rsqrtf(var + 1e-5f);
    g_hn[(size_t)tok*DD + d] = (v - mean)*r*gam[d] + bet[d];
}

/* ---------------- tf32 WMMA GEMM with 2-stage cp.async double buffer ----------------
   C = A[M,K]@B[K,N] (+bias+resid if EPI). BM=128, BN=64, BK=32.
   256 threads = 8 warps (4 along M x 2 along N), 32x32 per warp.
   dynamic smem: 2*(128*36 + 32*72) floats = 55296 B */
#define ASLD 36
#define BSLD 72
#define AST  (128*ASLD)          /* 4608 floats per stage */
#define BST  (32*BSLD)           /* 2304 floats per stage */
#define WG_SMEM ((2*AST + 2*BST)*4)

__device__ __forceinline__ void cp16(float* smem_dst, const float* gmem_src)
{
    unsigned d = (unsigned)__cvta_generic_to_shared(smem_dst);
    asm volatile("cp.async.cg.shared.global [%0], [%1], 16;\n" :: "r"(d), "l"(gmem_src));
}

template<bool EPI>
__global__ void wgemm(const float* __restrict__ A, const float* __restrict__ B,
                      float* __restrict__ C, int K, int lda, int ldb, int ldc,
                      const float* __restrict__ bias, const float* __restrict__ resid)
{
    extern __shared__ float dsm[];
    float* Asm[2] = { dsm, dsm + AST };
    float* Bsm[2] = { dsm + 2*AST, dsm + 2*AST + BST };
    int m0 = blockIdx.y*128, n0 = blockIdx.x*64;
    int tid = threadIdx.x, w = tid >> 5;
    int wm = w & 3, wn = w >> 2;

    wmma::fragment<wmma::accumulator,16,16,8,float> acc[2][2];
    #pragma unroll
    for (int i=0;i<2;i++)
        #pragma unroll
        for (int j=0;j<2;j++) wmma::fill_fragment(acc[i][j], 0.0f);

    auto issue = [&](int st, int k0){
        #pragma unroll
        for (int i=0;i<4;i++){
            int idx = tid + i*256;                 /* 1024 chunks of A */
            int r = idx >> 3, c4 = (idx & 7)*4;
            cp16(&Asm[st][r*ASLD + c4], &A[(size_t)(m0+r)*lda + k0 + c4]);
        }
        #pragma unroll
        for (int i=0;i<2;i++){
            int idx = tid + i*256;                 /* 512 chunks of B */
            int r = idx >> 4, c4 = (idx & 15)*4;
            cp16(&Bsm[st][r*BSLD + c4], &B[(size_t)(k0+r)*ldb + n0 + c4]);
        }
        asm volatile("cp.async.commit_group;\n");
    };

    int nt = K >> 5;
    issue(0, 0);
    for (int t = 0; t < nt; t++){
        if (t+1 < nt){
            issue((t+1)&1, (t+1)<<5);
            asm volatile("cp.async.wait_group 1;\n" ::: "memory");
        } else {
            asm volatile("cp.async.wait_group 0;\n" ::: "memory");
        }
        __syncthreads();
        int st = t & 1;
        #pragma unroll
        for (int ks = 0; ks < 32; ks += 8){
            wmma::fragment<wmma::matrix_a,16,16,8,wmma::precision::tf32,wmma::row_major> af[2];
            wmma::fragment<wmma::matrix_b,16,16,8,wmma::precision::tf32,wmma::row_major> bf[2];
            #pragma unroll
            for (int i=0;i<2;i++){
                wmma::load_matrix_sync(af[i], &Asm[st][(wm*32 + i*16)*ASLD + ks], ASLD);
                cvt_tf32(af[i]);
            }
            #pragma unroll
            for (int j=0;j<2;j++){
                wmma::load_matrix_sync(bf[j], &Bsm[st][ks*BSLD + wn*32 + j*16], BSLD);
                cvt_tf32(bf[j]);
            }
            #pragma unroll
            for (int i=0;i<2;i++)
                #pragma unroll
                for (int j=0;j<2;j++)
                    wmma::mma_sync(acc[i][j], af[i], bf[j], acc[i][j]);
        }
        __syncthreads();
    }

    if (!EPI) {
        #pragma unroll
        for (int i=0;i<2;i++)
            #pragma unroll
            for (int j=0;j<2;j++)
                wmma::store_matrix_sync(&C[(size_t)(m0 + wm*32 + i*16)*ldc + n0 + wn*32 + j*16],
                                        acc[i][j], ldc, wmma::mem_row_major);
    } else {
        float* Cs = dsm;                 /* 128 x BSLD = 9216 floats fits in 2*AST */
        #pragma unroll
        for (int i=0;i<2;i++)
            #pragma unroll
            for (int j=0;j<2;j++)
                wmma::store_matrix_sync(&Cs[(wm*32 + i*16)*BSLD + wn*32 + j*16],
                                        acc[i][j], BSLD, wmma::mem_row_major);
        __syncthreads();
        #pragma unroll
        for (int i=0;i<8;i++){
            int idx = tid + i*256;
            int r = idx >> 4, c4 = (idx & 15)*4;
            float4 v  = *(float4*)&Cs[r*BSLD + c4];
            float4 bb = *(const float4*)&bias[n0 + c4];
            float4 rr = *(const float4*)&resid[(size_t)(m0+r)*ldc + n0 + c4];
            v.x += bb.x + rr.x; v.y += bb.y + rr.y;
            v.z += bb.z + rr.z; v.w += bb.w + rr.w;
            *(float4*)&C[(size_t)(m0+r)*ldc + n0 + c4] = v;
        }
    }
}

/* ---------------- variable attention (feature axis, F=16): WMMA, warp per (bw,head) ----------------
   S = Q@K^T (16x16x128) and O = P@V (16x128x16) with fragments loaded straight from gmem.
   Only P (16x20 per warp) is staged in smem for the softmax. */
#define SPAD 20
__global__ void vattn_kernel(const float* __restrict__ qkv, float* __restrict__ o)
{
    __shared__ float Ps[HH][16*SPAD];
    int bw = blockIdx.x;
    int w  = threadIdx.x >> 5, lane = threadIdx.x & 31;
    const float* q = qkv + (size_t)bw*FF*QKVLD + w*DD;
    const float* k = q + INNER;
    const float* v = q + 2*INNER;
    float* op = o + (size_t)bw*FF*INNER + w*DD;
    float* Pw = &Ps[w][0];

    /* S = Q @ K^T */
    wmma::fragment<wmma::accumulator,16,16,8,float> sf;
    wmma::fill_fragment(sf, 0.0f);
    #pragma unroll
    for (int ks = 0; ks < DD; ks += 8){
        wmma::fragment<wmma::matrix_a,16,16,8,wmma::precision::tf32,wmma::row_major> af;
        wmma::fragment<wmma::matrix_b,16,16,8,wmma::precision::tf32,wmma::col_major> bf;
        wmma::load_matrix_sync(af, q + ks, QKVLD);
        cvt_tf32(af);
        wmma::load_matrix_sync(bf, k + ks, QKVLD);
        cvt_tf32(bf);
        wmma::mma_sync(sf, af, bf, sf);
    }
    #pragma unroll
    for (int e = 0; e < sf.num_elements; e++) sf.x[e] *= SCALE;
    wmma::store_matrix_sync(Pw, sf, SPAD, wmma::mem_row_major);
    __syncwarp();

    /* softmax: one lane per row */
    if (lane < FF){
        float* row = Pw + lane*SPAD;
        float mx = -1e30f;
        #pragma unroll
        for (int j=0;j<FF;j++) mx = fmaxf(mx, row[j]);
        float s = 0.f;
        #pragma unroll
        for (int j=0;j<FF;j++){ float p = fexp(row[j]-mx); row[j] = p; s += p; }
        float inv = 1.0f/s;
        #pragma unroll
        for (int j=0;j<FF;j++) row[j] *= inv;
    }
    __syncwarp();

    /* O = P @ V */
    wmma::fragment<wmma::matrix_a,16,16,8,wmma::precision::tf32,wmma::row_major> pf[2];
    wmma::load_matrix_sync(pf[0], Pw,     SPAD); cvt_tf32(pf[0]);
    wmma::load_matrix_sync(pf[1], Pw + 8, SPAD); cvt_tf32(pf[1]);
    #pragma unroll
    for (int n0 = 0; n0 < DD; n0 += 16){
        wmma::fragment<wmma::accumulator,16,16,8,float> of;
        wmma::fill_fragment(of, 0.0f);
        #pragma unroll
        for (int kk = 0; kk < 2; kk++){
            wmma::fragment<wmma::matrix_b,16,16,8,wmma::precision::tf32,wmma::row_major> vf;
            wmma::load_matrix_sync(vf, v + (size_t)kk*8*QKVLD + n0, QKVLD);
            cvt_tf32(vf);
            wmma::mma_sync(of, pf[kk], vf, of);
        }
        wmma::store_matrix_sync(op + n0, of, INNER, wmma::mem_row_major);
    }
}

/* ---------------- fused temporal attention (WMMA tf32, exact softmax) ---------------- */
#define QLD 132
#define KLD 128
#define SLD 256
#define VLD 132
#define OLD 132
#define TATTN_SMEM ((128*SLD + 128*QLD + 64*KLD + 128) * 4)

__global__ void tattn_kernel(const float* __restrict__ qkv, float* __restrict__ o)
{
    extern __shared__ float sm[];
    float* Ss = sm;
    float* Qs = sm + 128*SLD;
    float* Ks = Qs + 128*QLD;
    float* Ll = Ks + 64*KLD;
    float* Vs = Qs;
    float* Os = Ss;

    int batch = blockIdx.y;
    int hd = batch & 7, f = (batch >> 3) & 15, b = batch >> 7;
    int i0 = blockIdx.x * 128;
    size_t baseQ = ((size_t)(b*WW)*FF + f)*QKVLD + hd*DD;
    size_t baseK = baseQ + INNER;
    size_t baseV = baseQ + 2*INNER;
    size_t baseO = ((size_t)(b*WW)*FF + f)*INNER + hd*DD;
    int tid = threadIdx.x, w = tid >> 5;
    int wm = w & 3, wn = w >> 2;

    #pragma unroll
    for (int i=0;i<16;i++){
        int idx = tid + i*256;
        int r = idx >> 5, c4 = (idx & 31)*4;
        float4 v = *(const float4*)&qkv[baseQ + (size_t)(i0+r)*RS + c4];
        v.x *= SCALE; v.y *= SCALE; v.z *= SCALE; v.w *= SCALE;
        *(float4*)&Qs[r*QLD + c4] = v;
    }

    for (int jc=0; jc<4; jc++){
        __syncthreads();
        #pragma unroll
        for (int i=0;i<8;i++){
            int idx = tid + i*256;
            int r = idx >> 5, c4 = (idx & 31)*4;
            *(float4*)&Ks[r*KLD + c4] =
                *(const float4*)&qkv[baseK + (size_t)(jc*64 + r)*RS + c4];
        }
        __syncthreads();
        wmma::fragment<wmma::accumulator,16,16,8,float> sf[2][2];
        #pragma unroll
        for (int i=0;i<2;i++)
            #pragma unroll
            for (int j=0;j<2;j++) wmma::fill_fragment(sf[i][j], 0.0f);
        #pragma unroll
        for (int ks=0; ks<DD; ks+=8){
            wmma::fragment<wmma::matrix_a,16,16,8,wmma::precision::tf32,wmma::row_major> af[2];
            wmma::fragment<wmma::matrix_b,16,16,8,wmma::precision::tf32,wmma::col_major> bf[2];
            #pragma unroll
            for (int i=0;i<2;i++){
                wmma::load_matrix_sync(af[i], &Qs[(wm*32 + i*16)*QLD + ks], QLD);
                cvt_tf32(af[i]);
            }
            #pragma unroll
            for (int j=0;j<2;j++){
                wmma::load_matrix_sync(bf[j], &Ks[(wn*32 + j*16)*KLD + ks], KLD);
                cvt_tf32(bf[j]);
            }
            #pragma unroll
            for (int i=0;i<2;i++)
                #pragma unroll
                for (int j=0;j<2;j++)
                    wmma::mma_sync(sf[i][j], af[i], bf[j], sf[i][j]);
        }
        #pragma unroll
        for (int i=0;i<2;i++)
            #pragma unroll
            for (int j=0;j<2;j++)
                wmma::store_matrix_sync(&Ss[(wm*32 + i*16)*SLD + jc*64 + wn*32 + j*16],
                                        sf[i][j], SLD, wmma::mem_row_major);
    }
    __syncthreads();

    {
        int r = tid >> 1, half = tid & 1;
        float* row = Ss + r*SLD + half*128;
        float mx = -1e30f;
        #pragma unroll 4
        for (int c=0;c<128;c++) mx = fmaxf(mx, row[c]);
        mx = fmaxf(mx, __shfl_xor_sync(0xFFFFFFFFu, mx, 1));
        float s = 0.f;
        #pragma unroll 4
        for (int c=0;c<128;c++){ float p = fexp(row[c]-mx); row[c] = p; s += p; }
        s += __shfl_xor_sync(0xFFFFFFFFu, s, 1);
        if (half == 0) Ll[r] = 1.0f/s;
    }

    wmma::fragment<wmma::accumulator,16,16,8,float> of[2][4];
    #pragma unroll
    for (int i=0;i<2;i++)
        #pragma unroll
        for (int j=0;j<4;j++) wmma::fill_fragment(of[i][j], 0.0f);
    for (int jc=0; jc<4; jc++){
        __syncthreads();
        #pragma unroll
        for (int i=0;i<8;i++){
            int idx = tid + i*256;
            int r = idx >> 5, c4 = (idx & 31)*4;
            *(float4*)&Vs[r*VLD + c4] =
                *(const float4*)&qkv[baseV + (size_t)(jc*64 + r)*RS + c4];
        }
        __syncthreads();
        #pragma unroll
        for (int ks=0; ks<64; ks+=8){
            wmma::fragment<wmma::matrix_a,16,16,8,wmma::precision::tf32,wmma::row_major> pf[2];
            wmma::fragment<wmma::matrix_b,16,16,8,wmma::precision::tf32,wmma::row_major> vf[4];
            #pragma unroll
            for (int i=0;i<2;i++){
                wmma::load_matrix_sync(pf[i], &Ss[(wm*32 + i*16)*SLD + jc*64 + ks], SLD);
                cvt_tf32(pf[i]);
            }
            #pragma unroll
            for (int j=0;j<4;j++){
                wmma::load_matrix_sync(vf[j], &Vs[ks*VLD + wn*64 + j*16], VLD);
                cvt_tf32(vf[j]);
            }
            #pragma unroll
            for (int i=0;i<2;i++)
                #pragma unroll
                for (int j=0;j<4;j++)
                    wmma::mma_sync(of[i][j], pf[i], vf[j], of[i][j]);
        }
    }
    __syncthreads();
    #pragma unroll
    for (int i=0;i<2;i++)
        #pragma unroll
        for (int j=0;j<4;j++)
            wmma::store_matrix_sync(&Os[(wm*32 + i*16)*OLD + wn*64 + j*16],
                                    of[i][j], OLD, wmma::mem_row_major);
    __syncthreads();

    #pragma unroll
    for (int i=0;i<16;i++){
        int idx = tid + i*256;
        int r = idx >> 5, c4 = (idx & 31)*4;
        float inv = Ll[r];
        float4 v = *(float4*)&Os[r*OLD + c4];
        size_t p = baseO + (size_t)(i0 + r)*RO + c4;
        o[p]   += v.x*inv;
        o[p+1] += v.y*inv;
        o[p+2] += v.z*inv;
        o[p+3] += v.w*inv;
    }
}

/* ---------------- head ---------------- */
__global__ void head_kernel(const float* __restrict__ wh, const float* __restrict__ bh,
                            float* __restrict__ out)
{
    int bw = blockIdx.x;
    int n = threadIdx.x >> 5, lane = threadIdx.x & 31;
    const float* hrow = g_h + (size_t)bw*(FF*DD);
    float acc = 0.f;
    #pragma unroll 4
    for (int k = lane; k < FF*DD; k += 32)
        acc += hrow[k]*wh[k*FF + n];
    #pragma unroll
    for (int o=16;o>0;o>>=1) acc += __shfl_xor_sync(~0u, acc, o);
    if (lane == 0) out[bw*FF + n] = acc + bh[n];
}

/* ---------------- launcher ---------------- */
extern "C" void kernel_launch(void* const* d_in, const int* in_sizes, int n_in,
                              void* d_out, int out_size)
{
    (void)in_sizes; (void)n_in; (void)out_size;
    const float* x   = (const float*)d_in[0];
    const float* w1  = (const float*)d_in[1];
    const float* b1  = (const float*)d_in[2];
    const float* w2  = (const float*)d_in[3];
    const float* b2  = (const float*)d_in[4];
    const float* w3  = (const float*)d_in[5];
    const float* b3  = (const float*)d_in[6];
    const float* wv  = (const float*)d_in[7];
    const float* bv  = (const float*)d_in[8];
    const float* lng = (const float*)d_in[9];
    const float* lnb = (const float*)d_in[10];
    const float* wq  = (const float*)d_in[11];
    const float* wo  = (const float*)d_in[12];
    const float* bo  = (const float*)d_in[13];
    const float* wh  = (const float*)d_in[14];
    const float* bh  = (const float*)d_in[15];
    float* out = (float*)d_out;

    float *p_h, *p_hn, *p_qkv, *p_o;
    cudaGetSymbolAddress((void**)&p_h,   g_h);
    cudaGetSymbolAddress((void**)&p_hn,  g_hn);
    cudaGetSymbolAddress((void**)&p_qkv, g_qkv);
    cudaGetSymbolAddress((void**)&p_o,   g_o);

    cudaFuncSetAttribute(tattn_kernel,
        cudaFuncAttributeMaxDynamicSharedMemorySize, TATTN_SMEM);
    cudaFuncSetAttribute(wgemm<false>,
        cudaFuncAttributeMaxDynamicSharedMemorySize, WG_SMEM);
    cudaFuncSetAttribute(wgemm<true>,
        cudaFuncAttributeMaxDynamicSharedMemorySize, WG_SMEM);

    embed_kernel<<<NT, DD>>>(x, w1, b1, w2, b2, w3, b3, wv, bv);

    for (int l = 0; l < NL; l++) {
        ln_kernel<<<NT, DD>>>(lng + l*DD, lnb + l*DD);

        /* qkv = hn @ Wqkv[l] : [32768,128]@[128,3072] */
        wgemm<false><<<dim3(QKVLD/64, NT/128), 256, WG_SMEM>>>(
            p_hn, wq + (size_t)l*DD*QKVLD, p_qkv,
            DD, DD, QKVLD, QKVLD, nullptr, nullptr);

        /* variable attention writes g_o (WMMA, warp per (bw,head)) */
        vattn_kernel<<<BB*WW, 256>>>(p_qkv, p_o);

        /* fused temporal attention accumulates into g_o */
        tattn_kernel<<<dim3(2, BB*FF*HH), 256, TATTN_SMEM>>>(p_qkv, p_o);

        /* h = o @ Wout[l] + b_out[l] + h : [32768,1024]@[1024,128] */
        wgemm<true><<<dim3(DD/64, NT/128), 256, WG_SMEM>>>(
            p_o, wo + (size_t)l*INNER*DD, p_h,
            INNER, INNER, DD, DD, bo + l*DD, p_h);
    }

    head_kernel<<<BB*WW, 512>>>(wh, bh, out);
}

// round 5
// speedup vs baseline: 3.8513x; 2.3029x over previous
#include <cuda_runtime.h>
#include <cuda_fp16.h>
#include <mma.h>
#include <math.h>
using namespace nvcuda;

#define BB 8
#define WW 256
#define FF 16
#define DD 128
#define HH 8
#define NL 4
#define INNER 1024
#define NT (BB*WW*FF)          /* 32768 tokens */
#define QKVLD 3072
#define SCALE 0.08838834764831845f   /* 128^-0.5 */
#define RS (FF*QKVLD)          /* 49152: row stride (per w) in qkv */
#define RO (FF*INNER)          /* 16384: row stride (per w) in o   */

/* ---------------- scratch (static __device__, no allocation) ---------------- */
__device__ float  g_h  [NT*DD];                     /* 16 MB  running hidden state */
__device__ __half g_hn [NT*DD];                     /*  8 MB  layernorm output     */
__device__ __half g_qkv[(size_t)NT*QKVLD];          /* 201 MB qkv activations      */
__device__ __half g_o  [(size_t)NT*INNER];          /*  67 MB attention output     */
__device__ __half g_wqh[NL*DD*QKVLD];               /*  3 MB  half qkv weights     */
__device__ __half g_woh[NL*INNER*DD];               /*  1 MB  half out weights     */

/* ---------------- fast exp on the FMA pipe ---------------- */
__device__ __forceinline__ float fexp(float x)
{
    x = fmaxf(x, -80.0f);
    float z  = x * 1.4426950408889634f;
    float zj = z + 12582912.0f;
    int   k  = __float_as_int(zj) - 0x4B400000;
    float f  = z - (zj - 12582912.0f);
    float p  = 1.3333558146e-3f;
    p = p*f + 9.6181291076e-3f;
    p = p*f + 5.5504108665e-2f;
    p = p*f + 2.4022650696e-1f;
    p = p*f + 6.9314718056e-1f;
    p = p*f + 1.0f;
    return __int_as_float(__float_as_int(p) + (k << 23));
}

__device__ __forceinline__ void cp16(void* smem_dst, const void* gmem_src)
{
    unsigned d = (unsigned)__cvta_generic_to_shared(smem_dst);
    asm volatile("cp.async.cg.shared.global [%0], [%1], 16;\n" :: "r"(d), "l"(gmem_src));
}

/* ---------------- weight conversion fp32 -> fp16 (once per launch) ---------------- */
#define NQW (NL*DD*QKVLD)      /* 1572864 */
#define NOW (NL*INNER*DD)      /*  524288 */
__global__ void cvtw_kernel(const float* __restrict__ wq, const float* __restrict__ wo)
{
    int i = blockIdx.x*256 + threadIdx.x;
    if (i < NQW) g_wqh[i] = __float2half(wq[i]);
    if (i < NOW) g_woh[i] = __float2half(wo[i]);
}

/* ---------------- embed: convs + value proj + positional encoding ---------------- */
__global__ void embed_kernel(const float* __restrict__ x,
    const float* __restrict__ w1, const float* __restrict__ b1,
    const float* __restrict__ w2, const float* __restrict__ b2,
    const float* __restrict__ w3, const float* __restrict__ b3,
    const float* __restrict__ wv, const float* __restrict__ bv)
{
    int tok = blockIdx.x;
    int d   = threadIdx.x;
    int f   = tok % FF;
    int bw  = tok / FF;
    int w   = bw % WW;
    const float* xp = x + (size_t)(bw - w)*FF + f;

    float s0 = xp[(size_t)w*FF];
    float c1 = b1[f];
    #pragma unroll
    for (int j = 0; j < 4; j++) { int wi = w - (3-j);    if (wi >= 0) c1 += xp[(size_t)wi*FF]*w1[f*4+j]; }
    float c2 = b2[f];
    #pragma unroll
    for (int j = 0; j < 8; j++) { int wi = w - (7-j)*2;  if (wi >= 0) c2 += xp[(size_t)wi*FF]*w2[f*8+j]; }
    float c3 = b3[f];
    #pragma unroll
    for (int j = 0; j < 16; j++){ int wi = w - (15-j)*3; if (wi >= 0) c3 += xp[(size_t)wi*FF]*w3[f*16+j]; }

    float e = s0*wv[d] + c1*wv[DD+d] + c2*wv[2*DD+d] + c3*wv[3*DD+d] + bv[d];

    int   i2  = (d >> 1) * 2;
    float div = expf(-logf(10000.0f)/(float)DD * (float)i2);
    float ang = (float)w * div;
    float pe  = (d & 1) ? cosf(ang) : sinf(ang);

    g_h[(size_t)tok*DD + d] = e + pe;
}

/* ---------------- layernorm over D=128, half output ---------------- */
__global__ void ln_kernel(const float* __restrict__ gam, const float* __restrict__ bet)
{
    int tok = blockIdx.x;
    int d   = threadIdx.x;
    float v = g_h[(size_t)tok*DD + d];
    float s = v, ss = v*v;
    #pragma unroll
    for (int o = 16; o > 0; o >>= 1) {
        s  += __shfl_xor_sync(~0u, s,  o);
        ss += __shfl_xor_sync(~0u, ss, o);
    }
    __shared__ float sm[4], ssm[4];
    int wid = threadIdx.x >> 5;
    if ((threadIdx.x & 31) == 0) { sm[wid] = s; ssm[wid] = ss; }
    __syncthreads();
    s  = sm[0]+sm[1]+sm[2]+sm[3];
    ss = ssm[0]+ssm[1]+ssm[2]+ssm[3];
    float mean = s * (1.0f/DD);
    float var  = ss * (1.0f/DD) - mean*mean;
    float r    = rsqrtf(var + 1e-5f);
    g_hn[(size_t)tok*DD + d] = __float2half((v - mean)*r*gam[d] + bet[d]);
}

/* ---------------- fp16 WMMA GEMM, 2-stage cp.async double buffer ----------------
   C = A[M,K]@B[K,N]. BM=128, BN=64, BK=32. 8 warps (4M x 2N), 32x32 per warp.
   EPI=false: C half (qkv).  EPI=true: C float = acc + bias + resid (out-proj). */
#define AHLD 40
#define BHLD 72
#define AHST (128*AHLD)         /* halves per A stage */
#define BHST (32*BHLD)          /* halves per B stage */
#define CSLD 72
#define WG_SMEM (128*CSLD*4)    /* 36864 B >= 2*(AHST+BHST)*2 = 29696 B */

template<bool EPI>
__global__ void wgemm(const __half* __restrict__ A, const __half* __restrict__ B,
                      void* __restrict__ Cv, int K, int lda, int ldb, int ldc,
                      const float* __restrict__ bias, const float* __restrict__ resid)
{
    extern __shared__ char dsmb[];
    __half* Ah[2] = { (__half*)dsmb,           (__half*)dsmb + AHST };
    __half* Bh[2] = { (__half*)dsmb + 2*AHST,  (__half*)dsmb + 2*AHST + BHST };
    int m0 = blockIdx.y*128, n0 = blockIdx.x*64;
    int tid = threadIdx.x, w = tid >> 5;
    int wm = w & 3, wn = w >> 2;

    wmma::fragment<wmma::accumulator,16,16,16,float> acc[2][2];
    #pragma unroll
    for (int i=0;i<2;i++)
        #pragma unroll
        for (int j=0;j<2;j++) wmma::fill_fragment(acc[i][j], 0.0f);

    auto issue = [&](int st, int k0){
        #pragma unroll
        for (int i=0;i<2;i++){
            int idx = tid + i*256;                 /* 512 chunks of A (8 halves ea) */
            int r = idx >> 2, c8 = (idx & 3)*8;
            cp16(&Ah[st][r*AHLD + c8], &A[(size_t)(m0+r)*lda + k0 + c8]);
        }
        {
            int r = tid >> 3, c8 = (tid & 7)*8;    /* 256 chunks of B */
            cp16(&Bh[st][r*BHLD + c8], &B[(size_t)(k0+r)*ldb + n0 + c8]);
        }
        asm volatile("cp.async.commit_group;\n");
    };

    int nt = K >> 5;
    issue(0, 0);
    for (int t = 0; t < nt; t++){
        if (t+1 < nt){
            issue((t+1)&1, (t+1)<<5);
            asm volatile("cp.async.wait_group 1;\n" ::: "memory");
        } else {
            asm volatile("cp.async.wait_group 0;\n" ::: "memory");
        }
        __syncthreads();
        int st = t & 1;
        #pragma unroll
        for (int ks = 0; ks < 32; ks += 16){
            wmma::fragment<wmma::matrix_a,16,16,16,__half,wmma::row_major> af[2];
            wmma::fragment<wmma::matrix_b,16,16,16,__half,wmma::row_major> bf[2];
            #pragma unroll
            for (int i=0;i<2;i++)
                wmma::load_matrix_sync(af[i], &Ah[st][(wm*32 + i*16)*AHLD + ks], AHLD);
            #pragma unroll
            for (int j=0;j<2;j++)
                wmma::load_matrix_sync(bf[j], &Bh[st][ks*BHLD + wn*32 + j*16], BHLD);
            #pragma unroll
            for (int i=0;i<2;i++)
                #pragma unroll
                for (int j=0;j<2;j++)
                    wmma::mma_sync(acc[i][j], af[i], bf[j], acc[i][j]);
        }
        __syncthreads();
    }

    float* Cs = (float*)dsmb;                      /* 128 x CSLD fp32 staging */
    #pragma unroll
    for (int i=0;i<2;i++)
        #pragma unroll
        for (int j=0;j<2;j++)
            wmma::store_matrix_sync(&Cs[(wm*32 + i*16)*CSLD + wn*32 + j*16],
                                    acc[i][j], CSLD, wmma::mem_row_major);
    __syncthreads();

    if (!EPI) {
        __half* C = (__half*)Cv;
        #pragma unroll
        for (int i=0;i<8;i++){
            int idx = tid + i*256;
            int r = idx >> 4, c4 = (idx & 15)*4;
            float4 v = *(float4*)&Cs[r*CSLD + c4];
            __half2 h0 = __float22half2_rn(make_float2(v.x, v.y));
            __half2 h1 = __float22half2_rn(make_float2(v.z, v.w));
            __half2* dst = (__half2*)&C[(size_t)(m0+r)*ldc + n0 + c4];
            dst[0] = h0; dst[1] = h1;
        }
    } else {
        float* C = (float*)Cv;
        #pragma unroll
        for (int i=0;i<8;i++){
            int idx = tid + i*256;
            int r = idx >> 4, c4 = (idx & 15)*4;
            float4 v  = *(float4*)&Cs[r*CSLD + c4];
            float4 bb = *(const float4*)&bias[n0 + c4];
            float4 rr = *(const float4*)&resid[(size_t)(m0+r)*ldc + n0 + c4];
            v.x += bb.x + rr.x; v.y += bb.y + rr.y;
            v.z += bb.z + rr.z; v.w += bb.w + rr.w;
            *(float4*)&C[(size_t)(m0+r)*ldc + n0 + c4] = v;
        }
    }
}

/* ---------------- variable attention (F=16): fp16 WMMA, warp per (bw,head) ---------------- */
#define VPAD 24
__global__ void vattn_kernel(const __half* __restrict__ qkv, __half* __restrict__ o)
{
    __shared__ float  Pf [HH][16*VPAD];     /* scores fp32; reused as O staging */
    __shared__ __half Phh[HH][16*VPAD];     /* probs half */
    int bw = blockIdx.x;
    int w  = threadIdx.x >> 5, lane = threadIdx.x & 31;
    const __half* q = qkv + (size_t)bw*FF*QKVLD + w*DD;
    const __half* k = q + INNER;
    const __half* v = q + 2*INNER;
    __half* op = o + (size_t)bw*FF*INNER + w*DD;
    float*  Pw = &Pf[w][0];
    __half* Ph = &Phh[w][0];

    /* S = Q @ K^T  (16x16x128) */
    wmma::fragment<wmma::accumulator,16,16,16,float> sf;
    wmma::fill_fragment(sf, 0.0f);
    #pragma unroll
    for (int ks = 0; ks < DD; ks += 16){
        wmma::fragment<wmma::matrix_a,16,16,16,__half,wmma::row_major> af;
        wmma::fragment<wmma::matrix_b,16,16,16,__half,wmma::col_major> bf;
        wmma::load_matrix_sync(af, q + ks, QKVLD);
        wmma::load_matrix_sync(bf, k + ks, QKVLD);
        wmma::mma_sync(sf, af, bf, sf);
    }
    #pragma unroll
    for (int e = 0; e < sf.num_elements; e++) sf.x[e] *= SCALE;
    wmma::store_matrix_sync(Pw, sf, VPAD, wmma::mem_row_major);
    __syncwarp();

    /* softmax: one lane per row; write probs as half */
    if (lane < FF){
        float* row = Pw + lane*VPAD;
        __half* rh = Ph + lane*VPAD;
        float mx = -1e30f;
        #pragma unroll
        for (int j=0;j<FF;j++) mx = fmaxf(mx, row[j]);
        float tmp[FF]; float s = 0.f;
        #pragma unroll
        for (int j=0;j<FF;j++){ tmp[j] = fexp(row[j]-mx); s += tmp[j]; }
        float inv = 1.0f/s;
        #pragma unroll
        for (int j=0;j<FF;j++) rh[j] = __float2half(tmp[j]*inv);
    }
    __syncwarp();

    /* O = P @ V  (16x128x16): single A fragment, 8 n-chunks */
    wmma::fragment<wmma::matrix_a,16,16,16,__half,wmma::row_major> pf;
    wmma::load_matrix_sync(pf, Ph, VPAD);
    __syncwarp();
    #pragma unroll
    for (int n0 = 0; n0 < DD; n0 += 16){
        wmma::fragment<wmma::accumulator,16,16,16,float> of;
        wmma::fill_fragment(of, 0.0f);
        wmma::fragment<wmma::matrix_b,16,16,16,__half,wmma::row_major> vf;
        wmma::load_matrix_sync(vf, v + n0, QKVLD);
        wmma::mma_sync(of, pf, vf, of);
        wmma::store_matrix_sync(Pw, of, VPAD, wmma::mem_row_major);
        __syncwarp();
        {   /* convert + write 16x16 half tile: lane -> (row, 8 cols) */
            int r = lane >> 1, c0 = (lane & 1)*8;
            const float* src = Pw + r*VPAD + c0;
            __half2 hh[4];
            #pragma unroll
            for (int u=0;u<4;u++)
                hh[u] = __float22half2_rn(make_float2(src[2*u], src[2*u+1]));
            *(uint4*)(op + (size_t)r*INNER + n0 + c0) = *(uint4*)hh;
        }
        __syncwarp();
    }
}

/* ---------------- fused temporal attention (fp16 WMMA, exact softmax) ----------------
   block = (b,f,h) x 64-row i-tile. 256 threads = 8 warps. Full K (and V, aliased)
   resident in smem; V cp.async overlapped with softmax. smem = 188672 B dynamic. */
#define TI   64
#define SLDF 264               /* fp32 score row stride  */
#define PHLD 264               /* half prob row stride   */
#define QHLD 136
#define KHLD 136
#define OLDF 136
#define OFF_SS 0
#define OFF_PH (OFF_SS + TI*SLDF*4)            /* 67584  */
#define OFF_QH (OFF_PH + TI*PHLD*2)            /* 101376 */
#define OFF_KH (OFF_QH + TI*QHLD*2)            /* 118784 */
#define OFF_LL (OFF_KH + WW*KHLD*2)            /* 188416 */
#define TATTN_SMEM (OFF_LL + TI*4)             /* 188672 */

__global__ void tattn_kernel(const __half* __restrict__ qkv, __half* __restrict__ o)
{
    extern __shared__ char smb[];
    float*  Ss = (float*) (smb + OFF_SS);
    __half* Ph = (__half*)(smb + OFF_PH);
    __half* Qh = (__half*)(smb + OFF_QH);
    __half* Kh = (__half*)(smb + OFF_KH);      /* V aliases this after phase 1 */
    float*  Ll = (float*) (smb + OFF_LL);
    float*  Osf = Ss;                          /* O staging reuses score region */

    int batch = blockIdx.y;
    int hd = batch & 7, f = (batch >> 3) & 15, b = batch >> 7;
    int i0 = blockIdx.x * TI;
    size_t baseQ = ((size_t)(b*WW)*FF + f)*QKVLD + hd*DD;
    size_t baseK = baseQ + INNER;
    size_t baseV = baseQ + 2*INNER;
    size_t baseO = ((size_t)(b*WW)*FF + f)*INNER + hd*DD;
    int tid = threadIdx.x, w = tid >> 5;
    int wm = w & 1, wn = w >> 1;

    /* async load Q (64x128) and full K (256x128) */
    #pragma unroll
    for (int i=0;i<4;i++){
        int idx = tid + i*256;
        int r = idx >> 4, c8 = (idx & 15)*8;
        cp16(&Qh[r*QHLD + c8], &qkv[baseQ + (size_t)(i0+r)*RS + c8]);
    }
    #pragma unroll
    for (int i=0;i<16;i++){
        int idx = tid + i*256;
        int r = idx >> 4, c8 = (idx & 15)*8;
        cp16(&Kh[r*KHLD + c8], &qkv[baseK + (size_t)r*RS + c8]);
    }
    asm volatile("cp.async.commit_group;\n");
    asm volatile("cp.async.wait_group 0;\n" ::: "memory");
    __syncthreads();

    /* phase 1: S = Q @ K^T  (64 x 256, K=128). warp tile 32x64 -> sf[2][4] */
    {
        wmma::fragment<wmma::accumulator,16,16,16,float> sf[2][4];
        #pragma unroll
        for (int i=0;i<2;i++)
            #pragma unroll
            for (int j=0;j<4;j++) wmma::fill_fragment(sf[i][j], 0.0f);
        #pragma unroll
        for (int ks=0; ks<DD; ks+=16){
            wmma::fragment<wmma::matrix_a,16,16,16,__half,wmma::row_major> af[2];
            wmma::fragment<wmma::matrix_b,16,16,16,__half,wmma::col_major> bf[4];
            #pragma unroll
            for (int i=0;i<2;i++)
                wmma::load_matrix_sync(af[i], &Qh[(wm*32 + i*16)*QHLD + ks], QHLD);
            #pragma unroll
            for (int j=0;j<4;j++)
                wmma::load_matrix_sync(bf[j], &Kh[(wn*64 + j*16)*KHLD + ks], KHLD);
            #pragma unroll
            for (int i=0;i<2;i++)
                #pragma unroll
                for (int j=0;j<4;j++)
                    wmma::mma_sync(sf[i][j], af[i], bf[j], sf[i][j]);
        }
        #pragma unroll
        for (int i=0;i<2;i++)
            #pragma unroll
            for (int j=0;j<4;j++)
                wmma::store_matrix_sync(&Ss[(wm*32 + i*16)*SLDF + wn*64 + j*16],
                                        sf[i][j], SLDF, wmma::mem_row_major);
    }
    __syncthreads();

    /* issue V load into Kh region (overlaps with softmax below) */
    #pragma unroll
    for (int i=0;i<16;i++){
        int idx = tid + i*256;
        int r = idx >> 4, c8 = (idx & 15)*8;
        cp16(&Kh[r*KHLD + c8], &qkv[baseV + (size_t)r*RS + c8]);
    }
    asm volatile("cp.async.commit_group;\n");

    /* softmax: 4 threads per row, 64 cols each; SCALE folded into exp arg */
    {
        int r = tid >> 2, q4 = tid & 3;
        float* row = Ss + r*SLDF + q4*64;
        __half* ph = Ph + r*PHLD + q4*64;
        float mx = -1e30f;
        #pragma unroll 8
        for (int c=0;c<64;c++) mx = fmaxf(mx, row[c]);
        mx = fmaxf(mx, __shfl_xor_sync(0xFFFFFFFFu, mx, 1));
        mx = fmaxf(mx, __shfl_xor_sync(0xFFFFFFFFu, mx, 2));
        float s = 0.f;
        #pragma unroll 8
        for (int c=0;c<64;c++){
            float p = fexp((row[c]-mx)*SCALE);
            ph[c] = __float2half(p);
            s += p;
        }
        s += __shfl_xor_sync(0xFFFFFFFFu, s, 1);
        s += __shfl_xor_sync(0xFFFFFFFFu, s, 2);
        if (q4 == 0) Ll[r] = 1.0f/s;
    }
    asm volatile("cp.async.wait_group 0;\n" ::: "memory");
    __syncthreads();

    /* phase 2: O = P @ V  (64 x 128, K=256). warp tile 32x32 -> of[2][2] */
    {
        wmma::fragment<wmma::accumulator,16,16,16,float> of[2][2];
        #pragma unroll
        for (int i=0;i<2;i++)
            #pragma unroll
            for (int j=0;j<2;j++) wmma::fill_fragment(of[i][j], 0.0f);
        #pragma unroll
        for (int ks=0; ks<WW; ks+=16){
            wmma::fragment<wmma::matrix_a,16,16,16,__half,wmma::row_major> pf[2];
            wmma::fragment<wmma::matrix_b,16,16,16,__half,wmma::row_major> vf[2];
            #pragma unroll
            for (int i=0;i<2;i++)
                wmma::load_matrix_sync(pf[i], &Ph[(wm*32 + i*16)*PHLD + ks], PHLD);
            #pragma unroll
            for (int j=0;j<2;j++)
                wmma::load_matrix_sync(vf[j], &Kh[ks*KHLD + wn*32 + j*16], KHLD);
            #pragma unroll
            for (int i=0;i<2;i++)
                #pragma unroll
                for (int j=0;j<2;j++)
                    wmma::mma_sync(of[i][j], pf[i], vf[j], of[i][j]);
        }
        __syncthreads();               /* Ss region now dead -> reuse as Osf */
        #pragma unroll
        for (int i=0;i<2;i++)
            #pragma unroll
            for (int j=0;j<2;j++)
                wmma::store_matrix_sync(&Osf[(wm*32 + i*16)*OLDF + wn*32 + j*16],
                                        of[i][j], OLDF, wmma::mem_row_major);
    }
    __syncthreads();

    /* epilogue: o(half) += Osf * (1/l) per row */
    #pragma unroll
    for (int i=0;i<8;i++){
        int idx = tid + i*256;
        int r = idx >> 5, c4 = (idx & 31)*4;
        float inv = Ll[r];
        float4 v = *(float4*)&Osf[r*OLDF + c4];
        __half2* gp = (__half2*)&o[baseO + (size_t)(i0 + r)*RO + c4];
        float2 f0 = __half22float2(gp[0]);
        float2 f1 = __half22float2(gp[1]);
        f0.x += v.x*inv; f0.y += v.y*inv;
        f1.x += v.z*inv; f1.y += v.w*inv;
        gp[0] = __float22half2_rn(f0);
        gp[1] = __float22half2_rn(f1);
    }
}

/* ---------------- head ---------------- */
__global__ void head_kernel(const float* __restrict__ wh, const float* __restrict__ bh,
                            float* __restrict__ out)
{
    int bw = blockIdx.x;
    int n = threadIdx.x >> 5, lane = threadIdx.x & 31;
    const float* hrow = g_h + (size_t)bw*(FF*DD);
    float acc = 0.f;
    #pragma unroll 4
    for (int k = lane; k < FF*DD; k += 32)
        acc += hrow[k]*wh[k*FF + n];
    #pragma unroll
    for (int o=16;o>0;o>>=1) acc += __shfl_xor_sync(~0u, acc, o);
    if (lane == 0) out[bw*FF + n] = acc + bh[n];
}

/* ---------------- launcher ---------------- */
extern "C" void kernel_launch(void* const* d_in, const int* in_sizes, int n_in,
                              void* d_out, int out_size)
{
    (void)in_sizes; (void)n_in; (void)out_size;
    const float* x   = (const float*)d_in[0];
    const float* w1  = (const float*)d_in[1];
    const float* b1  = (const float*)d_in[2];
    const float* w2  = (const float*)d_in[3];
    const float* b2  = (const float*)d_in[4];
    const float* w3  = (const float*)d_in[5];
    const float* b3  = (const float*)d_in[6];
    const float* wv  = (const float*)d_in[7];
    const float* bv  = (const float*)d_in[8];
    const float* lng = (const float*)d_in[9];
    const float* lnb = (const float*)d_in[10];
    const float* wq  = (const float*)d_in[11];
    const float* wo  = (const float*)d_in[12];
    const float* bo  = (const float*)d_in[13];
    const float* wh  = (const float*)d_in[14];
    const float* bh  = (const float*)d_in[15];
    float* out = (float*)d_out;

    float *p_h; __half *p_hn, *p_qkv, *p_o, *p_wqh, *p_woh;
    cudaGetSymbolAddress((void**)&p_h,   g_h);
    cudaGetSymbolAddress((void**)&p_hn,  g_hn);
    cudaGetSymbolAddress((void**)&p_qkv, g_qkv);
    cudaGetSymbolAddress((void**)&p_o,   g_o);
    cudaGetSymbolAddress((void**)&p_wqh, g_wqh);
    cudaGetSymbolAddress((void**)&p_woh, g_woh);

    cudaFuncSetAttribute(tattn_kernel,
        cudaFuncAttributeMaxDynamicSharedMemorySize, TATTN_SMEM);
    cudaFuncSetAttribute(wgemm<false>,
        cudaFuncAttributeMaxDynamicSharedMemorySize, WG_SMEM);
    cudaFuncSetAttribute(wgemm<true>,
        cudaFuncAttributeMaxDynamicSharedMemorySize, WG_SMEM);

    cvtw_kernel<<<(NQW + 255)/256, 256>>>(wq, wo);
    embed_kernel<<<NT, DD>>>(x, w1, b1, w2, b2, w3, b3, wv, bv);

    for (int l = 0; l < NL; l++) {
        ln_kernel<<<NT, DD>>>(lng + l*DD, lnb + l*DD);

        /* qkv = hn @ Wqkv[l] : [32768,128]@[128,3072], fp16 in, half out */
        wgemm<false><<<dim3(QKVLD/64, NT/128), 256, WG_SMEM>>>(
            p_hn, p_wqh + (size_t)l*DD*QKVLD, p_qkv,
            DD, DD, QKVLD, QKVLD, nullptr, nullptr);

        /* variable attention writes g_o (half) */
        vattn_kernel<<<BB*WW, 256>>>(p_qkv, p_o);

        /* fused temporal attention accumulates into g_o (half RMW) */
        tattn_kernel<<<dim3(WW/TI, BB*FF*HH), 256, TATTN_SMEM>>>(p_qkv, p_o);

        /* h = o @ Wout[l] + b_out[l] + h : [32768,1024]@[1024,128], fp32 out */
        wgemm<true><<<dim3(DD/64, NT/128), 256, WG_SMEM>>>(
            p_o, p_woh + (size_t)l*INNER*DD, p_h,
            INNER, INNER, DD, DD, bo + l*DD, p_h);
    }

    head_kernel<<<BB*WW, 512>>>(wh, bh, out);
}

// round 7
// speedup vs baseline: 3.9371x; 1.0223x over previous
#include <cuda_runtime.h>
#include <cuda_fp16.h>
#include <mma.h>
#include <math.h>
using namespace nvcuda;

#define BB 8
#define WW 256
#define FF 16
#define DD 128
#define HH 8
#define NL 4
#define INNER 1024
#define NT (BB*WW*FF)          /* 32768 tokens */
#define QKVLD 3072
#define SCALE 0.08838834764831845f   /* 128^-0.5 */
#define RS (FF*QKVLD)          /* 49152: row stride (per w) in qkv */
#define RO (FF*INNER)          /* 16384: row stride (per w) in o   */

/* ---------------- scratch (static __device__, no allocation) ---------------- */
__device__ float  g_h  [NT*DD];                     /* 16 MB  running hidden state */
__device__ __half g_hn [NT*DD];                     /*  8 MB  layernorm output     */
__device__ __half g_qkv[(size_t)NT*QKVLD];          /* 201 MB qkv activations      */
__device__ __half g_o  [(size_t)NT*INNER];          /*  67 MB attention output     */
__device__ __half g_wqh[NL*DD*QKVLD];               /*  3 MB  half qkv weights     */
__device__ __half g_woh[NL*INNER*DD];               /*  1 MB  half out weights     */

/* ---------------- fast exp on the FMA pipe ---------------- */
__device__ __forceinline__ float fexp(float x)
{
    x = fmaxf(x, -80.0f);
    float z  = x * 1.4426950408889634f;
    float zj = z + 12582912.0f;
    int   k  = __float_as_int(zj) - 0x4B400000;
    float f  = z - (zj - 12582912.0f);
    float p  = 1.3333558146e-3f;
    p = p*f + 9.6181291076e-3f;
    p = p*f + 5.5504108665e-2f;
    p = p*f + 2.4022650696e-1f;
    p = p*f + 6.9314718056e-1f;
    p = p*f + 1.0f;
    return __int_as_float(__float_as_int(p) + (k << 23));
}

__device__ __forceinline__ void cp16(void* smem_dst, const void* gmem_src)
{
    unsigned d = (unsigned)__cvta_generic_to_shared(smem_dst);
    asm volatile("cp.async.cg.shared.global [%0], [%1], 16;\n" :: "r"(d), "l"(gmem_src));
}

/* ---------------- weight conversion fp32 -> fp16 (once per launch) ---------------- */
#define NQW (NL*DD*QKVLD)      /* 1572864 */
#define NOW (NL*INNER*DD)      /*  524288 */
__global__ void cvtw_kernel(const float* __restrict__ wq, const float* __restrict__ wo)
{
    int i = blockIdx.x*256 + threadIdx.x;
    if (i < NQW) g_wqh[i] = __float2half(wq[i]);
    if (i < NOW) g_woh[i] = __float2half(wo[i]);
}

/* ---------------- embed: convs + value proj + positional encoding ---------------- */
__global__ void embed_kernel(const float* __restrict__ x,
    const float* __restrict__ w1, const float* __restrict__ b1,
    const float* __restrict__ w2, const float* __restrict__ b2,
    const float* __restrict__ w3, const float* __restrict__ b3,
    const float* __restrict__ wv, const float* __restrict__ bv)
{
    int tok = blockIdx.x;
    int d   = threadIdx.x;
    int f   = tok % FF;
    int bw  = tok / FF;
    int w   = bw % WW;
    const float* xp = x + (size_t)(bw - w)*FF + f;

    float s0 = xp[(size_t)w*FF];
    float c1 = b1[f];
    #pragma unroll
    for (int j = 0; j < 4; j++) { int wi = w - (3-j);    if (wi >= 0) c1 += xp[(size_t)wi*FF]*w1[f*4+j]; }
    float c2 = b2[f];
    #pragma unroll
    for (int j = 0; j < 8; j++) { int wi = w - (7-j)*2;  if (wi >= 0) c2 += xp[(size_t)wi*FF]*w2[f*8+j]; }
    float c3 = b3[f];
    #pragma unroll
    for (int j = 0; j < 16; j++){ int wi = w - (15-j)*3; if (wi >= 0) c3 += xp[(size_t)wi*FF]*w3[f*16+j]; }

    float e = s0*wv[d] + c1*wv[DD+d] + c2*wv[2*DD+d] + c3*wv[3*DD+d] + bv[d];

    int   i2  = (d >> 1) * 2;
    float div = expf(-logf(10000.0f)/(float)DD * (float)i2);
    float ang = (float)w * div;
    float pe  = (d & 1) ? cosf(ang) : sinf(ang);

    g_h[(size_t)tok*DD + d] = e + pe;
}

/* ---------------- layernorm over D=128, half output ---------------- */
__global__ void ln_kernel(const float* __restrict__ gam, const float* __restrict__ bet)
{
    int tok = blockIdx.x;
    int d   = threadIdx.x;
    float v = g_h[(size_t)tok*DD + d];
    float s = v, ss = v*v;
    #pragma unroll
    for (int o = 16; o > 0; o >>= 1) {
        s  += __shfl_xor_sync(~0u, s,  o);
        ss += __shfl_xor_sync(~0u, ss, o);
    }
    __shared__ float sm[4], ssm[4];
    int wid = threadIdx.x >> 5;
    if ((threadIdx.x & 31) == 0) { sm[wid] = s; ssm[wid] = ss; }
    __syncthreads();
    s  = sm[0]+sm[1]+sm[2]+sm[3];
    ss = ssm[0]+ssm[1]+ssm[2]+ssm[3];
    float mean = s * (1.0f/DD);
    float var  = ss * (1.0f/DD) - mean*mean;
    float r    = rsqrtf(var + 1e-5f);
    g_hn[(size_t)tok*DD + d] = __float2half((v - mean)*r*gam[d] + bet[d]);
}

/* ---------------- fp16 WMMA GEMM, BM=128 BN=128 BK=32, 2-stage cp.async ----------------
   8 warps (4M x 2N), warp tile 32x64.
   EPI=false: C half (qkv).  EPI=true: C float = acc + bias + resid (out-proj). */
#define AHLD 40
#define BHLD 136
#define AHST (128*AHLD)         /* halves per A stage */
#define BHST (32*BHLD)          /* halves per B stage */
#define CSLD 136
#define WG_SMEM (128*CSLD*4)    /* 69632 B >= 2*(AHST+BHST)*2 = 37888 B */

template<bool EPI>
__global__ void __launch_bounds__(256)
wgemm(const __half* __restrict__ A, const __half* __restrict__ B,
      void* __restrict__ Cv, int K, int lda, int ldb, int ldc,
      const float* __restrict__ bias, const float* __restrict__ resid)
{
    extern __shared__ char dsmb[];
    __half* Ah[2] = { (__half*)dsmb,           (__half*)dsmb + AHST };
    __half* Bh[2] = { (__half*)dsmb + 2*AHST,  (__half*)dsmb + 2*AHST + BHST };
    int m0 = blockIdx.y*128, n0 = blockIdx.x*128;
    int tid = threadIdx.x, w = tid >> 5;
    int wm = w & 3, wn = w >> 2;

    wmma::fragment<wmma::accumulator,16,16,16,float> acc[2][4];
    #pragma unroll
    for (int i=0;i<2;i++)
        #pragma unroll
        for (int j=0;j<4;j++) wmma::fill_fragment(acc[i][j], 0.0f);

    auto issue = [&](int st, int k0){
        #pragma unroll
        for (int i=0;i<2;i++){
            int idx = tid + i*256;                 /* 512 chunks of A (8 halves ea) */
            int r = idx >> 2, c8 = (idx & 3)*8;
            cp16(&Ah[st][r*AHLD + c8], &A[(size_t)(m0+r)*lda + k0 + c8]);
        }
        #pragma unroll
        for (int i=0;i<2;i++){
            int idx = tid + i*256;                 /* 512 chunks of B */
            int r = idx >> 4, c8 = (idx & 15)*8;
            cp16(&Bh[st][r*BHLD + c8], &B[(size_t)(k0+r)*ldb + n0 + c8]);
        }
        asm volatile("cp.async.commit_group;\n");
    };

    int nt = K >> 5;
    issue(0, 0);
    for (int t = 0; t < nt; t++){
        if (t+1 < nt){
            issue((t+1)&1, (t+1)<<5);
            asm volatile("cp.async.wait_group 1;\n" ::: "memory");
        } else {
            asm volatile("cp.async.wait_group 0;\n" ::: "memory");
        }
        __syncthreads();
        int st = t & 1;
        #pragma unroll
        for (int ks = 0; ks < 32; ks += 16){
            wmma::fragment<wmma::matrix_a,16,16,16,__half,wmma::row_major> af[2];
            #pragma unroll
            for (int i=0;i<2;i++)
                wmma::load_matrix_sync(af[i], &Ah[st][(wm*32 + i*16)*AHLD + ks], AHLD);
            #pragma unroll
            for (int j=0;j<4;j++){
                wmma::fragment<wmma::matrix_b,16,16,16,__half,wmma::row_major> bf;
                wmma::load_matrix_sync(bf, &Bh[st][ks*BHLD + wn*64 + j*16], BHLD);
                wmma::mma_sync(acc[0][j], af[0], bf, acc[0][j]);
                wmma::mma_sync(acc[1][j], af[1], bf, acc[1][j]);
            }
        }
        __syncthreads();
    }

    float* Cs = (float*)dsmb;                      /* 128 x CSLD fp32 staging */
    #pragma unroll
    for (int i=0;i<2;i++)
        #pragma unroll
        for (int j=0;j<4;j++)
            wmma::store_matrix_sync(&Cs[(wm*32 + i*16)*CSLD + wn*64 + j*16],
                                    acc[i][j], CSLD, wmma::mem_row_major);
    __syncthreads();

    if (!EPI) {
        __half* C = (__half*)Cv;
        #pragma unroll
        for (int i=0;i<8;i++){                     /* 2048 chunks of 8 cols */
            int idx = tid + i*256;
            int r = idx >> 4, c8 = (idx & 15)*8;
            float4 v0 = *(float4*)&Cs[r*CSLD + c8];
            float4 v1 = *(float4*)&Cs[r*CSLD + c8 + 4];
            __half2 hh[4];
            hh[0] = __float22half2_rn(make_float2(v0.x, v0.y));
            hh[1] = __float22half2_rn(make_float2(v0.z, v0.w));
            hh[2] = __float22half2_rn(make_float2(v1.x, v1.y));
            hh[3] = __float22half2_rn(make_float2(v1.z, v1.w));
            *(uint4*)&C[(size_t)(m0+r)*ldc + n0 + c8] = *(uint4*)hh;
        }
    } else {
        float* C = (float*)Cv;
        #pragma unroll
        for (int i=0;i<16;i++){                    /* 4096 chunks of 4 cols */
            int idx = tid + i*256;
            int r = idx >> 5, c4 = (idx & 31)*4;
            float4 v  = *(float4*)&Cs[r*CSLD + c4];
            float4 bb = *(const float4*)&bias[n0 + c4];
            float4 rr = *(const float4*)&resid[(size_t)(m0+r)*ldc + n0 + c4];
            v.x += bb.x + rr.x; v.y += bb.y + rr.y;
            v.z += bb.z + rr.z; v.w += bb.w + rr.w;
            *(float4*)&C[(size_t)(m0+r)*ldc + n0 + c4] = v;
        }
    }
}

/* ---------------- variable attention (F=16): fp16 WMMA, warp per (bw,head) ---------------- */
#define VPAD 24
__global__ void vattn_kernel(const __half* __restrict__ qkv, __half* __restrict__ o)
{
    __shared__ float  Pf [HH][16*VPAD];     /* scores fp32; reused as O staging */
    __shared__ __half Phh[HH][16*VPAD];     /* probs half */
    int bw = blockIdx.x;
    int w  = threadIdx.x >> 5, lane = threadIdx.x & 31;
    const __half* q = qkv + (size_t)bw*FF*QKVLD + w*DD;
    const __half* k = q + INNER;
    const __half* v = q + 2*INNER;
    __half* op = o + (size_t)bw*FF*INNER + w*DD;
    float*  Pw = &Pf[w][0];
    __half* Ph = &Phh[w][0];

    /* S = Q @ K^T  (16x16x128) */
    wmma::fragment<wmma::accumulator,16,16,16,float> sf;
    wmma::fill_fragment(sf, 0.0f);
    #pragma unroll
    for (int ks = 0; ks < DD; ks += 16){
        wmma::fragment<wmma::matrix_a,16,16,16,__half,wmma::row_major> af;
        wmma::fragment<wmma::matrix_b,16,16,16,__half,wmma::col_major> bf;
        wmma::load_matrix_sync(af, q + ks, QKVLD);
        wmma::load_matrix_sync(bf, k + ks, QKVLD);
        wmma::mma_sync(sf, af, bf, sf);
    }
    #pragma unroll
    for (int e = 0; e < sf.num_elements; e++) sf.x[e] *= SCALE;
    wmma::store_matrix_sync(Pw, sf, VPAD, wmma::mem_row_major);
    __syncwarp();

    /* softmax: one lane per row; write probs as half */
    if (lane < FF){
        float* row = Pw + lane*VPAD;
        __half* rh = Ph + lane*VPAD;
        float mx = -1e30f;
        #pragma unroll
        for (int j=0;j<FF;j++) mx = fmaxf(mx, row[j]);
        float tmp[FF]; float s = 0.f;
        #pragma unroll
        for (int j=0;j<FF;j++){ tmp[j] = fexp(row[j]-mx); s += tmp[j]; }
        float inv = 1.0f/s;
        #pragma unroll
        for (int j=0;j<FF;j++) rh[j] = __float2half(tmp[j]*inv);
    }
    __syncwarp();

    /* O = P @ V  (16x128x16): single A fragment, 8 n-chunks */
    wmma::fragment<wmma::matrix_a,16,16,16,__half,wmma::row_major> pf;
    wmma::load_matrix_sync(pf, Ph, VPAD);
    __syncwarp();
    #pragma unroll
    for (int n0 = 0; n0 < DD; n0 += 16){
        wmma::fragment<wmma::accumulator,16,16,16,float> of;
        wmma::fill_fragment(of, 0.0f);
        wmma::fragment<wmma::matrix_b,16,16,16,__half,wmma::row_major> vf;
        wmma::load_matrix_sync(vf, v + n0, QKVLD);
        wmma::mma_sync(of, pf, vf, of);
        wmma::store_matrix_sync(Pw, of, VPAD, wmma::mem_row_major);
        __syncwarp();
        {   /* convert + write 16x16 half tile: lane -> (row, 8 cols) */
            int r = lane >> 1, c0 = (lane & 1)*8;
            const float* src = Pw + r*VPAD + c0;
            __half2 hh[4];
            #pragma unroll
            for (int u=0;u<4;u++)
                hh[u] = __float22half2_rn(make_float2(src[2*u], src[2*u+1]));
            *(uint4*)(op + (size_t)r*INNER + n0 + c0) = *(uint4*)hh;
        }
        __syncwarp();
    }
}

/* ---------------- fused temporal attention (fp16 WMMA, exact softmax) ----------------
   block = (b,f,h) x 64-row i-tile. 256 threads = 8 warps. Full K (and V, aliased)
   resident in smem; V cp.async overlapped with softmax. smem = 188672 B dynamic. */
#define TI   64
#define SLDF 264               /* fp32 score row stride  */
#define PHLD 264               /* half prob row stride   */
#define QHLD 136
#define KHLD 136
#define OLDF 136
#define OFF_SS 0
#define OFF_PH (OFF_SS + TI*SLDF*4)            /* 67584  */
#define OFF_QH (OFF_PH + TI*PHLD*2)            /* 101376 */
#define OFF_KH (OFF_QH + TI*QHLD*2)            /* 118784 */
#define OFF_LL (OFF_KH + WW*KHLD*2)            /* 188416 */
#define TATTN_SMEM (OFF_LL + TI*4)             /* 188672 */

__global__ void tattn_kernel(const __half* __restrict__ qkv, __half* __restrict__ o)
{
    extern __shared__ char smb[];
    float*  Ss = (float*) (smb + OFF_SS);
    __half* Ph = (__half*)(smb + OFF_PH);
    __half* Qh = (__half*)(smb + OFF_QH);
    __half* Kh = (__half*)(smb + OFF_KH);      /* V aliases this after phase 1 */
    float*  Ll = (float*) (smb + OFF_LL);
    float*  Osf = Ss;                          /* O staging reuses score region */

    int batch = blockIdx.y;
    int hd = batch & 7, f = (batch >> 3) & 15, b = batch >> 7;
    int i0 = blockIdx.x * TI;
    size_t baseQ = ((size_t)(b*WW)*FF + f)*QKVLD + hd*DD;
    size_t baseK = baseQ + INNER;
    size_t baseV = baseQ + 2*INNER;
    size_t baseO = ((size_t)(b*WW)*FF + f)*INNER + hd*DD;
    int tid = threadIdx.x, w = tid >> 5;
    int wm = w & 1, wn = w >> 1;

    /* async load Q (64x128) and full K (256x128) */
    #pragma unroll
    for (int i=0;i<4;i++){
        int idx = tid + i*256;
        int r = idx >> 4, c8 = (idx & 15)*8;
        cp16(&Qh[r*QHLD + c8], &qkv[baseQ + (size_t)(i0+r)*RS + c8]);
    }
    #pragma unroll
    for (int i=0;i<16;i++){
        int idx = tid + i*256;
        int r = idx >> 4, c8 = (idx & 15)*8;
        cp16(&Kh[r*KHLD + c8], &qkv[baseK + (size_t)r*RS + c8]);
    }
    asm volatile("cp.async.commit_group;\n");
    asm volatile("cp.async.wait_group 0;\n" ::: "memory");
    __syncthreads();

    /* phase 1: S = Q @ K^T  (64 x 256, K=128). warp tile 32x64 -> sf[2][4] */
    {
        wmma::fragment<wmma::accumulator,16,16,16,float> sf[2][4];
        #pragma unroll
        for (int i=0;i<2;i++)
            #pragma unroll
            for (int j=0;j<4;j++) wmma::fill_fragment(sf[i][j], 0.0f);
        #pragma unroll
        for (int ks=0; ks<DD; ks+=16){
            wmma::fragment<wmma::matrix_a,16,16,16,__half,wmma::row_major> af[2];
            wmma::fragment<wmma::matrix_b,16,16,16,__half,wmma::col_major> bf[4];
            #pragma unroll
            for (int i=0;i<2;i++)
                wmma::load_matrix_sync(af[i], &Qh[(wm*32 + i*16)*QHLD + ks], QHLD);
            #pragma unroll
            for (int j=0;j<4;j++)
                wmma::load_matrix_sync(bf[j], &Kh[(wn*64 + j*16)*KHLD + ks], KHLD);
            #pragma unroll
            for (int i=0;i<2;i++)
                #pragma unroll
                for (int j=0;j<4;j++)
                    wmma::mma_sync(sf[i][j], af[i], bf[j], sf[i][j]);
        }
        #pragma unroll
        for (int i=0;i<2;i++)
            #pragma unroll
            for (int j=0;j<4;j++)
                wmma::store_matrix_sync(&Ss[(wm*32 + i*16)*SLDF + wn*64 + j*16],
                                        sf[i][j], SLDF, wmma::mem_row_major);
    }
    __syncthreads();

    /* issue V load into Kh region (overlaps with softmax below) */
    #pragma unroll
    for (int i=0;i<16;i++){
        int idx = tid + i*256;
        int r = idx >> 4, c8 = (idx & 15)*8;
        cp16(&Kh[r*KHLD + c8], &qkv[baseV + (size_t)r*RS + c8]);
    }
    asm volatile("cp.async.commit_group;\n");

    /* softmax: 4 threads per row, 64 cols each; SCALE folded into exp arg */
    {
        int r = tid >> 2, q4 = tid & 3;
        float* row = Ss + r*SLDF + q4*64;
        __half* ph = Ph + r*PHLD + q4*64;
        float mx = -1e30f;
        #pragma unroll 8
        for (int c=0;c<64;c++) mx = fmaxf(mx, row[c]);
        mx = fmaxf(mx, __shfl_xor_sync(0xFFFFFFFFu, mx, 1));
        mx = fmaxf(mx, __shfl_xor_sync(0xFFFFFFFFu, mx, 2));
        float s = 0.f;
        #pragma unroll 8
        for (int c=0;c<64;c++){
            float p = fexp((row[c]-mx)*SCALE);
            ph[c] = __float2half(p);
            s += p;
        }
        s += __shfl_xor_sync(0xFFFFFFFFu, s, 1);
        s += __shfl_xor_sync(0xFFFFFFFFu, s, 2);
        if (q4 == 0) Ll[r] = 1.0f/s;
    }
    asm volatile("cp.async.wait_group 0;\n" ::: "memory");
    __syncthreads();

    /* phase 2: O = P @ V  (64 x 128, K=256). warp tile 32x32 -> of[2][2] */
    {
        wmma::fragment<wmma::accumulator,16,16,16,float> of[2][2];
        #pragma unroll
        for (int i=0;i<2;i++)
            #pragma unroll
            for (int j=0;j<2;j++) wmma::fill_fragment(of[i][j], 0.0f);
        #pragma unroll
        for (int ks=0; ks<WW; ks+=16){
            wmma::fragment<wmma::matrix_a,16,16,16,__half,wmma::row_major> pf[2];
            wmma::fragment<wmma::matrix_b,16,16,16,__half,wmma::row_major> vf[2];
            #pragma unroll
            for (int i=0;i<2;i++)
                wmma::load_matrix_sync(pf[i], &Ph[(wm*32 + i*16)*PHLD + ks], PHLD);
            #pragma unroll
            for (int j=0;j<2;j++)
                wmma::load_matrix_sync(vf[j], &Kh[ks*KHLD + wn*32 + j*16], KHLD);
            #pragma unroll
            for (int i=0;i<2;i++)
                #pragma unroll
                for (int j=0;j<2;j++)
                    wmma::mma_sync(of[i][j], pf[i], vf[j], of[i][j]);
        }
        __syncthreads();               /* Ss region now dead -> reuse as Osf */
        #pragma unroll
        for (int i=0;i<2;i++)
            #pragma unroll
            for (int j=0;j<2;j++)
                wmma::store_matrix_sync(&Osf[(wm*32 + i*16)*OLDF + wn*32 + j*16],
                                        of[i][j], OLDF, wmma::mem_row_major);
    }
    __syncthreads();

    /* epilogue: o(half) += Osf * (1/l) per row */
    #pragma unroll
    for (int i=0;i<8;i++){
        int idx = tid + i*256;
        int r = idx >> 5, c4 = (idx & 31)*4;
        float inv = Ll[r];
        float4 v = *(float4*)&Osf[r*OLDF + c4];
        __half2* gp = (__half2*)&o[baseO + (size_t)(i0 + r)*RO + c4];
        float2 f0 = __half22float2(gp[0]);
        float2 f1 = __half22float2(gp[1]);
        f0.x += v.x*inv; f0.y += v.y*inv;
        f1.x += v.z*inv; f1.y += v.w*inv;
        gp[0] = __float22half2_rn(f0);
        gp[1] = __float22half2_rn(f1);
    }
}

/* ---------------- head ---------------- */
__global__ void head_kernel(const float* __restrict__ wh, const float* __restrict__ bh,
                            float* __restrict__ out)
{
    int bw = blockIdx.x;
    int n = threadIdx.x >> 5, lane = threadIdx.x & 31;
    const float* hrow = g_h + (size_t)bw*(FF*DD);
    float acc = 0.f;
    #pragma unroll 4
    for (int k = lane; k < FF*DD; k += 32)
        acc += hrow[k]*wh[k*FF + n];
    #pragma unroll
    for (int o=16;o>0;o>>=1) acc += __shfl_xor_sync(~0u, acc, o);
    if (lane == 0) out[bw*FF + n] = acc + bh[n];
}

/* ---------------- launcher ---------------- */
extern "C" void kernel_launch(void* const* d_in, const int* in_sizes, int n_in,
                              void* d_out, int out_size)
{
    (void)in_sizes; (void)n_in; (void)out_size;
    const float* x   = (const float*)d_in[0];
    const float* w1  = (const float*)d_in[1];
    const float* b1  = (const float*)d_in[2];
    const float* w2  = (const float*)d_in[3];
    const float* b2  = (const float*)d_in[4];
    const float* w3  = (const float*)d_in[5];
    const float* b3  = (const float*)d_in[6];
    const float* wv  = (const float*)d_in[7];
    const float* bv  = (const float*)d_in[8];
    const float* lng = (const float*)d_in[9];
    const float* lnb = (const float*)d_in[10];
    const float* wq  = (const float*)d_in[11];
    const float* wo  = (const float*)d_in[12];
    const float* bo  = (const float*)d_in[13];
    const float* wh  = (const float*)d_in[14];
    const float* bh  = (const float*)d_in[15];
    float* out = (float*)d_out;

    float *p_h; __half *p_hn, *p_qkv, *p_o, *p_wqh, *p_woh;
    cudaGetSymbolAddress((void**)&p_h,   g_h);
    cudaGetSymbolAddress((void**)&p_hn,  g_hn);
    cudaGetSymbolAddress((void**)&p_qkv, g_qkv);
    cudaGetSymbolAddress((void**)&p_o,   g_o);
    cudaGetSymbolAddress((void**)&p_wqh, g_wqh);
    cudaGetSymbolAddress((void**)&p_woh, g_woh);

    cudaFuncSetAttribute(tattn_kernel,
        cudaFuncAttributeMaxDynamicSharedMemorySize, TATTN_SMEM);
    cudaFuncSetAttribute(wgemm<false>,
        cudaFuncAttributeMaxDynamicSharedMemorySize, WG_SMEM);
    cudaFuncSetAttribute(wgemm<true>,
        cudaFuncAttributeMaxDynamicSharedMemorySize, WG_SMEM);

    cvtw_kernel<<<(NQW + 255)/256, 256>>>(wq, wo);
    embed_kernel<<<NT, DD>>>(x, w1, b1, w2, b2, w3, b3, wv, bv);

    for (int l = 0; l < NL; l++) {
        ln_kernel<<<NT, DD>>>(lng + l*DD, lnb + l*DD);

        /* qkv = hn @ Wqkv[l] : [32768,128]@[128,3072], fp16 in, half out */
        wgemm<false><<<dim3(QKVLD/128, NT/128), 256, WG_SMEM>>>(
            p_hn, p_wqh + (size_t)l*DD*QKVLD, p_qkv,
            DD, DD, QKVLD, QKVLD, nullptr, nullptr);

        /* variable attention writes g_o (half) */
        vattn_kernel<<<BB*WW, 256>>>(p_qkv, p_o);

        /* fused temporal attention accumulates into g_o (half RMW) */
        tattn_kernel<<<dim3(WW/TI, BB*FF*HH), 256, TATTN_SMEM>>>(p_qkv, p_o);

        /* h = o @ Wout[l] + b_out[l] + h : [32768,1024]@[1024,128], fp32 out */
        wgemm<true><<<dim3(DD/128, NT/128), 256, WG_SMEM>>>(
            p_o, p_woh + (size_t)l*INNER*DD, p_h,
            INNER, INNER, DD, DD, bo + l*DD, p_h);
    }

    head_kernel<<<BB*WW, 512>>>(wh, bh, out);
}

// round 8
// speedup vs baseline: 4.2242x; 1.0729x over previous
#include <cuda_runtime.h>
#include <cuda_fp16.h>
#include <mma.h>
#include <math.h>
using namespace nvcuda;

#define BB 8
#define WW 256
#define FF 16
#define DD 128
#define HH 8
#define NL 4
#define INNER 1024
#define NT (BB*WW*FF)          /* 32768 tokens */
#define QKVLD 3072
#define SCALE 0.08838834764831845f   /* 128^-0.5 */
#define RS (FF*QKVLD)          /* 49152: row stride (per w) in qkv */
#define RO (FF*INNER)          /* 16384: row stride (per w) in o   */

/* ---------------- scratch (static __device__, no allocation) ---------------- */
__device__ float  g_h  [NT*DD];                     /* 16 MB  running hidden state */
__device__ __half g_qkv[(size_t)NT*QKVLD];          /* 201 MB qkv activations      */
__device__ __half g_o  [(size_t)NT*INNER];          /*  67 MB attention output     */
__device__ __half g_wqh[NL*DD*QKVLD];               /*  3 MB  half qkv weights     */
__device__ __half g_woh[NL*INNER*DD];               /*  1 MB  half out weights     */

/* ---------------- fast exp on the FMA pipe ---------------- */
__device__ __forceinline__ float fexp(float x)
{
    x = fmaxf(x, -80.0f);
    float z  = x * 1.4426950408889634f;
    float zj = z + 12582912.0f;
    int   k  = __float_as_int(zj) - 0x4B400000;
    float f  = z - (zj - 12582912.0f);
    float p  = 1.3333558146e-3f;
    p = p*f + 9.6181291076e-3f;
    p = p*f + 5.5504108665e-2f;
    p = p*f + 2.4022650696e-1f;
    p = p*f + 6.9314718056e-1f;
    p = p*f + 1.0f;
    return __int_as_float(__float_as_int(p) + (k << 23));
}

__device__ __forceinline__ void cp16(void* smem_dst, const void* gmem_src)
{
    unsigned d = (unsigned)__cvta_generic_to_shared(smem_dst);
    asm volatile("cp.async.cg.shared.global [%0], [%1], 16;\n" :: "r"(d), "l"(gmem_src));
}

/* ---------------- weight conversion fp32 -> fp16 (once per launch) ---------------- */
#define NQW (NL*DD*QKVLD)      /* 1572864 */
#define NOW (NL*INNER*DD)      /*  524288 */
__global__ void cvtw_kernel(const float* __restrict__ wq, const float* __restrict__ wo)
{
    int i = blockIdx.x*256 + threadIdx.x;
    if (i < NQW) g_wqh[i] = __float2half(wq[i]);
    if (i < NOW) g_woh[i] = __float2half(wo[i]);
}

/* ---------------- embed: convs + value proj + positional encoding ---------------- */
__global__ void embed_kernel(const float* __restrict__ x,
    const float* __restrict__ w1, const float* __restrict__ b1,
    const float* __restrict__ w2, const float* __restrict__ b2,
    const float* __restrict__ w3, const float* __restrict__ b3,
    const float* __restrict__ wv, const float* __restrict__ bv)
{
    int tok = blockIdx.x;
    int d   = threadIdx.x;
    int f   = tok % FF;
    int bw  = tok / FF;
    int w   = bw % WW;
    const float* xp = x + (size_t)(bw - w)*FF + f;

    float s0 = xp[(size_t)w*FF];
    float c1 = b1[f];
    #pragma unroll
    for (int j = 0; j < 4; j++) { int wi = w - (3-j);    if (wi >= 0) c1 += xp[(size_t)wi*FF]*w1[f*4+j]; }
    float c2 = b2[f];
    #pragma unroll
    for (int j = 0; j < 8; j++) { int wi = w - (7-j)*2;  if (wi >= 0) c2 += xp[(size_t)wi*FF]*w2[f*8+j]; }
    float c3 = b3[f];
    #pragma unroll
    for (int j = 0; j < 16; j++){ int wi = w - (15-j)*3; if (wi >= 0) c3 += xp[(size_t)wi*FF]*w3[f*16+j]; }

    float e = s0*wv[d] + c1*wv[DD+d] + c2*wv[2*DD+d] + c3*wv[3*DD+d] + bv[d];

    int   i2  = (d >> 1) * 2;
    float div = expf(-logf(10000.0f)/(float)DD * (float)i2);
    float ang = (float)w * div;
    float pe  = (d & 1) ? cosf(ang) : sinf(ang);

    g_h[(size_t)tok*DD + d] = e + pe;
}

/* ---------------- fused LN + QKV GEMM (A-resident) ----------------
   Block: 128 tokens x 1536 output cols (12 chunks of 128). 256 threads, 8 warps (4M x 2N).
   A (post-LN, half) resident in smem for the whole kernel; B double-buffered BK=32.
   48-tile continuous cp.async pipeline; per-chunk epilogue overlapped with next prefetch. */
#define QAHLD 136
#define QBHLD 136
#define QB_ST (32*QBHLD)       /* halves per B stage */
#define QCSLD 72
#define NCHUNK 12
#define QKV_SMEM (128*QAHLD*2 + 2*QB_ST*2 + 128*QCSLD*4)   /* 89088 B */

__global__ void __launch_bounds__(256)
qkvln_kernel(const float* __restrict__ h, const __half* __restrict__ Bw,
             __half* __restrict__ C,
             const float* __restrict__ gam, const float* __restrict__ bet)
{
    extern __shared__ char smp[];
    __half* Ah    = (__half*)smp;
    __half* Bh[2] = { (__half*)(smp + 128*QAHLD*2),
                      (__half*)(smp + 128*QAHLD*2) + QB_ST };
    float*  Cs    = (float*)(smp + 128*QAHLD*2 + 2*QB_ST*2);

    int m0 = blockIdx.y * 128;
    int nbase = blockIdx.x * (NCHUNK*128);
    int tid = threadIdx.x, w = tid >> 5;
    int wm = w & 3, wn = w >> 2;

    /* stage gamma/beta in Cs[0..255] */
    if (tid < 128) Cs[tid] = gam[tid];
    else           Cs[tid] = bet[tid-128];
    __syncthreads();

    /* LayerNorm: 2 threads per row (64 cols each), write half A to smem */
    {
        int r = tid >> 1, c0 = (tid & 1)*64;
        const float* hr = h + (size_t)(m0+r)*DD + c0;
        float s = 0.f, ss = 0.f;
        #pragma unroll
        for (int i=0;i<16;i++){
            float4 v = *(const float4*)&hr[i*4];
            s  += v.x+v.y+v.z+v.w;
            ss += v.x*v.x+v.y*v.y+v.z*v.z+v.w*v.w;
        }
        s  += __shfl_xor_sync(~0u, s, 1);
        ss += __shfl_xor_sync(~0u, ss, 1);
        float mean = s * (1.0f/DD);
        float rstd = rsqrtf(ss*(1.0f/DD) - mean*mean + 1e-5f);
        #pragma unroll
        for (int i=0;i<16;i++){
            float4 v = *(const float4*)&hr[i*4];
            int c = c0 + i*4;
            __half2 a = __float22half2_rn(make_float2(
                (v.x-mean)*rstd*Cs[c+0] + Cs[128+c+0],
                (v.y-mean)*rstd*Cs[c+1] + Cs[128+c+1]));
            __half2 b = __float22half2_rn(make_float2(
                (v.z-mean)*rstd*Cs[c+2] + Cs[128+c+2],
                (v.w-mean)*rstd*Cs[c+3] + Cs[128+c+3]));
            *(__half2*)&Ah[r*QAHLD + c]     = a;
            *(__half2*)&Ah[r*QAHLD + c + 2] = b;
        }
    }
    __syncthreads();

    auto issueB = [&](int st, int tt){
        int k0 = (tt & 3) << 5;
        int n0 = nbase + (tt >> 2)*128;
        #pragma unroll
        for (int i=0;i<2;i++){
            int idx = tid + i*256;                 /* 512 chunks of 8 halves */
            int r = idx >> 4, c8 = (idx & 15)*8;
            cp16(&Bh[st][r*QBHLD + c8], &Bw[(size_t)(k0+r)*QKVLD + n0 + c8]);
        }
        asm volatile("cp.async.commit_group;\n");
    };

    issueB(0, 0);
    for (int c = 0; c < NCHUNK; c++){
        wmma::fragment<wmma::accumulator,16,16,16,float> acc[2][4];
        #pragma unroll
        for (int i=0;i<2;i++)
            #pragma unroll
            for (int j=0;j<4;j++) wmma::fill_fragment(acc[i][j], 0.0f);

        for (int kt = 0; kt < 4; kt++){
            int tt = c*4 + kt;
            if (tt+1 < NCHUNK*4){
                issueB((tt+1)&1, tt+1);
                asm volatile("cp.async.wait_group 1;\n" ::: "memory");
            } else {
                asm volatile("cp.async.wait_group 0;\n" ::: "memory");
            }
            __syncthreads();
            int st = tt & 1;
            #pragma unroll
            for (int ks = 0; ks < 32; ks += 16){
                wmma::fragment<wmma::matrix_a,16,16,16,__half,wmma::row_major> af[2];
                #pragma unroll
                for (int i=0;i<2;i++)
                    wmma::load_matrix_sync(af[i], &Ah[(wm*32 + i*16)*QAHLD + kt*32 + ks], QAHLD);
                #pragma unroll
                for (int j=0;j<4;j++){
                    wmma::fragment<wmma::matrix_b,16,16,16,__half,wmma::row_major> bf;
                    wmma::load_matrix_sync(bf, &Bh[st][ks*QBHLD + wn*64 + j*16], QBHLD);
                    wmma::mma_sync(acc[0][j], af[0], bf, acc[0][j]);
                    wmma::mma_sync(acc[1][j], af[1], bf, acc[1][j]);
                }
            }
            __syncthreads();
        }

        /* epilogue in two 64-col passes through Cs (128 x QCSLD fp32) */
        int n0 = nbase + c*128;
        #pragma unroll
        for (int pass = 0; pass < 2; pass++){
            if (wn == pass){
                #pragma unroll
                for (int i=0;i<2;i++)
                    #pragma unroll
                    for (int j=0;j<4;j++)
                        wmma::store_matrix_sync(&Cs[(wm*32 + i*16)*QCSLD + j*16],
                                                acc[i][j], QCSLD, wmma::mem_row_major);
            }
            __syncthreads();
            #pragma unroll
            for (int i=0;i<4;i++){
                int idx = tid + i*256;             /* 1024 chunks of 8 over 128x64 */
                int r = idx >> 3, c8 = (idx & 7)*8;
                float4 v0 = *(float4*)&Cs[r*QCSLD + c8];
                float4 v1 = *(float4*)&Cs[r*QCSLD + c8 + 4];
                __half2 hh[4];
                hh[0] = __float22half2_rn(make_float2(v0.x, v0.y));
                hh[1] = __float22half2_rn(make_float2(v0.z, v0.w));
                hh[2] = __float22half2_rn(make_float2(v1.x, v1.y));
                hh[3] = __float22half2_rn(make_float2(v1.z, v1.w));
                *(uint4*)&C[(size_t)(m0+r)*QKVLD + n0 + pass*64 + c8] = *(uint4*)hh;
            }
            __syncthreads();
        }
    }
}

/* ---------------- out-proj GEMM: h = o @ Wout + bias + resid ----------------
   BM=64, BN=128, BK=32, 2-stage cp.async. 8 warps (2M x 4N), warp tile 32x32. */
#define OAHLD 40
#define OBHLD 136
#define OA_ST (64*OAHLD)
#define OB_ST (32*OBHLD)
#define OCSLD 136
#define WOUT_SMEM (2*OA_ST*2 + 2*OB_ST*2 + 64*OCSLD*4)     /* 62464 B */

__global__ void __launch_bounds__(256)
wgemm_out(const __half* __restrict__ A, const __half* __restrict__ B,
          float* __restrict__ C,
          const float* __restrict__ bias, const float* __restrict__ resid)
{
    extern __shared__ char smp[];
    __half* Ah[2] = { (__half*)smp, (__half*)smp + OA_ST };
    __half* Bh[2] = { (__half*)(smp + 2*OA_ST*2), (__half*)(smp + 2*OA_ST*2) + OB_ST };
    float*  Cs    = (float*)(smp + 2*OA_ST*2 + 2*OB_ST*2);

    int m0 = blockIdx.x * 64;
    int tid = threadIdx.x, w = tid >> 5;
    int wm = w & 1, wn = w >> 1;

    wmma::fragment<wmma::accumulator,16,16,16,float> acc[2][2];
    #pragma unroll
    for (int i=0;i<2;i++)
        #pragma unroll
        for (int j=0;j<2;j++) wmma::fill_fragment(acc[i][j], 0.0f);

    auto issue = [&](int st, int k0){
        {
            int r = tid >> 2, c8 = (tid & 3)*8;    /* 256 chunks: A 64x32 */
            cp16(&Ah[st][r*OAHLD + c8], &A[(size_t)(m0+r)*INNER + k0 + c8]);
        }
        #pragma unroll
        for (int i=0;i<2;i++){
            int idx = tid + i*256;                 /* 512 chunks: B 32x128 */
            int r = idx >> 4, c8 = (idx & 15)*8;
            cp16(&Bh[st][r*OBHLD + c8], &B[(size_t)(k0+r)*DD + c8]);
        }
        asm volatile("cp.async.commit_group;\n");
    };

    const int nt = INNER >> 5;                     /* 32 tiles */
    issue(0, 0);
    for (int t = 0; t < nt; t++){
        if (t+1 < nt){
            issue((t+1)&1, (t+1)<<5);
            asm volatile("cp.async.wait_group 1;\n" ::: "memory");
        } else {
            asm volatile("cp.async.wait_group 0;\n" ::: "memory");
        }
        __syncthreads();
        int st = t & 1;
        #pragma unroll
        for (int ks = 0; ks < 32; ks += 16){
            wmma::fragment<wmma::matrix_a,16,16,16,__half,wmma::row_major> af[2];
            wmma::fragment<wmma::matrix_b,16,16,16,__half,wmma::row_major> bf[2];
            #pragma unroll
            for (int i=0;i<2;i++)
                wmma::load_matrix_sync(af[i], &Ah[st][(wm*32 + i*16)*OAHLD + ks], OAHLD);
            #pragma unroll
            for (int j=0;j<2;j++)
                wmma::load_matrix_sync(bf[j], &Bh[st][ks*OBHLD + wn*32 + j*16], OBHLD);
            #pragma unroll
            for (int i=0;i<2;i++)
                #pragma unroll
                for (int j=0;j<2;j++)
                    wmma::mma_sync(acc[i][j], af[i], bf[j], acc[i][j]);
        }
        __syncthreads();
    }

    #pragma unroll
    for (int i=0;i<2;i++)
        #pragma unroll
        for (int j=0;j<2;j++)
            wmma::store_matrix_sync(&Cs[(wm*32 + i*16)*OCSLD + wn*32 + j*16],
                                    acc[i][j], OCSLD, wmma::mem_row_major);
    __syncthreads();

    #pragma unroll
    for (int i=0;i<8;i++){
        int idx = tid + i*256;                     /* 2048 chunks of 4: 64x128 */
        int r = idx >> 5, c4 = (idx & 31)*4;
        float4 v  = *(float4*)&Cs[r*OCSLD + c4];
        float4 bb = *(const float4*)&bias[c4];
        float4 rr = *(const float4*)&resid[(size_t)(m0+r)*DD + c4];
        v.x += bb.x + rr.x; v.y += bb.y + rr.y;
        v.z += bb.z + rr.z; v.w += bb.w + rr.w;
        *(float4*)&C[(size_t)(m0+r)*DD + c4] = v;
    }
}

/* ---------------- variable attention (F=16): fp16 WMMA, warp per (bw,head) ---------------- */
#define VPAD 24
__global__ void vattn_kernel(const __half* __restrict__ qkv, __half* __restrict__ o)
{
    __shared__ float  Pf [HH][16*VPAD];     /* scores fp32; reused as O staging */
    __shared__ __half Phh[HH][16*VPAD];     /* probs half */
    int bw = blockIdx.x;
    int w  = threadIdx.x >> 5, lane = threadIdx.x & 31;
    const __half* q = qkv + (size_t)bw*FF*QKVLD + w*DD;
    const __half* k = q + INNER;
    const __half* v = q + 2*INNER;
    __half* op = o + (size_t)bw*FF*INNER + w*DD;
    float*  Pw = &Pf[w][0];
    __half* Ph = &Phh[w][0];

    wmma::fragment<wmma::accumulator,16,16,16,float> sf;
    wmma::fill_fragment(sf, 0.0f);
    #pragma unroll
    for (int ks = 0; ks < DD; ks += 16){
        wmma::fragment<wmma::matrix_a,16,16,16,__half,wmma::row_major> af;
        wmma::fragment<wmma::matrix_b,16,16,16,__half,wmma::col_major> bf;
        wmma::load_matrix_sync(af, q + ks, QKVLD);
        wmma::load_matrix_sync(bf, k + ks, QKVLD);
        wmma::mma_sync(sf, af, bf, sf);
    }
    #pragma unroll
    for (int e = 0; e < sf.num_elements; e++) sf.x[e] *= SCALE;
    wmma::store_matrix_sync(Pw, sf, VPAD, wmma::mem_row_major);
    __syncwarp();

    if (lane < FF){
        float* row = Pw + lane*VPAD;
        __half* rh = Ph + lane*VPAD;
        float mx = -1e30f;
        #pragma unroll
        for (int j=0;j<FF;j++) mx = fmaxf(mx, row[j]);
        float tmp[FF]; float s = 0.f;
        #pragma unroll
        for (int j=0;j<FF;j++){ tmp[j] = fexp(row[j]-mx); s += tmp[j]; }
        float inv = 1.0f/s;
        #pragma unroll
        for (int j=0;j<FF;j++) rh[j] = __float2half(tmp[j]*inv);
    }
    __syncwarp();

    wmma::fragment<wmma::matrix_a,16,16,16,__half,wmma::row_major> pf;
    wmma::load_matrix_sync(pf, Ph, VPAD);
    __syncwarp();
    #pragma unroll
    for (int n0 = 0; n0 < DD; n0 += 16){
        wmma::fragment<wmma::accumulator,16,16,16,float> of;
        wmma::fill_fragment(of, 0.0f);
        wmma::fragment<wmma::matrix_b,16,16,16,__half,wmma::row_major> vf;
        wmma::load_matrix_sync(vf, v + n0, QKVLD);
        wmma::mma_sync(of, pf, vf, of);
        wmma::store_matrix_sync(Pw, of, VPAD, wmma::mem_row_major);
        __syncwarp();
        {
            int r = lane >> 1, c0 = (lane & 1)*8;
            const float* src = Pw + r*VPAD + c0;
            __half2 hh[4];
            #pragma unroll
            for (int u=0;u<4;u++)
                hh[u] = __float22half2_rn(make_float2(src[2*u], src[2*u+1]));
            *(uint4*)(op + (size_t)r*INNER + n0 + c0) = *(uint4*)hh;
        }
        __syncwarp();
    }
}

/* ---------------- fused temporal attention (fp16 WMMA, exact softmax) ---------------- */
#define TI   64
#define SLDF 264
#define PHLD 264
#define QHLD 136
#define KHLD 136
#define OLDF 136
#define OFF_SS 0
#define OFF_PH (OFF_SS + TI*SLDF*4)
#define OFF_QH (OFF_PH + TI*PHLD*2)
#define OFF_KH (OFF_QH + TI*QHLD*2)
#define OFF_LL (OFF_KH + WW*KHLD*2)
#define TATTN_SMEM (OFF_LL + TI*4)             /* 188672 */

__global__ void tattn_kernel(const __half* __restrict__ qkv, __half* __restrict__ o)
{
    extern __shared__ char smb[];
    float*  Ss = (float*) (smb + OFF_SS);
    __half* Ph = (__half*)(smb + OFF_PH);
    __half* Qh = (__half*)(smb + OFF_QH);
    __half* Kh = (__half*)(smb + OFF_KH);
    float*  Ll = (float*) (smb + OFF_LL);
    float*  Osf = Ss;

    int batch = blockIdx.y;
    int hd = batch & 7, f = (batch >> 3) & 15, b = batch >> 7;
    int i0 = blockIdx.x * TI;
    size_t baseQ = ((size_t)(b*WW)*FF + f)*QKVLD + hd*DD;
    size_t baseK = baseQ + INNER;
    size_t baseV = baseQ + 2*INNER;
    size_t baseO = ((size_t)(b*WW)*FF + f)*INNER + hd*DD;
    int tid = threadIdx.x, w = tid >> 5;
    int wm = w & 1, wn = w >> 1;

    #pragma unroll
    for (int i=0;i<4;i++){
        int idx = tid + i*256;
        int r = idx >> 4, c8 = (idx & 15)*8;
        cp16(&Qh[r*QHLD + c8], &qkv[baseQ + (size_t)(i0+r)*RS + c8]);
    }
    #pragma unroll
    for (int i=0;i<16;i++){
        int idx = tid + i*256;
        int r = idx >> 4, c8 = (idx & 15)*8;
        cp16(&Kh[r*KHLD + c8], &qkv[baseK + (size_t)r*RS + c8]);
    }
    asm volatile("cp.async.commit_group;\n");
    asm volatile("cp.async.wait_group 0;\n" ::: "memory");
    __syncthreads();

    {
        wmma::fragment<wmma::accumulator,16,16,16,float> sf[2][4];
        #pragma unroll
        for (int i=0;i<2;i++)
            #pragma unroll
            for (int j=0;j<4;j++) wmma::fill_fragment(sf[i][j], 0.0f);
        #pragma unroll
        for (int ks=0; ks<DD; ks+=16){
            wmma::fragment<wmma::matrix_a,16,16,16,__half,wmma::row_major> af[2];
            wmma::fragment<wmma::matrix_b,16,16,16,__half,wmma::col_major> bf[4];
            #pragma unroll
            for (int i=0;i<2;i++)
                wmma::load_matrix_sync(af[i], &Qh[(wm*32 + i*16)*QHLD + ks], QHLD);
            #pragma unroll
            for (int j=0;j<4;j++)
                wmma::load_matrix_sync(bf[j], &Kh[(wn*64 + j*16)*KHLD + ks], KHLD);
            #pragma unroll
            for (int i=0;i<2;i++)
                #pragma unroll
                for (int j=0;j<4;j++)
                    wmma::mma_sync(sf[i][j], af[i], bf[j], sf[i][j]);
        }
        #pragma unroll
        for (int i=0;i<2;i++)
            #pragma unroll
            for (int j=0;j<4;j++)
                wmma::store_matrix_sync(&Ss[(wm*32 + i*16)*SLDF + wn*64 + j*16],
                                        sf[i][j], SLDF, wmma::mem_row_major);
    }
    __syncthreads();

    #pragma unroll
    for (int i=0;i<16;i++){
        int idx = tid + i*256;
        int r = idx >> 4, c8 = (idx & 15)*8;
        cp16(&Kh[r*KHLD + c8], &qkv[baseV + (size_t)r*RS + c8]);
    }
    asm volatile("cp.async.commit_group;\n");

    {
        int r = tid >> 2, q4 = tid & 3;
        float* row = Ss + r*SLDF + q4*64;
        __half* ph = Ph + r*PHLD + q4*64;
        float mx = -1e30f;
        #pragma unroll 8
        for (int c=0;c<64;c++) mx = fmaxf(mx, row[c]);
        mx = fmaxf(mx, __shfl_xor_sync(0xFFFFFFFFu, mx, 1));
        mx = fmaxf(mx, __shfl_xor_sync(0xFFFFFFFFu, mx, 2));
        float s = 0.f;
        #pragma unroll 8
        for (int c=0;c<64;c++){
            float p = fexp((row[c]-mx)*SCALE);
            ph[c] = __float2half(p);
            s += p;
        }
        s += __shfl_xor_sync(0xFFFFFFFFu, s, 1);
        s += __shfl_xor_sync(0xFFFFFFFFu, s, 2);
        if (q4 == 0) Ll[r] = 1.0f/s;
    }
    asm volatile("cp.async.wait_group 0;\n" ::: "memory");
    __syncthreads();

    {
        wmma::fragment<wmma::accumulator,16,16,16,float> of[2][2];
        #pragma unroll
        for (int i=0;i<2;i++)
            #pragma unroll
            for (int j=0;j<2;j++) wmma::fill_fragment(of[i][j], 0.0f);
        #pragma unroll
        for (int ks=0; ks<WW; ks+=16){
            wmma::fragment<wmma::matrix_a,16,16,16,__half,wmma::row_major> pf[2];
            wmma::fragment<wmma::matrix_b,16,16,16,__half,wmma::row_major> vf[2];
            #pragma unroll
            for (int i=0;i<2;i++)
                wmma::load_matrix_sync(pf[i], &Ph[(wm*32 + i*16)*PHLD + ks], PHLD);
            #pragma unroll
            for (int j=0;j<2;j++)
                wmma::load_matrix_sync(vf[j], &Kh[ks*KHLD + wn*32 + j*16], KHLD);
            #pragma unroll
            for (int i=0;i<2;i++)
                #pragma unroll
                for (int j=0;j<2;j++)
                    wmma::mma_sync(of[i][j], pf[i], vf[j], of[i][j]);
        }
        __syncthreads();
        #pragma unroll
        for (int i=0;i<2;i++)
            #pragma unroll
            for (int j=0;j<2;j++)
                wmma::store_matrix_sync(&Osf[(wm*32 + i*16)*OLDF + wn*32 + j*16],
                                        of[i][j], OLDF, wmma::mem_row_major);
    }
    __syncthreads();

    #pragma unroll
    for (int i=0;i<8;i++){
        int idx = tid + i*256;
        int r = idx >> 5, c4 = (idx & 31)*4;
        float inv = Ll[r];
        float4 v = *(float4*)&Osf[r*OLDF + c4];
        __half2* gp = (__half2*)&o[baseO + (size_t)(i0 + r)*RO + c4];
        float2 f0 = __half22float2(gp[0]);
        float2 f1 = __half22float2(gp[1]);
        f0.x += v.x*inv; f0.y += v.y*inv;
        f1.x += v.z*inv; f1.y += v.w*inv;
        gp[0] = __float22half2_rn(f0);
        gp[1] = __float22half2_rn(f1);
    }
}

/* ---------------- head ---------------- */
__global__ void head_kernel(const float* __restrict__ wh, const float* __restrict__ bh,
                            float* __restrict__ out)
{
    int bw = blockIdx.x;
    int n = threadIdx.x >> 5, lane = threadIdx.x & 31;
    const float* hrow = g_h + (size_t)bw*(FF*DD);
    float acc = 0.f;
    #pragma unroll 4
    for (int k = lane; k < FF*DD; k += 32)
        acc += hrow[k]*wh[k*FF + n];
    #pragma unroll
    for (int o=16;o>0;o>>=1) acc += __shfl_xor_sync(~0u, acc, o);
    if (lane == 0) out[bw*FF + n] = acc + bh[n];
}

/* ---------------- launcher ---------------- */
extern "C" void kernel_launch(void* const* d_in, const int* in_sizes, int n_in,
                              void* d_out, int out_size)
{
    (void)in_sizes; (void)n_in; (void)out_size;
    const float* x   = (const float*)d_in[0];
    const float* w1  = (const float*)d_in[1];
    const float* b1  = (const float*)d_in[2];
    const float* w2  = (const float*)d_in[3];
    const float* b2  = (const float*)d_in[4];
    const float* w3  = (const float*)d_in[5];
    const float* b3  = (const float*)d_in[6];
    const float* wv  = (const float*)d_in[7];
    const float* bv  = (const float*)d_in[8];
    const float* lng = (const float*)d_in[9];
    const float* lnb = (const float*)d_in[10];
    const float* wq  = (const float*)d_in[11];
    const float* wo  = (const float*)d_in[12];
    const float* bo  = (const float*)d_in[13];
    const float* wh  = (const float*)d_in[14];
    const float* bh  = (const float*)d_in[15];
    float* out = (float*)d_out;

    float *p_h; __half *p_qkv, *p_o, *p_wqh, *p_woh;
    cudaGetSymbolAddress((void**)&p_h,   g_h);
    cudaGetSymbolAddress((void**)&p_qkv, g_qkv);
    cudaGetSymbolAddress((void**)&p_o,   g_o);
    cudaGetSymbolAddress((void**)&p_wqh, g_wqh);
    cudaGetSymbolAddress((void**)&p_woh, g_woh);

    cudaFuncSetAttribute(tattn_kernel,
        cudaFuncAttributeMaxDynamicSharedMemorySize, TATTN_SMEM);
    cudaFuncSetAttribute(qkvln_kernel,
        cudaFuncAttributeMaxDynamicSharedMemorySize, QKV_SMEM);
    cudaFuncSetAttribute(wgemm_out,
        cudaFuncAttributeMaxDynamicSharedMemorySize, WOUT_SMEM);

    cvtw_kernel<<<(NQW + 255)/256, 256>>>(wq, wo);
    embed_kernel<<<NT, DD>>>(x, w1, b1, w2, b2, w3, b3, wv, bv);

    for (int l = 0; l < NL; l++) {
        /* fused LN + qkv GEMM : [32768,128]@[128,3072] */
        qkvln_kernel<<<dim3(2, NT/128), 256, QKV_SMEM>>>(
            p_h, p_wqh + (size_t)l*DD*QKVLD, p_qkv, lng + l*DD, lnb + l*DD);

        /* variable attention writes g_o (half) */
        vattn_kernel<<<BB*WW, 256>>>(p_qkv, p_o);

        /* fused temporal attention accumulates into g_o (half RMW) */
        tattn_kernel<<<dim3(WW/TI, BB*FF*HH), 256, TATTN_SMEM>>>(p_qkv, p_o);

        /* h = o @ Wout[l] + b_out[l] + h : [32768,1024]@[1024,128], fp32 out */
        wgemm_out<<<NT/64, 256, WOUT_SMEM>>>(
            p_o, p_woh + (size_t)l*INNER*DD, p_h, bo + l*DD, p_h);
    }

    head_kernel<<<BB*WW, 512>>>(wh, bh, out);
}

// round 9
// speedup vs baseline: 5.7552x; 1.3624x over previous
#include <cuda_runtime.h>
#include <cuda_fp16.h>
#include <mma.h>
#include <math.h>
using namespace nvcuda;

#define BB 8
#define WW 256
#define FF 16
#define DD 128
#define HH 8
#define NL 4
#define INNER 1024
#define NT (BB*WW*FF)          /* 32768 tokens */
#define QKVLD 3072
#define SCALE 0.08838834764831845f   /* 128^-0.5 */
#define RS (FF*QKVLD)          /* 49152: row stride (per w) in qkv */
#define RO (FF*INNER)          /* 16384: row stride (per w) in o   */

/* ---------------- scratch (static __device__, no allocation) ---------------- */
__device__ float  g_h  [NT*DD];                     /* 16 MB  running hidden state */
__device__ __half g_qkv[(size_t)NT*QKVLD];          /* 201 MB qkv activations      */
__device__ __half g_o  [(size_t)NT*INNER];          /*  67 MB attention output     */
__device__ __half g_wqh[NL*DD*QKVLD];               /*  3 MB  half qkv weights     */
__device__ __half g_woh[NL*INNER*DD];               /*  1 MB  half out weights     */

/* ---------------- fast exp on the FMA pipe ---------------- */
__device__ __forceinline__ float fexp(float x)
{
    x = fmaxf(x, -80.0f);
    float z  = x * 1.4426950408889634f;
    float zj = z + 12582912.0f;
    int   k  = __float_as_int(zj) - 0x4B400000;
    float f  = z - (zj - 12582912.0f);
    float p  = 1.3333558146e-3f;
    p = p*f + 9.6181291076e-3f;
    p = p*f + 5.5504108665e-2f;
    p = p*f + 2.4022650696e-1f;
    p = p*f + 6.9314718056e-1f;
    p = p*f + 1.0f;
    return __int_as_float(__float_as_int(p) + (k << 23));
}

__device__ __forceinline__ void cp16(void* smem_dst, const void* gmem_src)
{
    unsigned d = (unsigned)__cvta_generic_to_shared(smem_dst);
    asm volatile("cp.async.cg.shared.global [%0], [%1], 16;\n" :: "r"(d), "l"(gmem_src));
}

/* ---------------- weight conversion fp32 -> fp16 (once per launch) ---------------- */
#define NQW (NL*DD*QKVLD)      /* 1572864 */
#define NOW (NL*INNER*DD)      /*  524288 */
__global__ void cvtw_kernel(const float* __restrict__ wq, const float* __restrict__ wo)
{
    int i = blockIdx.x*256 + threadIdx.x;
    if (i < NQW) g_wqh[i] = __float2half(wq[i]);
    if (i < NOW) g_woh[i] = __float2half(wo[i]);
}

/* ---------------- embed: convs + value proj + positional encoding ---------------- */
__global__ void embed_kernel(const float* __restrict__ x,
    const float* __restrict__ w1, const float* __restrict__ b1,
    const float* __restrict__ w2, const float* __restrict__ b2,
    const float* __restrict__ w3, const float* __restrict__ b3,
    const float* __restrict__ wv, const float* __restrict__ bv)
{
    int tok = blockIdx.x;
    int d   = threadIdx.x;
    int f   = tok % FF;
    int bw  = tok / FF;
    int w   = bw % WW;
    const float* xp = x + (size_t)(bw - w)*FF + f;

    float s0 = xp[(size_t)w*FF];
    float c1 = b1[f];
    #pragma unroll
    for (int j = 0; j < 4; j++) { int wi = w - (3-j);    if (wi >= 0) c1 += xp[(size_t)wi*FF]*w1[f*4+j]; }
    float c2 = b2[f];
    #pragma unroll
    for (int j = 0; j < 8; j++) { int wi = w - (7-j)*2;  if (wi >= 0) c2 += xp[(size_t)wi*FF]*w2[f*8+j]; }
    float c3 = b3[f];
    #pragma unroll
    for (int j = 0; j < 16; j++){ int wi = w - (15-j)*3; if (wi >= 0) c3 += xp[(size_t)wi*FF]*w3[f*16+j]; }

    float e = s0*wv[d] + c1*wv[DD+d] + c2*wv[2*DD+d] + c3*wv[3*DD+d] + bv[d];

    int   i2  = (d >> 1) * 2;
    float div = expf(-logf(10000.0f)/(float)DD * (float)i2);
    float ang = (float)w * div;
    float pe  = (d & 1) ? cosf(ang) : sinf(ang);

    g_h[(size_t)tok*DD + d] = e + pe;
}

/* ---------------- fused LN + QKV GEMM (A-resident) ---------------- */
#define QAHLD 136
#define QBHLD 136
#define QB_ST (32*QBHLD)
#define QCSLD 72
#define NCHUNK 12
#define QKV_SMEM (128*QAHLD*2 + 2*QB_ST*2 + 128*QCSLD*4)   /* 89088 B */

__global__ void __launch_bounds__(256)
qkvln_kernel(const float* __restrict__ h, const __half* __restrict__ Bw,
             __half* __restrict__ C,
             const float* __restrict__ gam, const float* __restrict__ bet)
{
    extern __shared__ char smp[];
    __half* Ah    = (__half*)smp;
    __half* Bh[2] = { (__half*)(smp + 128*QAHLD*2),
                      (__half*)(smp + 128*QAHLD*2) + QB_ST };
    float*  Cs    = (float*)(smp + 128*QAHLD*2 + 2*QB_ST*2);

    int m0 = blockIdx.y * 128;
    int nbase = blockIdx.x * (NCHUNK*128);
    int tid = threadIdx.x, w = tid >> 5;
    int wm = w & 3, wn = w >> 2;

    if (tid < 128) Cs[tid] = gam[tid];
    else           Cs[tid] = bet[tid-128];
    __syncthreads();

    {
        int r = tid >> 1, c0 = (tid & 1)*64;
        const float* hr = h + (size_t)(m0+r)*DD + c0;
        float s = 0.f, ss = 0.f;
        #pragma unroll
        for (int i=0;i<16;i++){
            float4 v = *(const float4*)&hr[i*4];
            s  += v.x+v.y+v.z+v.w;
            ss += v.x*v.x+v.y*v.y+v.z*v.z+v.w*v.w;
        }
        s  += __shfl_xor_sync(~0u, s, 1);
        ss += __shfl_xor_sync(~0u, ss, 1);
        float mean = s * (1.0f/DD);
        float rstd = rsqrtf(ss*(1.0f/DD) - mean*mean + 1e-5f);
        #pragma unroll
        for (int i=0;i<16;i++){
            float4 v = *(const float4*)&hr[i*4];
            int c = c0 + i*4;
            __half2 a = __float22half2_rn(make_float2(
                (v.x-mean)*rstd*Cs[c+0] + Cs[128+c+0],
                (v.y-mean)*rstd*Cs[c+1] + Cs[128+c+1]));
            __half2 b = __float22half2_rn(make_float2(
                (v.z-mean)*rstd*Cs[c+2] + Cs[128+c+2],
                (v.w-mean)*rstd*Cs[c+3] + Cs[128+c+3]));
            *(__half2*)&Ah[r*QAHLD + c]     = a;
            *(__half2*)&Ah[r*QAHLD + c + 2] = b;
        }
    }
    __syncthreads();

    auto issueB = [&](int st, int tt){
        int k0 = (tt & 3) << 5;
        int n0 = nbase + (tt >> 2)*128;
        #pragma unroll
        for (int i=0;i<2;i++){
            int idx = tid + i*256;
            int r = idx >> 4, c8 = (idx & 15)*8;
            cp16(&Bh[st][r*QBHLD + c8], &Bw[(size_t)(k0+r)*QKVLD + n0 + c8]);
        }
        asm volatile("cp.async.commit_group;\n");
    };

    issueB(0, 0);
    for (int c = 0; c < NCHUNK; c++){
        wmma::fragment<wmma::accumulator,16,16,16,float> acc[2][4];
        #pragma unroll
        for (int i=0;i<2;i++)
            #pragma unroll
            for (int j=0;j<4;j++) wmma::fill_fragment(acc[i][j], 0.0f);

        for (int kt = 0; kt < 4; kt++){
            int tt = c*4 + kt;
            if (tt+1 < NCHUNK*4){
                issueB((tt+1)&1, tt+1);
                asm volatile("cp.async.wait_group 1;\n" ::: "memory");
            } else {
                asm volatile("cp.async.wait_group 0;\n" ::: "memory");
            }
            __syncthreads();
            int st = tt & 1;
            #pragma unroll
            for (int ks = 0; ks < 32; ks += 16){
                wmma::fragment<wmma::matrix_a,16,16,16,__half,wmma::row_major> af[2];
                #pragma unroll
                for (int i=0;i<2;i++)
                    wmma::load_matrix_sync(af[i], &Ah[(wm*32 + i*16)*QAHLD + kt*32 + ks], QAHLD);
                #pragma unroll
                for (int j=0;j<4;j++){
                    wmma::fragment<wmma::matrix_b,16,16,16,__half,wmma::row_major> bf;
                    wmma::load_matrix_sync(bf, &Bh[st][ks*QBHLD + wn*64 + j*16], QBHLD);
                    wmma::mma_sync(acc[0][j], af[0], bf, acc[0][j]);
                    wmma::mma_sync(acc[1][j], af[1], bf, acc[1][j]);
                }
            }
            __syncthreads();
        }

        int n0 = nbase + c*128;
        #pragma unroll
        for (int pass = 0; pass < 2; pass++){
            if (wn == pass){
                #pragma unroll
                for (int i=0;i<2;i++)
                    #pragma unroll
                    for (int j=0;j<4;j++)
                        wmma::store_matrix_sync(&Cs[(wm*32 + i*16)*QCSLD + j*16],
                                                acc[i][j], QCSLD, wmma::mem_row_major);
            }
            __syncthreads();
            #pragma unroll
            for (int i=0;i<4;i++){
                int idx = tid + i*256;
                int r = idx >> 3, c8 = (idx & 7)*8;
                float4 v0 = *(float4*)&Cs[r*QCSLD + c8];
                float4 v1 = *(float4*)&Cs[r*QCSLD + c8 + 4];
                __half2 hh[4];
                hh[0] = __float22half2_rn(make_float2(v0.x, v0.y));
                hh[1] = __float22half2_rn(make_float2(v0.z, v0.w));
                hh[2] = __float22half2_rn(make_float2(v1.x, v1.y));
                hh[3] = __float22half2_rn(make_float2(v1.z, v1.w));
                *(uint4*)&C[(size_t)(m0+r)*QKVLD + n0 + pass*64 + c8] = *(uint4*)hh;
            }
            __syncthreads();
        }
    }
}

/* ---------------- out-proj GEMM: h = o @ Wout + bias + resid ---------------- */
#define OAHLD 40
#define OBHLD 136
#define OA_ST (64*OAHLD)
#define OB_ST (32*OBHLD)
#define OCSLD 136
#define WOUT_SMEM (2*OA_ST*2 + 2*OB_ST*2 + 64*OCSLD*4)     /* 62464 B */

__global__ void __launch_bounds__(256)
wgemm_out(const __half* __restrict__ A, const __half* __restrict__ B,
          float* __restrict__ C,
          const float* __restrict__ bias, const float* __restrict__ resid)
{
    extern __shared__ char smp[];
    __half* Ah[2] = { (__half*)smp, (__half*)smp + OA_ST };
    __half* Bh[2] = { (__half*)(smp + 2*OA_ST*2), (__half*)(smp + 2*OA_ST*2) + OB_ST };
    float*  Cs    = (float*)(smp + 2*OA_ST*2 + 2*OB_ST*2);

    int m0 = blockIdx.x * 64;
    int tid = threadIdx.x, w = tid >> 5;
    int wm = w & 1, wn = w >> 1;

    wmma::fragment<wmma::accumulator,16,16,16,float> acc[2][2];
    #pragma unroll
    for (int i=0;i<2;i++)
        #pragma unroll
        for (int j=0;j<2;j++) wmma::fill_fragment(acc[i][j], 0.0f);

    auto issue = [&](int st, int k0){
        {
            int r = tid >> 2, c8 = (tid & 3)*8;
            cp16(&Ah[st][r*OAHLD + c8], &A[(size_t)(m0+r)*INNER + k0 + c8]);
        }
        #pragma unroll
        for (int i=0;i<2;i++){
            int idx = tid + i*256;
            int r = idx >> 4, c8 = (idx & 15)*8;
            cp16(&Bh[st][r*OBHLD + c8], &B[(size_t)(k0+r)*DD + c8]);
        }
        asm volatile("cp.async.commit_group;\n");
    };

    const int nt = INNER >> 5;
    issue(0, 0);
    for (int t = 0; t < nt; t++){
        if (t+1 < nt){
            issue((t+1)&1, (t+1)<<5);
            asm volatile("cp.async.wait_group 1;\n" ::: "memory");
        } else {
            asm volatile("cp.async.wait_group 0;\n" ::: "memory");
        }
        __syncthreads();
        int st = t & 1;
        #pragma unroll
        for (int ks = 0; ks < 32; ks += 16){
            wmma::fragment<wmma::matrix_a,16,16,16,__half,wmma::row_major> af[2];
            wmma::fragment<wmma::matrix_b,16,16,16,__half,wmma::row_major> bf[2];
            #pragma unroll
            for (int i=0;i<2;i++)
                wmma::load_matrix_sync(af[i], &Ah[st][(wm*32 + i*16)*OAHLD + ks], OAHLD);
            #pragma unroll
            for (int j=0;j<2;j++)
                wmma::load_matrix_sync(bf[j], &Bh[st][ks*OBHLD + wn*32 + j*16], OBHLD);
            #pragma unroll
            for (int i=0;i<2;i++)
                #pragma unroll
                for (int j=0;j<2;j++)
                    wmma::mma_sync(acc[i][j], af[i], bf[j], acc[i][j]);
        }
        __syncthreads();
    }

    #pragma unroll
    for (int i=0;i<2;i++)
        #pragma unroll
        for (int j=0;j<2;j++)
            wmma::store_matrix_sync(&Cs[(wm*32 + i*16)*OCSLD + wn*32 + j*16],
                                    acc[i][j], OCSLD, wmma::mem_row_major);
    __syncthreads();

    #pragma unroll
    for (int i=0;i<8;i++){
        int idx = tid + i*256;
        int r = idx >> 5, c4 = (idx & 31)*4;
        float4 v  = *(float4*)&Cs[r*OCSLD + c4];
        float4 bb = *(const float4*)&bias[c4];
        float4 rr = *(const float4*)&resid[(size_t)(m0+r)*DD + c4];
        v.x += bb.x + rr.x; v.y += bb.y + rr.y;
        v.z += bb.z + rr.z; v.w += bb.w + rr.w;
        *(float4*)&C[(size_t)(m0+r)*DD + c4] = v;
    }
}

/* ---------------- variable attention (F=16): fp16 WMMA, warp per (bw,head) ---------------- */
#define VPAD 24
__global__ void vattn_kernel(const __half* __restrict__ qkv, __half* __restrict__ o)
{
    __shared__ float  Pf [HH][16*VPAD];
    __shared__ __half Phh[HH][16*VPAD];
    int bw = blockIdx.x;
    int w  = threadIdx.x >> 5, lane = threadIdx.x & 31;
    const __half* q = qkv + (size_t)bw*FF*QKVLD + w*DD;
    const __half* k = q + INNER;
    const __half* v = q + 2*INNER;
    __half* op = o + (size_t)bw*FF*INNER + w*DD;
    float*  Pw = &Pf[w][0];
    __half* Ph = &Phh[w][0];

    wmma::fragment<wmma::accumulator,16,16,16,float> sf;
    wmma::fill_fragment(sf, 0.0f);
    #pragma unroll
    for (int ks = 0; ks < DD; ks += 16){
        wmma::fragment<wmma::matrix_a,16,16,16,__half,wmma::row_major> af;
        wmma::fragment<wmma::matrix_b,16,16,16,__half,wmma::col_major> bf;
        wmma::load_matrix_sync(af, q + ks, QKVLD);
        wmma::load_matrix_sync(bf, k + ks, QKVLD);
        wmma::mma_sync(sf, af, bf, sf);
    }
    #pragma unroll
    for (int e = 0; e < sf.num_elements; e++) sf.x[e] *= SCALE;
    wmma::store_matrix_sync(Pw, sf, VPAD, wmma::mem_row_major);
    __syncwarp();

    if (lane < FF){
        float* row = Pw + lane*VPAD;
        __half* rh = Ph + lane*VPAD;
        float mx = -1e30f;
        #pragma unroll
        for (int j=0;j<FF;j++) mx = fmaxf(mx, row[j]);
        float tmp[FF]; float s = 0.f;
        #pragma unroll
        for (int j=0;j<FF;j++){ tmp[j] = fexp(row[j]-mx); s += tmp[j]; }
        float inv = 1.0f/s;
        #pragma unroll
        for (int j=0;j<FF;j++) rh[j] = __float2half(tmp[j]*inv);
    }
    __syncwarp();

    wmma::fragment<wmma::matrix_a,16,16,16,__half,wmma::row_major> pf;
    wmma::load_matrix_sync(pf, Ph, VPAD);
    __syncwarp();
    #pragma unroll
    for (int n0 = 0; n0 < DD; n0 += 16){
        wmma::fragment<wmma::accumulator,16,16,16,float> of;
        wmma::fill_fragment(of, 0.0f);
        wmma::fragment<wmma::matrix_b,16,16,16,__half,wmma::row_major> vf;
        wmma::load_matrix_sync(vf, v + n0, QKVLD);
        wmma::mma_sync(of, pf, vf, of);
        wmma::store_matrix_sync(Pw, of, VPAD, wmma::mem_row_major);
        __syncwarp();
        {
            int r = lane >> 1, c0 = (lane & 1)*8;
            const float* src = Pw + r*VPAD + c0;
            __half2 hh[4];
            #pragma unroll
            for (int u=0;u<4;u++)
                hh[u] = __float22half2_rn(make_float2(src[2*u], src[2*u+1]));
            *(uint4*)(op + (size_t)r*INNER + n0 + c0) = *(uint4*)hh;
        }
        __syncwarp();
    }
}

/* ---------------- fused temporal attention v2: register softmax, 2 blocks/SM ----------------
   block = (b,f,h) x 64-row i-tile. 256 threads = 8 warps (2M x 4N).
   Q fragments straight from gmem (ldm=RS). K resident in smem (V overwrites after phase 1).
   Softmax on accumulator fragments in registers; unnormalized probs -> Ph (half);
   1/rowsum kept in registers; epilogue RMWs gmem directly from O fragments.
   acc fragment layout (m16n16, fp32): row=(lane>>2)+8*((e>>1)&1), col=(lane&3)*2+(e&1)+8*(e>>2). */
#define TI    64
#define KHLD  136
#define PHLD  264
#define OFF_PH (256*KHLD*2)                    /* 69632  */
#define OFF_RR (OFF_PH + TI*PHLD*2)            /* 103424 */
#define TATTN_SMEM (OFF_RR + TI*4*4)           /* 104448 */

__global__ void __launch_bounds__(256, 2)
tattn_kernel(const __half* __restrict__ qkv, __half* __restrict__ o)
{
    extern __shared__ char smb[];
    __half* Kh = (__half*)smb;                 /* K, then V */
    __half* Ph = (__half*)(smb + OFF_PH);
    float*  RR = (float*) (smb + OFF_RR);      /* 64 rows x 4 wn partials */

    int batch = blockIdx.y;
    int hd = batch & 7, f = (batch >> 3) & 15, b = batch >> 7;
    int i0 = blockIdx.x * TI;
    size_t baseQ = ((size_t)(b*WW)*FF + f)*QKVLD + hd*DD;
    size_t baseK = baseQ + INNER;
    size_t baseV = baseQ + 2*INNER;
    size_t baseO = ((size_t)(b*WW)*FF + f)*INNER + hd*DD;
    int tid = threadIdx.x, w = tid >> 5, lane = tid & 31;
    int wm = w & 1, wn = w >> 1;
    int lg = lane >> 2, lq = lane & 3;

    /* async load full K (256 x 128) */
    #pragma unroll
    for (int i=0;i<16;i++){
        int idx = tid + i*256;
        int r = idx >> 4, c8 = (idx & 15)*8;
        cp16(&Kh[r*KHLD + c8], &qkv[baseK + (size_t)r*RS + c8]);
    }
    asm volatile("cp.async.commit_group;\n");
    asm volatile("cp.async.wait_group 0;\n" ::: "memory");
    __syncthreads();

    /* phase 1: S = Q @ K^T (64 x 256). Q fragments from gmem. */
    const __half* qp = qkv + baseQ + (size_t)i0*RS;
    wmma::fragment<wmma::accumulator,16,16,16,float> sf[2][4];
    #pragma unroll
    for (int i=0;i<2;i++)
        #pragma unroll
        for (int j=0;j<4;j++) wmma::fill_fragment(sf[i][j], 0.0f);
    #pragma unroll
    for (int ks=0; ks<DD; ks+=16){
        wmma::fragment<wmma::matrix_a,16,16,16,__half,wmma::row_major> af[2];
        wmma::fragment<wmma::matrix_b,16,16,16,__half,wmma::col_major> bf[4];
        #pragma unroll
        for (int i=0;i<2;i++)
            wmma::load_matrix_sync(af[i], qp + (size_t)(wm*32 + i*16)*RS + ks, RS);
        #pragma unroll
        for (int j=0;j<4;j++)
            wmma::load_matrix_sync(bf[j], &Kh[(wn*64 + j*16)*KHLD + ks], KHLD);
        #pragma unroll
        for (int i=0;i<2;i++)
            #pragma unroll
            for (int j=0;j<4;j++)
                wmma::mma_sync(sf[i][j], af[i], bf[j], sf[i][j]);
    }
    __syncthreads();                       /* all warps done reading K */

    /* issue V load into Kh (overlaps register softmax) */
    #pragma unroll
    for (int i=0;i<16;i++){
        int idx = tid + i*256;
        int r = idx >> 4, c8 = (idx & 15)*8;
        cp16(&Kh[r*KHLD + c8], &qkv[baseV + (size_t)r*RS + c8]);
    }
    asm volatile("cp.async.commit_group;\n");

    /* ---- register softmax over fragment rows ---- */
    /* lane owns 4 rows: wm*32 + if*16 + hh*8 + lg, for (if,hh) in {0,1}^2 */
    float pm[4];
    #pragma unroll
    for (int i=0;i<2;i++)
        #pragma unroll
        for (int hh=0;hh<2;hh++){
            float m = -1e30f;
            #pragma unroll
            for (int j=0;j<4;j++){
                float* x = sf[i][j].x;
                int e0 = hh*2;
                m = fmaxf(m, fmaxf(fmaxf(x[e0], x[e0+1]), fmaxf(x[e0+4], x[e0+5])));
            }
            pm[i*2+hh] = m;
        }
    #pragma unroll
    for (int u=0;u<4;u++){
        pm[u] = fmaxf(pm[u], __shfl_xor_sync(~0u, pm[u], 1));
        pm[u] = fmaxf(pm[u], __shfl_xor_sync(~0u, pm[u], 2));
    }
    if (lq == 0){
        #pragma unroll
        for (int i=0;i<2;i++)
            #pragma unroll
            for (int hh=0;hh<2;hh++)
                RR[(wm*32 + i*16 + hh*8 + lg)*4 + wn] = pm[i*2+hh];
    }
    __syncthreads();
    float gmax[4];
    #pragma unroll
    for (int i=0;i<2;i++)
        #pragma unroll
        for (int hh=0;hh<2;hh++){
            const float* rr = &RR[(wm*32 + i*16 + hh*8 + lg)*4];
            gmax[i*2+hh] = fmaxf(fmaxf(rr[0], rr[1]), fmaxf(rr[2], rr[3]));
        }
    __syncthreads();                       /* RR consumed; reuse for sums */

    float ps[4] = {0.f, 0.f, 0.f, 0.f};
    #pragma unroll
    for (int i=0;i<2;i++)
        #pragma unroll
        for (int j=0;j<4;j++){
            float* x = sf[i][j].x;
            #pragma unroll
            for (int e=0;e<8;e++){
                int hh = (e>>1)&1;
                float p = fexp((x[e] - gmax[i*2+hh])*SCALE);
                x[e] = p;
                ps[i*2+hh] += p;
            }
        }
    #pragma unroll
    for (int u=0;u<4;u++){
        ps[u] += __shfl_xor_sync(~0u, ps[u], 1);
        ps[u] += __shfl_xor_sync(~0u, ps[u], 2);
    }
    if (lq == 0){
        #pragma unroll
        for (int i=0;i<2;i++)
            #pragma unroll
            for (int hh=0;hh<2;hh++)
                RR[(wm*32 + i*16 + hh*8 + lg)*4 + wn] = ps[i*2+hh];
    }
    __syncthreads();
    float rinv[4];
    #pragma unroll
    for (int i=0;i<2;i++)
        #pragma unroll
        for (int hh=0;hh<2;hh++){
            const float* rr = &RR[(wm*32 + i*16 + hh*8 + lg)*4];
            rinv[i*2+hh] = 1.0f/(rr[0]+rr[1]+rr[2]+rr[3]);
        }

    /* write unnormalized probs (half) to Ph */
    #pragma unroll
    for (int i=0;i<2;i++)
        #pragma unroll
        for (int j=0;j<4;j++){
            float* x = sf[i][j].x;
            #pragma unroll
            for (int e=0;e<8;e+=2){
                int hh = (e>>1)&1;
                int row = wm*32 + i*16 + hh*8 + lg;
                int col = wn*64 + j*16 + lq*2 + 8*(e>>2);
                *(__half2*)&Ph[row*PHLD + col] =
                    __float22half2_rn(make_float2(x[e], x[e+1]));
            }
        }
    asm volatile("cp.async.wait_group 0;\n" ::: "memory");
    __syncthreads();

    /* phase 2: O = P @ V (64 x 128, K=256). warp tile 32x32. */
    wmma::fragment<wmma::accumulator,16,16,16,float> of[2][2];
    #pragma unroll
    for (int i=0;i<2;i++)
        #pragma unroll
        for (int j=0;j<2;j++) wmma::fill_fragment(of[i][j], 0.0f);
    #pragma unroll
    for (int ks=0; ks<WW; ks+=16){
        wmma::fragment<wmma::matrix_a,16,16,16,__half,wmma::row_major> pf[2];
        wmma::fragment<wmma::matrix_b,16,16,16,__half,wmma::row_major> vf[2];
        #pragma unroll
        for (int i=0;i<2;i++)
            wmma::load_matrix_sync(pf[i], &Ph[(wm*32 + i*16)*PHLD + ks], PHLD);
        #pragma unroll
        for (int j=0;j<2;j++)
            wmma::load_matrix_sync(vf[j], &Kh[ks*KHLD + wn*32 + j*16], KHLD);
        #pragma unroll
        for (int i=0;i<2;i++)
            #pragma unroll
            for (int j=0;j<2;j++)
                wmma::mma_sync(of[i][j], pf[i], vf[j], of[i][j]);
    }

    /* epilogue: o(half) += of * rinv, straight from fragments */
    #pragma unroll
    for (int i=0;i<2;i++)
        #pragma unroll
        for (int j=0;j<2;j++){
            float* x = of[i][j].x;
            #pragma unroll
            for (int e=0;e<8;e+=2){
                int hh = (e>>1)&1;
                int row = wm*32 + i*16 + hh*8 + lg;
                int col = wn*32 + j*16 + lq*2 + 8*(e>>2);
                float inv = rinv[i*2+hh];
                __half2* gp = (__half2*)&o[baseO + (size_t)(i0+row)*RO + col];
                float2 f0 = __half22float2(*gp);
                f0.x += x[e]*inv;
                f0.y += x[e+1]*inv;
                *gp = __float22half2_rn(f0);
            }
        }
}

/* ---------------- head ---------------- */
__global__ void head_kernel(const float* __restrict__ wh, const float* __restrict__ bh,
                            float* __restrict__ out)
{
    int bw = blockIdx.x;
    int n = threadIdx.x >> 5, lane = threadIdx.x & 31;
    const float* hrow = g_h + (size_t)bw*(FF*DD);
    float acc = 0.f;
    #pragma unroll 4
    for (int k = lane; k < FF*DD; k += 32)
        acc += hrow[k]*wh[k*FF + n];
    #pragma unroll
    for (int o=16;o>0;o>>=1) acc += __shfl_xor_sync(~0u, acc, o);
    if (lane == 0) out[bw*FF + n] = acc + bh[n];
}

/* ---------------- launcher ---------------- */
extern "C" void kernel_launch(void* const* d_in, const int* in_sizes, int n_in,
                              void* d_out, int out_size)
{
    (void)in_sizes; (void)n_in; (void)out_size;
    const float* x   = (const float*)d_in[0];
    const float* w1  = (const float*)d_in[1];
    const float* b1  = (const float*)d_in[2];
    const float* w2  = (const float*)d_in[3];
    const float* b2  = (const float*)d_in[4];
    const float* w3  = (const float*)d_in[5];
    const float* b3  = (const float*)d_in[6];
    const float* wv  = (const float*)d_in[7];
    const float* bv  = (const float*)d_in[8];
    const float* lng = (const float*)d_in[9];
    const float* lnb = (const float*)d_in[10];
    const float* wq  = (const float*)d_in[11];
    const float* wo  = (const float*)d_in[12];
    const float* bo  = (const float*)d_in[13];
    const float* wh  = (const float*)d_in[14];
    const float* bh  = (const float*)d_in[15];
    float* out = (float*)d_out;

    float *p_h; __half *p_qkv, *p_o, *p_wqh, *p_woh;
    cudaGetSymbolAddress((void**)&p_h,   g_h);
    cudaGetSymbolAddress((void**)&p_qkv, g_qkv);
    cudaGetSymbolAddress((void**)&p_o,   g_o);
    cudaGetSymbolAddress((void**)&p_wqh, g_wqh);
    cudaGetSymbolAddress((void**)&p_woh, g_woh);

    cudaFuncSetAttribute(tattn_kernel,
        cudaFuncAttributeMaxDynamicSharedMemorySize, TATTN_SMEM);
    cudaFuncSetAttribute(qkvln_kernel,
        cudaFuncAttributeMaxDynamicSharedMemorySize, QKV_SMEM);
    cudaFuncSetAttribute(wgemm_out,
        cudaFuncAttributeMaxDynamicSharedMemorySize, WOUT_SMEM);

    cvtw_kernel<<<(NQW + 255)/256, 256>>>(wq, wo);
    embed_kernel<<<NT, DD>>>(x, w1, b1, w2, b2, w3, b3, wv, bv);

    for (int l = 0; l < NL; l++) {
        /* fused LN + qkv GEMM : [32768,128]@[128,3072] */
        qkvln_kernel<<<dim3(2, NT/128), 256, QKV_SMEM>>>(
            p_h, p_wqh + (size_t)l*DD*QKVLD, p_qkv, lng + l*DD, lnb + l*DD);

        /* variable attention writes g_o (half) */
        vattn_kernel<<<BB*WW, 256>>>(p_qkv, p_o);

        /* fused temporal attention accumulates into g_o (half RMW) */
        tattn_kernel<<<dim3(WW/TI, BB*FF*HH), 256, TATTN_SMEM>>>(p_qkv, p_o);

        /* h = o @ Wout[l] + b_out[l] + h : [32768,1024]@[1024,128], fp32 out */
        wgemm_out<<<NT/64, 256, WOUT_SMEM>>>(
            p_o, p_woh + (size_t)l*INNER*DD, p_h, bo + l*DD, p_h);
    }

    head_kernel<<<BB*WW, 512>>>(wh, bh, out);
}

// round 10
// speedup vs baseline: 6.1237x; 1.0640x over previous
#include <cuda_runtime.h>
#include <cuda_fp16.h>
#include <mma.h>
#include <math.h>
using namespace nvcuda;

#define BB 8
#define WW 256
#define FF 16
#define DD 128
#define HH 8
#define NL 4
#define INNER 1024
#define NT (BB*WW*FF)          /* 32768 tokens */
#define QKVLD 3072
#define SCALE 0.08838834764831845f   /* 128^-0.5 */
#define RS (FF*QKVLD)          /* 49152: row stride (per w) in qkv */
#define RO (FF*INNER)          /* 16384: row stride (per w) in o   */

/* ---------------- scratch (static __device__, no allocation) ---------------- */
__device__ float  g_h  [NT*DD];                     /* 16 MB  running hidden state */
__device__ __half g_qkv[(size_t)NT*QKVLD];          /* 201 MB qkv activations      */
__device__ __half g_o  [(size_t)NT*INNER];          /*  67 MB attention output     */
__device__ __half g_wqh[NL*DD*QKVLD];               /*  3 MB  half qkv weights     */
__device__ __half g_woh[NL*INNER*DD];               /*  1 MB  half out weights     */

/* ---------------- fast exp on the FMA pipe ---------------- */
__device__ __forceinline__ float fexp(float x)
{
    x = fmaxf(x, -80.0f);
    float z  = x * 1.4426950408889634f;
    float zj = z + 12582912.0f;
    int   k  = __float_as_int(zj) - 0x4B400000;
    float f  = z - (zj - 12582912.0f);
    float p  = 1.3333558146e-3f;
    p = p*f + 9.6181291076e-3f;
    p = p*f + 5.5504108665e-2f;
    p = p*f + 2.4022650696e-1f;
    p = p*f + 6.9314718056e-1f;
    p = p*f + 1.0f;
    return __int_as_float(__float_as_int(p) + (k << 23));
}

__device__ __forceinline__ void cp16(void* smem_dst, const void* gmem_src)
{
    unsigned d = (unsigned)__cvta_generic_to_shared(smem_dst);
    asm volatile("cp.async.cg.shared.global [%0], [%1], 16;\n" :: "r"(d), "l"(gmem_src));
}

/* ---------------- weight conversion fp32 -> fp16 (once per launch) ---------------- */
#define NQW (NL*DD*QKVLD)      /* 1572864 */
#define NOW (NL*INNER*DD)      /*  524288 */
__global__ void cvtw_kernel(const float* __restrict__ wq, const float* __restrict__ wo)
{
    int i = blockIdx.x*256 + threadIdx.x;
    if (i < NQW) g_wqh[i] = __float2half(wq[i]);
    if (i < NOW) g_woh[i] = __float2half(wo[i]);
}

/* ---------------- embed: convs + value proj + positional encoding ---------------- */
__global__ void embed_kernel(const float* __restrict__ x,
    const float* __restrict__ w1, const float* __restrict__ b1,
    const float* __restrict__ w2, const float* __restrict__ b2,
    const float* __restrict__ w3, const float* __restrict__ b3,
    const float* __restrict__ wv, const float* __restrict__ bv)
{
    int tok = blockIdx.x;
    int d   = threadIdx.x;
    int f   = tok % FF;
    int bw  = tok / FF;
    int w   = bw % WW;
    const float* xp = x + (size_t)(bw - w)*FF + f;

    float s0 = xp[(size_t)w*FF];
    float c1 = b1[f];
    #pragma unroll
    for (int j = 0; j < 4; j++) { int wi = w - (3-j);    if (wi >= 0) c1 += xp[(size_t)wi*FF]*w1[f*4+j]; }
    float c2 = b2[f];
    #pragma unroll
    for (int j = 0; j < 8; j++) { int wi = w - (7-j)*2;  if (wi >= 0) c2 += xp[(size_t)wi*FF]*w2[f*8+j]; }
    float c3 = b3[f];
    #pragma unroll
    for (int j = 0; j < 16; j++){ int wi = w - (15-j)*3; if (wi >= 0) c3 += xp[(size_t)wi*FF]*w3[f*16+j]; }

    float e = s0*wv[d] + c1*wv[DD+d] + c2*wv[2*DD+d] + c3*wv[3*DD+d] + bv[d];

    int   i2  = (d >> 1) * 2;
    float div = expf(-logf(10000.0f)/(float)DD * (float)i2);
    float ang = (float)w * div;
    float pe  = (d & 1) ? cosf(ang) : sinf(ang);

    g_h[(size_t)tok*DD + d] = e + pe;
}

/* ---------------- fused LN + QKV GEMM (A-resident) ---------------- */
#define QAHLD 136
#define QBHLD 136
#define QB_ST (32*QBHLD)
#define QCSLD 72
#define NCHUNK 12
#define QKV_SMEM (128*QAHLD*2 + 2*QB_ST*2 + 128*QCSLD*4)   /* 89088 B */

__global__ void __launch_bounds__(256)
qkvln_kernel(const float* __restrict__ h, const __half* __restrict__ Bw,
             __half* __restrict__ C,
             const float* __restrict__ gam, const float* __restrict__ bet)
{
    extern __shared__ char smp[];
    __half* Ah    = (__half*)smp;
    __half* Bh[2] = { (__half*)(smp + 128*QAHLD*2),
                      (__half*)(smp + 128*QAHLD*2) + QB_ST };
    float*  Cs    = (float*)(smp + 128*QAHLD*2 + 2*QB_ST*2);

    int m0 = blockIdx.y * 128;
    int nbase = blockIdx.x * (NCHUNK*128);
    int tid = threadIdx.x, w = tid >> 5;
    int wm = w & 3, wn = w >> 2;

    if (tid < 128) Cs[tid] = gam[tid];
    else           Cs[tid] = bet[tid-128];
    __syncthreads();

    {
        int r = tid >> 1, c0 = (tid & 1)*64;
        const float* hr = h + (size_t)(m0+r)*DD + c0;
        float s = 0.f, ss = 0.f;
        #pragma unroll
        for (int i=0;i<16;i++){
            float4 v = *(const float4*)&hr[i*4];
            s  += v.x+v.y+v.z+v.w;
            ss += v.x*v.x+v.y*v.y+v.z*v.z+v.w*v.w;
        }
        s  += __shfl_xor_sync(~0u, s, 1);
        ss += __shfl_xor_sync(~0u, ss, 1);
        float mean = s * (1.0f/DD);
        float rstd = rsqrtf(ss*(1.0f/DD) - mean*mean + 1e-5f);
        #pragma unroll
        for (int i=0;i<16;i++){
            float4 v = *(const float4*)&hr[i*4];
            int c = c0 + i*4;
            __half2 a = __float22half2_rn(make_float2(
                (v.x-mean)*rstd*Cs[c+0] + Cs[128+c+0],
                (v.y-mean)*rstd*Cs[c+1] + Cs[128+c+1]));
            __half2 b = __float22half2_rn(make_float2(
                (v.z-mean)*rstd*Cs[c+2] + Cs[128+c+2],
                (v.w-mean)*rstd*Cs[c+3] + Cs[128+c+3]));
            *(__half2*)&Ah[r*QAHLD + c]     = a;
            *(__half2*)&Ah[r*QAHLD + c + 2] = b;
        }
    }
    __syncthreads();

    auto issueB = [&](int st, int tt){
        int k0 = (tt & 3) << 5;
        int n0 = nbase + (tt >> 2)*128;
        #pragma unroll
        for (int i=0;i<2;i++){
            int idx = tid + i*256;
            int r = idx >> 4, c8 = (idx & 15)*8;
            cp16(&Bh[st][r*QBHLD + c8], &Bw[(size_t)(k0+r)*QKVLD + n0 + c8]);
        }
        asm volatile("cp.async.commit_group;\n");
    };

    issueB(0, 0);
    for (int c = 0; c < NCHUNK; c++){
        wmma::fragment<wmma::accumulator,16,16,16,float> acc[2][4];
        #pragma unroll
        for (int i=0;i<2;i++)
            #pragma unroll
            for (int j=0;j<4;j++) wmma::fill_fragment(acc[i][j], 0.0f);

        for (int kt = 0; kt < 4; kt++){
            int tt = c*4 + kt;
            if (tt+1 < NCHUNK*4){
                issueB((tt+1)&1, tt+1);
                asm volatile("cp.async.wait_group 1;\n" ::: "memory");
            } else {
                asm volatile("cp.async.wait_group 0;\n" ::: "memory");
            }
            __syncthreads();
            int st = tt & 1;
            #pragma unroll
            for (int ks = 0; ks < 32; ks += 16){
                wmma::fragment<wmma::matrix_a,16,16,16,__half,wmma::row_major> af[2];
                #pragma unroll
                for (int i=0;i<2;i++)
                    wmma::load_matrix_sync(af[i], &Ah[(wm*32 + i*16)*QAHLD + kt*32 + ks], QAHLD);
                #pragma unroll
                for (int j=0;j<4;j++){
                    wmma::fragment<wmma::matrix_b,16,16,16,__half,wmma::row_major> bf;
                    wmma::load_matrix_sync(bf, &Bh[st][ks*QBHLD + wn*64 + j*16], QBHLD);
                    wmma::mma_sync(acc[0][j], af[0], bf, acc[0][j]);
                    wmma::mma_sync(acc[1][j], af[1], bf, acc[1][j]);
                }
            }
            __syncthreads();
        }

        int n0 = nbase + c*128;
        #pragma unroll
        for (int pass = 0; pass < 2; pass++){
            if (wn == pass){
                #pragma unroll
                for (int i=0;i<2;i++)
                    #pragma unroll
                    for (int j=0;j<4;j++)
                        wmma::store_matrix_sync(&Cs[(wm*32 + i*16)*QCSLD + j*16],
                                                acc[i][j], QCSLD, wmma::mem_row_major);
            }
            __syncthreads();
            #pragma unroll
            for (int i=0;i<4;i++){
                int idx = tid + i*256;
                int r = idx >> 3, c8 = (idx & 7)*8;
                float4 v0 = *(float4*)&Cs[r*QCSLD + c8];
                float4 v1 = *(float4*)&Cs[r*QCSLD + c8 + 4];
                __half2 hh[4];
                hh[0] = __float22half2_rn(make_float2(v0.x, v0.y));
                hh[1] = __float22half2_rn(make_float2(v0.z, v0.w));
                hh[2] = __float22half2_rn(make_float2(v1.x, v1.y));
                hh[3] = __float22half2_rn(make_float2(v1.z, v1.w));
                *(uint4*)&C[(size_t)(m0+r)*QKVLD + n0 + pass*64 + c8] = *(uint4*)hh;
            }
            __syncthreads();
        }
    }
}

/* ---------------- out-proj GEMM v3: 3-stage ring, 1 sync per tile ----------------
   h = o @ Wout + bias + resid. BM=64, BN=128, BK=32, 8 warps (2M x 4N).
   fp32 C staging aliases the stage buffers. smem = 41472 B -> 5 blocks/SM. */
#define OAHLD 40
#define OBHLD 136
#define OA_ST (64*OAHLD)
#define OB_ST (32*OBHLD)
#define OST_B ((OA_ST + OB_ST)*2)      /* 13824 B per stage */
#define OCSLD 136
#define WOUT_SMEM (3*OST_B)            /* 41472 B >= 64*OCSLD*4 = 34816 */

__global__ void __launch_bounds__(256)
wgemm_out(const __half* __restrict__ A, const __half* __restrict__ B,
          float* __restrict__ C,
          const float* __restrict__ bias, const float* __restrict__ resid)
{
    extern __shared__ char smp[];
    int m0 = blockIdx.x * 64;
    int tid = threadIdx.x, w = tid >> 5;
    int wm = w & 1, wn = w >> 1;

    wmma::fragment<wmma::accumulator,16,16,16,float> acc[2][2];
    #pragma unroll
    for (int i=0;i<2;i++)
        #pragma unroll
        for (int j=0;j<2;j++) wmma::fill_fragment(acc[i][j], 0.0f);

    auto issue = [&](int t){
        char* stg = smp + (t % 3)*OST_B;
        __half* Ast = (__half*)stg;
        __half* Bst = (__half*)stg + OA_ST;
        int k0 = t << 5;
        {
            int r = tid >> 2, c8 = (tid & 3)*8;
            cp16(&Ast[r*OAHLD + c8], &A[(size_t)(m0+r)*INNER + k0 + c8]);
        }
        #pragma unroll
        for (int i=0;i<2;i++){
            int idx = tid + i*256;
            int r = idx >> 4, c8 = (idx & 15)*8;
            cp16(&Bst[r*OBHLD + c8], &B[(size_t)(k0+r)*DD + c8]);
        }
        asm volatile("cp.async.commit_group;\n");
    };

    const int nt = INNER >> 5;                     /* 32 tiles */
    issue(0);
    issue(1);
    for (int t = 0; t < nt; t++){
        if (t < nt-1) { asm volatile("cp.async.wait_group 1;\n" ::: "memory"); }
        else          { asm volatile("cp.async.wait_group 0;\n" ::: "memory"); }
        __syncthreads();
        if (t+2 < nt) issue(t+2);
        char* stg = smp + (t % 3)*OST_B;
        __half* Ast = (__half*)stg;
        __half* Bst = (__half*)stg + OA_ST;
        #pragma unroll
        for (int ks = 0; ks < 32; ks += 16){
            wmma::fragment<wmma::matrix_a,16,16,16,__half,wmma::row_major> af[2];
            wmma::fragment<wmma::matrix_b,16,16,16,__half,wmma::row_major> bf[2];
            #pragma unroll
            for (int i=0;i<2;i++)
                wmma::load_matrix_sync(af[i], &Ast[(wm*32 + i*16)*OAHLD + ks], OAHLD);
            #pragma unroll
            for (int j=0;j<2;j++)
                wmma::load_matrix_sync(bf[j], &Bst[ks*OBHLD + wn*32 + j*16], OBHLD);
            #pragma unroll
            for (int i=0;i<2;i++)
                #pragma unroll
                for (int j=0;j<2;j++)
                    wmma::mma_sync(acc[i][j], af[i], bf[j], acc[i][j]);
        }
    }
    __syncthreads();                   /* all compute done before aliasing Cs */

    float* Cs = (float*)smp;
    #pragma unroll
    for (int i=0;i<2;i++)
        #pragma unroll
        for (int j=0;j<2;j++)
            wmma::store_matrix_sync(&Cs[(wm*32 + i*16)*OCSLD + wn*32 + j*16],
                                    acc[i][j], OCSLD, wmma::mem_row_major);
    __syncthreads();

    #pragma unroll
    for (int i=0;i<8;i++){
        int idx = tid + i*256;
        int r = idx >> 5, c4 = (idx & 31)*4;
        float4 v  = *(float4*)&Cs[r*OCSLD + c4];
        float4 bb = *(const float4*)&bias[c4];
        float4 rr = *(const float4*)&resid[(size_t)(m0+r)*DD + c4];
        v.x += bb.x + rr.x; v.y += bb.y + rr.y;
        v.z += bb.z + rr.z; v.w += bb.w + rr.w;
        *(float4*)&C[(size_t)(m0+r)*DD + c4] = v;
    }
}

/* ---------------- variable attention v3: warp-private staging + register softmax ----------------
   block = one (b,w) token group; 8 warps, one head each. Per warp: cp.async Q/K/V
   (48 rows x 128 halves, 136-stride) into a private smem region. No __syncthreads.
   S softmax entirely in registers; unnormalized P (half) overwrites the dead Q rows;
   O written half2-direct from accumulator fragments.
   acc layout (m16n16): row=(lane>>2)+8*((e>>1)&1), col=(lane&3)*2+(e&1)+8*(e>>2). */
#define VLD2 136
#define VWB  (48*VLD2)                 /* halves per warp region */
#define VATTN_SMEM (HH*VWB*2)          /* 104448 B */

__global__ void __launch_bounds__(256, 2)
vattn_kernel(const __half* __restrict__ qkv, __half* __restrict__ o)
{
    extern __shared__ __half vs[];
    int bw = blockIdx.x;
    int w  = threadIdx.x >> 5, lane = threadIdx.x & 31;
    int lg = lane >> 2, lq = lane & 3;
    __half* Wb = vs + w*VWB;           /* rows: Q 0-15, K 16-31, V 32-47 */
    const __half* base = qkv + (size_t)bw*FF*QKVLD + w*DD;
    __half* op = o + (size_t)bw*FF*INNER + w*DD;

    /* stage Q/K/V: 768 16B-chunks per warp, 24 per lane, coalesced rows */
    #pragma unroll
    for (int i=0;i<24;i++){
        int idx = lane + i*32;
        int r = idx >> 4, c8 = (idx & 15)*8;
        int f = r & 15, sel = r >> 4;
        cp16(&Wb[r*VLD2 + c8], base + (size_t)f*QKVLD + sel*INNER + c8);
    }
    asm volatile("cp.async.commit_group;\n");
    asm volatile("cp.async.wait_group 0;\n" ::: "memory");
    __syncwarp();

    /* S = Q @ K^T (16x16x128) from smem */
    wmma::fragment<wmma::accumulator,16,16,16,float> sf;
    wmma::fill_fragment(sf, 0.0f);
    #pragma unroll
    for (int ks = 0; ks < DD; ks += 16){
        wmma::fragment<wmma::matrix_a,16,16,16,__half,wmma::row_major> af;
        wmma::fragment<wmma::matrix_b,16,16,16,__half,wmma::col_major> bf;
        wmma::load_matrix_sync(af, Wb + ks, VLD2);
        wmma::load_matrix_sync(bf, Wb + 16*VLD2 + ks, VLD2);
        wmma::mma_sync(sf, af, bf, sf);
    }

    /* register softmax: lane owns rows lg and lg+8 (hh=0,1); cols via lq shfl */
    float m2[2], s2[2], rinv[2];
    #pragma unroll
    for (int hh=0; hh<2; hh++){
        int e0 = hh*2;
        float m = fmaxf(fmaxf(sf.x[e0], sf.x[e0+1]), fmaxf(sf.x[e0+4], sf.x[e0+5]));
        m = fmaxf(m, __shfl_xor_sync(~0u, m, 1));
        m = fmaxf(m, __shfl_xor_sync(~0u, m, 2));
        m2[hh] = m;
    }
    #pragma unroll
    for (int hh=0; hh<2; hh++) s2[hh] = 0.f;
    #pragma unroll
    for (int e=0; e<8; e++){
        int hh = (e>>1)&1;
        float p = fexp((sf.x[e] - m2[hh])*SCALE);
        sf.x[e] = p;
        s2[hh] += p;
    }
    #pragma unroll
    for (int hh=0; hh<2; hh++){
        float s = s2[hh];
        s += __shfl_xor_sync(~0u, s, 1);
        s += __shfl_xor_sync(~0u, s, 2);
        rinv[hh] = 1.0f/s;
    }

    /* write unnormalized P (half) into dead Q rows */
    __syncwarp();
    #pragma unroll
    for (int e=0; e<8; e+=2){
        int hh = (e>>1)&1;
        int row = lg + 8*hh;
        int col = lq*2 + 8*(e>>2);
        *(__half2*)&Wb[row*VLD2 + col] =
            __float22half2_rn(make_float2(sf.x[e], sf.x[e+1]));
    }
    __syncwarp();

    wmma::fragment<wmma::matrix_a,16,16,16,__half,wmma::row_major> pf;
    wmma::load_matrix_sync(pf, Wb, VLD2);

    /* O = P @ V (16x128x16): epilogue half2-direct from fragments */
    #pragma unroll
    for (int n0 = 0; n0 < DD; n0 += 16){
        wmma::fragment<wmma::accumulator,16,16,16,float> of;
        wmma::fill_fragment(of, 0.0f);
        wmma::fragment<wmma::matrix_b,16,16,16,__half,wmma::row_major> vf;
        wmma::load_matrix_sync(vf, Wb + 32*VLD2 + n0, VLD2);
        wmma::mma_sync(of, pf, vf, of);
        #pragma unroll
        for (int e=0; e<8; e+=2){
            int hh = (e>>1)&1;
            int row = lg + 8*hh;
            int col = n0 + lq*2 + 8*(e>>2);
            float inv = rinv[hh];
            *(__half2*)&op[(size_t)row*INNER + col] =
                __float22half2_rn(make_float2(of.x[e]*inv, of.x[e+1]*inv));
        }
    }
}

/* ---------------- fused temporal attention v2: register softmax, 2 blocks/SM ---------------- */
#define TI    64
#define KHLD  136
#define PHLD  264
#define OFF_PH (256*KHLD*2)                    /* 69632  */
#define OFF_RR (OFF_PH + TI*PHLD*2)            /* 103424 */
#define TATTN_SMEM (OFF_RR + TI*4*4)           /* 104448 */

__global__ void __launch_bounds__(256, 2)
tattn_kernel(const __half* __restrict__ qkv, __half* __restrict__ o)
{
    extern __shared__ char smb[];
    __half* Kh = (__half*)smb;
    __half* Ph = (__half*)(smb + OFF_PH);
    float*  RR = (float*) (smb + OFF_RR);

    int batch = blockIdx.y;
    int hd = batch & 7, f = (batch >> 3) & 15, b = batch >> 7;
    int i0 = blockIdx.x * TI;
    size_t baseQ = ((size_t)(b*WW)*FF + f)*QKVLD + hd*DD;
    size_t baseK = baseQ + INNER;
    size_t baseV = baseQ + 2*INNER;
    size_t baseO = ((size_t)(b*WW)*FF + f)*INNER + hd*DD;
    int tid = threadIdx.x, w = tid >> 5, lane = tid & 31;
    int wm = w & 1, wn = w >> 1;
    int lg = lane >> 2, lq = lane & 3;

    #pragma unroll
    for (int i=0;i<16;i++){
        int idx = tid + i*256;
        int r = idx >> 4, c8 = (idx & 15)*8;
        cp16(&Kh[r*KHLD + c8], &qkv[baseK + (size_t)r*RS + c8]);
    }
    asm volatile("cp.async.commit_group;\n");
    asm volatile("cp.async.wait_group 0;\n" ::: "memory");
    __syncthreads();

    const __half* qp = qkv + baseQ + (size_t)i0*RS;
    wmma::fragment<wmma::accumulator,16,16,16,float> sf[2][4];
    #pragma unroll
    for (int i=0;i<2;i++)
        #pragma unroll
        for (int j=0;j<4;j++) wmma::fill_fragment(sf[i][j], 0.0f);
    #pragma unroll
    for (int ks=0; ks<DD; ks+=16){
        wmma::fragment<wmma::matrix_a,16,16,16,__half,wmma::row_major> af[2];
        wmma::fragment<wmma::matrix_b,16,16,16,__half,wmma::col_major> bf[4];
        #pragma unroll
        for (int i=0;i<2;i++)
            wmma::load_matrix_sync(af[i], qp + (size_t)(wm*32 + i*16)*RS + ks, RS);
        #pragma unroll
        for (int j=0;j<4;j++)
            wmma::load_matrix_sync(bf[j], &Kh[(wn*64 + j*16)*KHLD + ks], KHLD);
        #pragma unroll
        for (int i=0;i<2;i++)
            #pragma unroll
            for (int j=0;j<4;j++)
                wmma::mma_sync(sf[i][j], af[i], bf[j], sf[i][j]);
    }
    __syncthreads();

    #pragma unroll
    for (int i=0;i<16;i++){
        int idx = tid + i*256;
        int r = idx >> 4, c8 = (idx & 15)*8;
        cp16(&Kh[r*KHLD + c8], &qkv[baseV + (size_t)r*RS + c8]);
    }
    asm volatile("cp.async.commit_group;\n");

    float pm[4];
    #pragma unroll
    for (int i=0;i<2;i++)
        #pragma unroll
        for (int hh=0;hh<2;hh++){
            float m = -1e30f;
            #pragma unroll
            for (int j=0;j<4;j++){
                float* x = sf[i][j].x;
                int e0 = hh*2;
                m = fmaxf(m, fmaxf(fmaxf(x[e0], x[e0+1]), fmaxf(x[e0+4], x[e0+5])));
            }
            pm[i*2+hh] = m;
        }
    #pragma unroll
    for (int u=0;u<4;u++){
        pm[u] = fmaxf(pm[u], __shfl_xor_sync(~0u, pm[u], 1));
        pm[u] = fmaxf(pm[u], __shfl_xor_sync(~0u, pm[u], 2));
    }
    if (lq == 0){
        #pragma unroll
        for (int i=0;i<2;i++)
            #pragma unroll
            for (int hh=0;hh<2;hh++)
                RR[(wm*32 + i*16 + hh*8 + lg)*4 + wn] = pm[i*2+hh];
    }
    __syncthreads();
    float gmax[4];
    #pragma unroll
    for (int i=0;i<2;i++)
        #pragma unroll
        for (int hh=0;hh<2;hh++){
            const float* rr = &RR[(wm*32 + i*16 + hh*8 + lg)*4];
            gmax[i*2+hh] = fmaxf(fmaxf(rr[0], rr[1]), fmaxf(rr[2], rr[3]));
        }
    __syncthreads();

    float ps[4] = {0.f, 0.f, 0.f, 0.f};
    #pragma unroll
    for (int i=0;i<2;i++)
        #pragma unroll
        for (int j=0;j<4;j++){
            float* x = sf[i][j].x;
            #pragma unroll
            for (int e=0;e<8;e++){
                int hh = (e>>1)&1;
                float p = fexp((x[e] - gmax[i*2+hh])*SCALE);
                x[e] = p;
                ps[i*2+hh] += p;
            }
        }
    #pragma unroll
    for (int u=0;u<4;u++){
        ps[u] += __shfl_xor_sync(~0u, ps[u], 1);
        ps[u] += __shfl_xor_sync(~0u, ps[u], 2);
    }
    if (lq == 0){
        #pragma unroll
        for (int i=0;i<2;i++)
            #pragma unroll
            for (int hh=0;hh<2;hh++)
                RR[(wm*32 + i*16 + hh*8 + lg)*4 + wn] = ps[i*2+hh];
    }
    __syncthreads();
    float rinv[4];
    #pragma unroll
    for (int i=0;i<2;i++)
        #pragma unroll
        for (int hh=0;hh<2;hh++){
            const float* rr = &RR[(wm*32 + i*16 + hh*8 + lg)*4];
            rinv[i*2+hh] = 1.0f/(rr[0]+rr[1]+rr[2]+rr[3]);
        }

    #pragma unroll
    for (int i=0;i<2;i++)
        #pragma unroll
        for (int j=0;j<4;j++){
            float* x = sf[i][j].x;
            #pragma unroll
            for (int e=0;e<8;e+=2){
                int hh = (e>>1)&1;
                int row = wm*32 + i*16 + hh*8 + lg;
                int col = wn*64 + j*16 + lq*2 + 8*(e>>2);
                *(__half2*)&Ph[row*PHLD + col] =
                    __float22half2_rn(make_float2(x[e], x[e+1]));
            }
        }
    asm volatile("cp.async.wait_group 0;\n" ::: "memory");
    __syncthreads();

    wmma::fragment<wmma::accumulator,16,16,16,float> of[2][2];
    #pragma unroll
    for (int i=0;i<2;i++)
        #pragma unroll
        for (int j=0;j<2;j++) wmma::fill_fragment(of[i][j], 0.0f);
    #pragma unroll
    for (int ks=0; ks<WW; ks+=16){
        wmma::fragment<wmma::matrix_a,16,16,16,__half,wmma::row_major> pf[2];
        wmma::fragment<wmma::matrix_b,16,16,16,__half,wmma::row_major> vf[2];
        #pragma unroll
        for (int i=0;i<2;i++)
            wmma::load_matrix_sync(pf[i], &Ph[(wm*32 + i*16)*PHLD + ks], PHLD);
        #pragma unroll
        for (int j=0;j<2;j++)
            wmma::load_matrix_sync(vf[j], &Kh[ks*KHLD + wn*32 + j*16], KHLD);
        #pragma unroll
        for (int i=0;i<2;i++)
            #pragma unroll
            for (int j=0;j<2;j++)
                wmma::mma_sync(of[i][j], pf[i], vf[j], of[i][j]);
    }

    #pragma unroll
    for (int i=0;i<2;i++)
        #pragma unroll
        for (int j=0;j<2;j++){
            float* x = of[i][j].x;
            #pragma unroll
            for (int e=0;e<8;e+=2){
                int hh = (e>>1)&1;
                int row = wm*32 + i*16 + hh*8 + lg;
                int col = wn*32 + j*16 + lq*2 + 8*(e>>2);
                float inv = rinv[i*2+hh];
                __half2* gp = (__half2*)&o[baseO + (size_t)(i0+row)*RO + col];
                float2 f0 = __half22float2(*gp);
                f0.x += x[e]*inv;
                f0.y += x[e+1]*inv;
                *gp = __float22half2_rn(f0);
            }
        }
}

/* ---------------- head ---------------- */
__global__ void head_kernel(const float* __restrict__ wh, const float* __restrict__ bh,
                            float* __restrict__ out)
{
    int bw = blockIdx.x;
    int n = threadIdx.x >> 5, lane = threadIdx.x & 31;
    const float* hrow = g_h + (size_t)bw*(FF*DD);
    float acc = 0.f;
    #pragma unroll 4
    for (int k = lane; k < FF*DD; k += 32)
        acc += hrow[k]*wh[k*FF + n];
    #pragma unroll
    for (int o=16;o>0;o>>=1) acc += __shfl_xor_sync(~0u, acc, o);
    if (lane == 0) out[bw*FF + n] = acc + bh[n];
}

/* ---------------- launcher ---------------- */
extern "C" void kernel_launch(void* const* d_in, const int* in_sizes, int n_in,
                              void* d_out, int out_size)
{
    (void)in_sizes; (void)n_in; (void)out_size;
    const float* x   = (const float*)d_in[0];
    const float* w1  = (const float*)d_in[1];
    const float* b1  = (const float*)d_in[2];
    const float* w2  = (const float*)d_in[3];
    const float* b2  = (const float*)d_in[4];
    const float* w3  = (const float*)d_in[5];
    const float* b3  = (const float*)d_in[6];
    const float* wv  = (const float*)d_in[7];
    const float* bv  = (const float*)d_in[8];
    const float* lng = (const float*)d_in[9];
    const float* lnb = (const float*)d_in[10];
    const float* wq  = (const float*)d_in[11];
    const float* wo  = (const float*)d_in[12];
    const float* bo  = (const float*)d_in[13];
    const float* wh  = (const float*)d_in[14];
    const float* bh  = (const float*)d_in[15];
    float* out = (float*)d_out;

    float *p_h; __half *p_qkv, *p_o, *p_wqh, *p_woh;
    cudaGetSymbolAddress((void**)&p_h,   g_h);
    cudaGetSymbolAddress((void**)&p_qkv, g_qkv);
    cudaGetSymbolAddress((void**)&p_o,   g_o);
    cudaGetSymbolAddress((void**)&p_wqh, g_wqh);
    cudaGetSymbolAddress((void**)&p_woh, g_woh);

    cudaFuncSetAttribute(tattn_kernel,
        cudaFuncAttributeMaxDynamicSharedMemorySize, TATTN_SMEM);
    cudaFuncSetAttribute(vattn_kernel,
        cudaFuncAttributeMaxDynamicSharedMemorySize, VATTN_SMEM);
    cudaFuncSetAttribute(qkvln_kernel,
        cudaFuncAttributeMaxDynamicSharedMemorySize, QKV_SMEM);
    cudaFuncSetAttribute(wgemm_out,
        cudaFuncAttributeMaxDynamicSharedMemorySize, WOUT_SMEM);

    cvtw_kernel<<<(NQW + 255)/256, 256>>>(wq, wo);
    embed_kernel<<<NT, DD>>>(x, w1, b1, w2, b2, w3, b3, wv, bv);

    for (int l = 0; l < NL; l++) {
        /* fused LN + qkv GEMM : [32768,128]@[128,3072] */
        qkvln_kernel<<<dim3(2, NT/128), 256, QKV_SMEM>>>(
            p_h, p_wqh + (size_t)l*DD*QKVLD, p_qkv, lng + l*DD, lnb + l*DD);

        /* variable attention writes g_o (half) */
        vattn_kernel<<<BB*WW, 256, VATTN_SMEM>>>(p_qkv, p_o);

        /* fused temporal attention accumulates into g_o (half RMW) */
        tattn_kernel<<<dim3(WW/TI, BB*FF*HH), 256, TATTN_SMEM>>>(p_qkv, p_o);

        /* h = o @ Wout[l] + b_out[l] + h : [32768,1024]@[1024,128], fp32 out */
        wgemm_out<<<NT/64, 256, WOUT_SMEM>>>(
            p_o, p_woh + (size_t)l*INNER*DD, p_h, bo + l*DD, p_h);
    }

    head_kernel<<<BB*WW, 512>>>(wh, bh, out);
}